// round 7
// baseline (speedup 1.0000x reference)
#include <cuda_runtime.h>
#include <cuda_bf16.h>
#include <math.h>
#include <stdint.h>

#define N_TOK 1024
#define C_IN  512
#define CQ    64
#define BATCH 32

#if defined(__CUDA_ARCH__)
#if defined(__CUDA_ARCH_FEAT_SM103_ALL)
#define USE_TCGEN05 1
#else
#define USE_TCGEN05 0
#endif
#else
#define USE_TCGEN05 0
#endif

// ---------------- scratch (device globals; no allocation allowed) ----------
__device__ __align__(128) float g_Wn [640 * C_IN];                   // rows: q 0-63, k 64-127, v 128-639 (K-major, c contiguous)
__device__ __align__(128) float g_bias[640];
__device__ __align__(128) float g_xT [(size_t)BATCH * N_TOK * C_IN]; // [b][n][c]
__device__ __align__(128) float g_qT [(size_t)BATCH * N_TOK * CQ];   // [b][n][o]
__device__ __align__(128) float g_kT [(size_t)BATCH * N_TOK * CQ];   // [b][m][o]
__device__ __align__(128) float g_v  [(size_t)BATCH * C_IN * N_TOK]; // [b][c][n]
__device__ __align__(128) float g_S  [(size_t)BATCH * N_TOK * N_TOK];// [b][m][n]

// ---------------- small PTX helpers ----------------------------------------
__device__ __forceinline__ uint32_t cvta_smem(const void* p) {
    uint32_t a;
    asm("{ .reg .u64 t; cvta.to.shared.u64 t, %1; cvt.u32.u64 %0, t; }" : "=r"(a) : "l"(p));
    return a;
}

#if USE_TCGEN05
__device__ __forceinline__ int elect_one() {
    uint32_t pred;
    asm volatile("{\n\t.reg .pred p;\n\telect.sync _|p, 0xFFFFFFFF;\n\tselp.b32 %0, 1, 0, p;\n\t}" : "=r"(pred));
    return (int)pred;
}
#define MB_INIT(addr, cnt) \
    asm volatile("mbarrier.init.shared.b64 [%0], %1;" :: "r"(addr), "r"((uint32_t)(cnt)) : "memory")
#define MB_WAIT(addr, phv) do { \
    uint32_t _m = (addr), _p = (uint32_t)(phv), _d; \
    asm volatile("{\n\t.reg .pred p;\n\t" \
        "mbarrier.try_wait.parity.acquire.cta.shared::cta.b64 p, [%1], %2;\n\t" \
        "selp.b32 %0,1,0,p;\n\t}" : "=r"(_d) : "r"(_m), "r"(_p) : "memory"); \
    while (!_d) { \
        asm volatile("{\n\t.reg .pred p;\n\t" \
            "mbarrier.try_wait.parity.acquire.cta.shared::cta.b64 p, [%1], %2, 0x989680;\n\t" \
            "selp.b32 %0,1,0,p;\n\t}" : "=r"(_d) : "r"(_m), "r"(_p) : "memory"); \
    } \
} while (0)
#define TC_ALLOC(addr, n) \
    asm volatile("tcgen05.alloc.cta_group::1.sync.aligned.shared::cta.b32 [%0], %1;" :: "r"(addr), "r"((uint32_t)(n)) : "memory")
#define TC_RELINQ() \
    asm volatile("tcgen05.relinquish_alloc_permit.cta_group::1.sync.aligned;")
#define TC_DEALLOC(tm, n) \
    asm volatile("tcgen05.dealloc.cta_group::1.sync.aligned.b32 %0, %1;" :: "r"(tm), "r"((uint32_t)(n)))
#define TC_COMMIT(addr) \
    asm volatile("tcgen05.commit.cta_group::1.mbarrier::arrive::one.shared::cluster.b64 [%0];" :: "r"(addr) : "memory")
#define TC_FENCE_AFTER()  asm volatile("tcgen05.fence::after_thread_sync;" ::: "memory")
#define TC_WAIT_LD()      asm volatile("tcgen05.wait::ld.sync.aligned;" ::: "memory")
#define FENCE_ASYNC()     asm volatile("fence.proxy.async.shared::cta;" ::: "memory")

#define LDTM32(r, tma) \
    asm volatile("tcgen05.ld.sync.aligned.32x32b.x32.b32 " \
        "{%0,%1,%2,%3,%4,%5,%6,%7,%8,%9,%10,%11,%12,%13,%14,%15," \
        "%16,%17,%18,%19,%20,%21,%22,%23,%24,%25,%26,%27,%28,%29,%30,%31}, [%32];" \
        : "=r"((r)[0]),"=r"((r)[1]),"=r"((r)[2]),"=r"((r)[3]),"=r"((r)[4]),"=r"((r)[5]),"=r"((r)[6]),"=r"((r)[7]), \
          "=r"((r)[8]),"=r"((r)[9]),"=r"((r)[10]),"=r"((r)[11]),"=r"((r)[12]),"=r"((r)[13]),"=r"((r)[14]),"=r"((r)[15]), \
          "=r"((r)[16]),"=r"((r)[17]),"=r"((r)[18]),"=r"((r)[19]),"=r"((r)[20]),"=r"((r)[21]),"=r"((r)[22]),"=r"((r)[23]), \
          "=r"((r)[24]),"=r"((r)[25]),"=r"((r)[26]),"=r"((r)[27]),"=r"((r)[28]),"=r"((r)[29]),"=r"((r)[30]),"=r"((r)[31]) \
        : "r"(tma))

__device__ __forceinline__ uint64_t smem_desc(uint32_t addr) {
    // SW128, version=1 (Blackwell), LBO=1, SBO=64
    return 0x4000404000010000ULL | (uint64_t)((addr >> 4) & 0x3FFF);
}
__device__ __forceinline__ void mma_bf16_ss(uint32_t d, uint64_t ad, uint64_t bd,
                                            uint32_t idesc, uint32_t en) {
    asm volatile(
        "{\n\t.reg .pred p;\n\tsetp.ne.u32 p, %4, 0;\n\t"
        "tcgen05.mma.cta_group::1.kind::f16 [%0], %1, %2, %3, {%5,%5,%5,%5}, p;\n\t}"
        :: "r"(d), "l"(ad), "l"(bd), "r"(idesc), "r"(en), "r"(0u) : "memory");
}
// idesc: dtype=F32, atype=btype=BF16, M=128, N variable
#define IDESC(NN) (0x8000490u | ((uint32_t)((NN) / 8) << 17))

// ---------------- fp32 -> (bf16 hi, bf16 lo) split --------------------------
__device__ __forceinline__ void split2(float a, float b, uint32_t& h, uint32_t& l) {
    __nv_bfloat16 ah = __float2bfloat16(a);
    __nv_bfloat16 bh = __float2bfloat16(b);
    __nv_bfloat16 al = __float2bfloat16(a - __bfloat162float(ah));
    __nv_bfloat16 bl = __float2bfloat16(b - __bfloat162float(bh));
    h = (uint32_t)__bfloat16_as_ushort(ah) | ((uint32_t)__bfloat16_as_ushort(bh) << 16);
    l = (uint32_t)__bfloat16_as_ushort(al) | ((uint32_t)__bfloat16_as_ushort(bl) << 16);
}

// Load a ROWS x 64 fp32 chunk (rows stride rstride, cols c0..c0+63), split to
// bf16 hi/lo, store into SW128-swizzled smem tiles (128B rows).
template<int ROWS>
__device__ __forceinline__ void load_split(const float* __restrict__ src, int rstride,
                                           int c0, uint32_t s_hi, uint32_t s_lo, int tid) {
#pragma unroll
    for (int it = 0; it < ROWS / 32; it++) {
        int idx = tid + it * 256;
        int r = idx >> 3;
        int cc = (idx & 7) << 3;
        const float* p = src + (size_t)r * rstride + c0 + cc;
        float4 v0 = *(const float4*)p;
        float4 v1 = *(const float4*)(p + 4);
        uint32_t h0, h1, h2, h3, l0, l1, l2, l3;
        split2(v0.x, v0.y, h0, l0); split2(v0.z, v0.w, h1, l1);
        split2(v1.x, v1.y, h2, l2); split2(v1.z, v1.w, h3, l3);
        uint32_t off = (uint32_t)((r << 7) + (cc << 1));
        uint32_t sw = off ^ ((off >> 3) & 0x70u);
        asm volatile("st.shared.v4.b32 [%0], {%1,%2,%3,%4};"
                     :: "r"(s_hi + sw), "r"(h0), "r"(h1), "r"(h2), "r"(h3) : "memory");
        asm volatile("st.shared.v4.b32 [%0], {%1,%2,%3,%4};"
                     :: "r"(s_lo + sw), "r"(l0), "r"(l1), "r"(l2), "r"(l3) : "memory");
    }
}

// Issue one K=64 chunk: 3 split-products x 4 K-steps, accumulating into TMEM.
__device__ __forceinline__ void issue_chunk(uint32_t d, uint32_t ahi, uint32_t alo,
                                            uint32_t bhi, uint32_t blo,
                                            uint32_t idesc, bool first) {
    uint64_t AH = smem_desc(ahi), AL = smem_desc(alo);
    uint64_t BH = smem_desc(bhi), BL = smem_desc(blo);
#pragma unroll
    for (int ks = 0; ks < 4; ks++) mma_bf16_ss(d, AH + 2 * ks, BH + 2 * ks, idesc, (first && ks == 0) ? 0u : 1u);
#pragma unroll
    for (int ks = 0; ks < 4; ks++) mma_bf16_ss(d, AH + 2 * ks, BL + 2 * ks, idesc, 1u);
#pragma unroll
    for (int ks = 0; ks < 4; ks++) mma_bf16_ss(d, AL + 2 * ks, BH + 2 * ks, idesc, 1u);
}
#endif  // USE_TCGEN05

// ---------------- spectral norm ---------------------------------------------
__global__ void sn_kernel(const float* __restrict__ Wq, const float* __restrict__ uq, const float* __restrict__ bq,
                          const float* __restrict__ Wk, const float* __restrict__ uk, const float* __restrict__ bk,
                          const float* __restrict__ Wv, const float* __restrict__ uv, const float* __restrict__ bv) {
    const float* W; const float* u; const float* bias; int out; int dst;
    if (blockIdx.x == 0)      { W = Wq; u = uq; bias = bq; out = CQ;   dst = 0;   }
    else if (blockIdx.x == 1) { W = Wk; u = uk; bias = bk; out = CQ;   dst = 64;  }
    else                      { W = Wv; u = uv; bias = bv; out = C_IN; dst = 128; }

    __shared__ float su[C_IN];
    __shared__ float sv[C_IN];
    __shared__ float red[512];
    int tid = threadIdx.x;

    if (tid < out) { su[tid] = u[tid]; g_bias[dst + tid] = bias[tid]; }
    __syncthreads();

    float t = 0.f;
    for (int i = 0; i < out; i++) t += W[i * C_IN + tid] * su[i];
    red[tid] = t * t;
    __syncthreads();
    for (int s = 256; s > 0; s >>= 1) { if (tid < s) red[tid] += red[tid + s]; __syncthreads(); }
    float nv = sqrtf(red[0]);
    sv[tid] = t / nv;
    __syncthreads();

    float p = 0.f;
    for (int i = tid; i < out; i += blockDim.x) {
        float r = 0.f;
        for (int j = 0; j < C_IN; j++) r += W[i * C_IN + j] * sv[j];
        p += r * r;
    }
    red[tid] = p;
    __syncthreads();
    for (int s = 256; s > 0; s >>= 1) { if (tid < s) red[tid] += red[tid + s]; __syncthreads(); }
    float inv_sigma = rsqrtf(red[0]);

    for (int e = tid; e < out * C_IN; e += blockDim.x)
        g_Wn[(size_t)dst * C_IN + e] = W[e] * inv_sigma;
}

// ---------------- x transpose: xT[b][n][c] ----------------------------------
__global__ void transpose_kernel(const float* __restrict__ x) {
    __shared__ float t[32][33];
    int b = blockIdx.z, c0 = blockIdx.y * 32, n0 = blockIdx.x * 32;
    int tx = threadIdx.x, ty = threadIdx.y;
    const float* src = x + (size_t)b * C_IN * N_TOK;
    float* dst = g_xT + (size_t)b * N_TOK * C_IN;
#pragma unroll
    for (int i = ty; i < 32; i += 8) t[i][tx] = src[(size_t)(c0 + i) * N_TOK + n0 + tx];
    __syncthreads();
#pragma unroll
    for (int i = ty; i < 32; i += 8) dst[(size_t)(n0 + i) * C_IN + c0 + tx] = t[tx][i];
}

// ---------------- proj: D[n=128][ocat tile] = xT @ Wn^T ---------------------
// grid (8, 3, BATCH): n0 = x*128, o0 = y*256, NN = y<2 ? 256 : 128
__global__ void __launch_bounds__(256) proj_mma() {
#if USE_TCGEN05
    extern __shared__ char dyn[];
    __shared__ uint32_t s_tmem;
    __shared__ uint64_t s_mb[2];
    __shared__ float s_bias[256];
    __shared__ float tb[4 * 32 * 33];

    int tid = threadIdx.x, wid = tid >> 5, lane = tid & 31;
    int b = blockIdx.z, n0 = blockIdx.x * 128, y = blockIdx.y, o0 = y * 256;
    int NN = (y < 2) ? 256 : 128;
    uint32_t idesc = IDESC(NN);

    uint32_t dynb = (cvta_smem(dyn) + 1023u) & ~1023u;
    uint32_t AHI[2], ALO[2], BHI[2], BLO[2];
#pragma unroll
    for (int p = 0; p < 2; p++) {
        uint32_t base = dynb + (uint32_t)p * 98304u;
        AHI[p] = base; ALO[p] = base + 16384u; BHI[p] = base + 32768u; BLO[p] = base + 65536u;
    }
    uint32_t mb0 = cvta_smem(&s_mb[0]), mb1 = cvta_smem(&s_mb[1]);

    if (wid == 0) { TC_ALLOC(cvta_smem(&s_tmem), 256); TC_RELINQ(); }
    if (tid == 0) { MB_INIT(mb0, 1); MB_INIT(mb1, 1); }
    for (int i = tid; i < NN; i += 256) s_bias[i] = g_bias[o0 + i];
    __syncthreads();
    uint32_t tmem = s_tmem;

    const float* Asrc = g_xT + ((size_t)b * N_TOK + n0) * C_IN;
    const float* Bsrc = g_Wn + (size_t)o0 * C_IN;

    int ph0 = 0, ph1 = 0;
    const int KT = C_IN / 64;
    for (int kt = 0; kt < KT; kt++) {
        int p = kt & 1;
        if (kt >= 2) {
            if (p == 0) { MB_WAIT(mb0, ph0); ph0 ^= 1; }
            else        { MB_WAIT(mb1, ph1); ph1 ^= 1; }
        }
        load_split<128>(Asrc, C_IN, kt * 64, AHI[p], ALO[p], tid);
        if (NN == 256) load_split<256>(Bsrc, C_IN, kt * 64, BHI[p], BLO[p], tid);
        else           load_split<128>(Bsrc, C_IN, kt * 64, BHI[p], BLO[p], tid);
        __syncthreads();
        if (wid == 0 && elect_one()) {
            FENCE_ASYNC();
            issue_chunk(tmem, AHI[p], ALO[p], BHI[p], BLO[p], idesc, kt == 0);
            TC_COMMIT(p == 0 ? mb0 : mb1);
        }
    }
    MB_WAIT(mb0, ph0);
    MB_WAIT(mb1, ph1);
    TC_FENCE_AFTER();
    __syncthreads();

    for (int c0 = 0; c0 < NN; c0 += 32) {
        bool dir = (o0 + c0) < 128;
        if (tid < 128) {
            uint32_t r[32];
            LDTM32(r, tmem + c0);
            TC_WAIT_LD();
            if (dir) {  // q/k region (only y==0): write qT/kT[n][o]
                int n = n0 + wid * 32 + lane;
                float* dst = (c0 < 64) ? (g_qT + ((size_t)b * N_TOK + n) * CQ + c0)
                                       : (g_kT + ((size_t)b * N_TOK + n) * CQ + (c0 - 64));
#pragma unroll
                for (int j = 0; j < 32; j += 4) {
                    float4 w4;
                    w4.x = __uint_as_float(r[j + 0]) + s_bias[c0 + j + 0];
                    w4.y = __uint_as_float(r[j + 1]) + s_bias[c0 + j + 1];
                    w4.z = __uint_as_float(r[j + 2]) + s_bias[c0 + j + 2];
                    w4.w = __uint_as_float(r[j + 3]) + s_bias[c0 + j + 3];
                    *(float4*)(dst + j) = w4;
                }
            } else {    // v region: stage for transpose
                int cb = wid * 1056 + lane * 33;
#pragma unroll
                for (int j = 0; j < 32; j++) tb[cb + j] = __uint_as_float(r[j]);
            }
        }
        if (!dir) {
            __syncthreads();
            int cg = o0 + c0 - 128;
#pragma unroll
            for (int i = 0; i < 16; i++) {
                int rid = wid * 16 + i;
                int wsrc = rid >> 5, j = rid & 31;
                float val = tb[wsrc * 1056 + lane * 33 + j] + s_bias[c0 + j];
                g_v[((size_t)b * C_IN + cg + j) * N_TOK + n0 + wsrc * 32 + lane] = val;
            }
            __syncthreads();
        }
    }
    __syncthreads();
    if (wid == 0) TC_DEALLOC(tmem, 256);
#else
    // fallback: naive, same output mapping
    int tid = threadIdx.x;
    int b = blockIdx.z, n0 = blockIdx.x * 128, y = blockIdx.y, o0 = y * 256;
    int NN = (y < 2) ? 256 : 128;
    const float* Asrc = g_xT + (size_t)b * N_TOK * C_IN;
    for (int e = tid; e < 128 * NN; e += 256) {
        int n = n0 + (e & 127);
        int oc = o0 + (e >> 7);
        const float* xa = Asrc + (size_t)n * C_IN;
        const float* wr = g_Wn + (size_t)oc * C_IN;
        float s = 0.f;
        for (int c = 0; c < C_IN; c++) s += xa[c] * wr[c];
        s += g_bias[oc];
        if (oc < 64)        g_qT[((size_t)b * N_TOK + n) * CQ + oc] = s;
        else if (oc < 128)  g_kT[((size_t)b * N_TOK + n) * CQ + (oc - 64)] = s;
        else                g_v[((size_t)b * C_IN + (oc - 128)) * N_TOK + n] = s;
    }
#endif
}

// ---------------- qk: D[n=128][m=256], S[m][n] = D[n][m] --------------------
// grid (8, 4, BATCH): n0 = x*128, m0 = y*256
__global__ void __launch_bounds__(256) qk_mma() {
#if USE_TCGEN05
    extern __shared__ char dyn[];
    __shared__ uint32_t s_tmem;
    __shared__ uint64_t s_mb;

    int tid = threadIdx.x, wid = tid >> 5, lane = tid & 31;
    int b = blockIdx.z, n0 = blockIdx.x * 128, m0 = blockIdx.y * 256;
    uint32_t idesc = IDESC(256);

    uint32_t dynb = (cvta_smem(dyn) + 1023u) & ~1023u;
    uint32_t AHI = dynb, ALO = dynb + 16384u, BHI = dynb + 32768u, BLO = dynb + 65536u;
    uint32_t mb = cvta_smem(&s_mb);

    if (wid == 0) { TC_ALLOC(cvta_smem(&s_tmem), 256); TC_RELINQ(); }
    if (tid == 0) MB_INIT(mb, 1);
    __syncthreads();
    uint32_t tmem = s_tmem;

    load_split<128>(g_qT + ((size_t)b * N_TOK + n0) * CQ, CQ, 0, AHI, ALO, tid);
    load_split<256>(g_kT + ((size_t)b * N_TOK + m0) * CQ, CQ, 0, BHI, BLO, tid);
    __syncthreads();
    if (wid == 0 && elect_one()) {
        FENCE_ASYNC();
        issue_chunk(tmem, AHI, ALO, BHI, BLO, idesc, true);
        TC_COMMIT(mb);
    }
    MB_WAIT(mb, 0);
    TC_FENCE_AFTER();

    float* Sb = g_S + (size_t)b * N_TOK * N_TOK;
    for (int c0 = 0; c0 < 256; c0 += 32) {
        if (tid < 128) {
            uint32_t r[32];
            LDTM32(r, tmem + c0);
            TC_WAIT_LD();
            int n = n0 + wid * 32 + lane;
#pragma unroll
            for (int j = 0; j < 32; j++)
                Sb[(size_t)(m0 + c0 + j) * N_TOK + n] = __uint_as_float(r[j]);
        }
    }
    __syncthreads();
    if (wid == 0) TC_DEALLOC(tmem, 256);
#else
    int tid = threadIdx.x;
    int b = blockIdx.z, n0 = blockIdx.x * 128, m0 = blockIdx.y * 256;
    float* Sb = g_S + (size_t)b * N_TOK * N_TOK;
    for (int e = tid; e < 128 * 256; e += 256) {
        int n = n0 + (e & 127);
        int m = m0 + (e >> 7);
        const float* qa = g_qT + ((size_t)b * N_TOK + n) * CQ;
        const float* ka = g_kT + ((size_t)b * N_TOK + m) * CQ;
        float s = 0.f;
        for (int o = 0; o < CQ; o++) s += qa[o] * ka[o];
        Sb[(size_t)m * N_TOK + n] = s;
    }
#endif
}

// ---------------- row softmax over n ----------------------------------------
__global__ void __launch_bounds__(256) softmax_kernel() {
    int b = blockIdx.y, m = blockIdx.x;
    float* row = g_S + ((size_t)b * N_TOK + m) * N_TOK;
    int tid = threadIdx.x;
    __shared__ float sm[8];

    float4 v = ((float4*)row)[tid];
    float mx = fmaxf(fmaxf(v.x, v.y), fmaxf(v.z, v.w));
#pragma unroll
    for (int s = 16; s; s >>= 1) mx = fmaxf(mx, __shfl_xor_sync(0xffffffffu, mx, s));
    if ((tid & 31) == 0) sm[tid >> 5] = mx;
    __syncthreads();
    mx = sm[0];
#pragma unroll
    for (int w = 1; w < 8; w++) mx = fmaxf(mx, sm[w]);
    __syncthreads();

    v.x = __expf(v.x - mx); v.y = __expf(v.y - mx);
    v.z = __expf(v.z - mx); v.w = __expf(v.w - mx);
    float s4 = v.x + v.y + v.z + v.w;
#pragma unroll
    for (int s = 16; s; s >>= 1) s4 += __shfl_xor_sync(0xffffffffu, s4, s);
    if ((tid & 31) == 0) sm[tid >> 5] = s4;
    __syncthreads();
    float tot = 0.f;
#pragma unroll
    for (int w = 0; w < 8; w++) tot += sm[w];
    float inv = 1.f / tot;
    v.x *= inv; v.y *= inv; v.z *= inv; v.w *= inv;
    ((float4*)row)[tid] = v;
}

// ---------------- av: D[m=128][c=256], out = gamma*D + x --------------------
// grid (8, 2, BATCH): m0 = x*128, c0g = y*256
__global__ void __launch_bounds__(256) av_mma(const float* __restrict__ x,
                                              const float* __restrict__ gamma_p,
                                              float* __restrict__ out) {
#if USE_TCGEN05
    extern __shared__ char dyn[];
    __shared__ uint32_t s_tmem;
    __shared__ uint64_t s_mb[2];

    int tid = threadIdx.x, wid = tid >> 5, lane = tid & 31;
    int b = blockIdx.z, m0 = blockIdx.x * 128, c0g = blockIdx.y * 256;
    uint32_t idesc = IDESC(256);

    uint32_t dynb = (cvta_smem(dyn) + 1023u) & ~1023u;
    uint32_t AHI[2], ALO[2], BHI[2], BLO[2];
#pragma unroll
    for (int p = 0; p < 2; p++) {
        uint32_t base = dynb + (uint32_t)p * 98304u;
        AHI[p] = base; ALO[p] = base + 16384u; BHI[p] = base + 32768u; BLO[p] = base + 65536u;
    }
    uint32_t mb0 = cvta_smem(&s_mb[0]), mb1 = cvta_smem(&s_mb[1]);

    if (wid == 0) { TC_ALLOC(cvta_smem(&s_tmem), 256); TC_RELINQ(); }
    if (tid == 0) { MB_INIT(mb0, 1); MB_INIT(mb1, 1); }
    __syncthreads();
    uint32_t tmem = s_tmem;

    const float* Asrc = g_S + ((size_t)b * N_TOK + m0) * N_TOK;
    const float* Bsrc = g_v + ((size_t)b * C_IN + c0g) * N_TOK;

    int ph0 = 0, ph1 = 0;
    const int KT = N_TOK / 64;
    for (int kt = 0; kt < KT; kt++) {
        int p = kt & 1;
        if (kt >= 2) {
            if (p == 0) { MB_WAIT(mb0, ph0); ph0 ^= 1; }
            else        { MB_WAIT(mb1, ph1); ph1 ^= 1; }
        }
        load_split<128>(Asrc, N_TOK, kt * 64, AHI[p], ALO[p], tid);
        load_split<256>(Bsrc, N_TOK, kt * 64, BHI[p], BLO[p], tid);
        __syncthreads();
        if (wid == 0 && elect_one()) {
            FENCE_ASYNC();
            issue_chunk(tmem, AHI[p], ALO[p], BHI[p], BLO[p], idesc, kt == 0);
            TC_COMMIT(p == 0 ? mb0 : mb1);
        }
    }
    MB_WAIT(mb0, ph0);
    MB_WAIT(mb1, ph1);
    TC_FENCE_AFTER();

    float g = *gamma_p;
    for (int c0 = 0; c0 < 256; c0 += 32) {
        if (tid < 128) {
            uint32_t r[32];
            LDTM32(r, tmem + c0);
            TC_WAIT_LD();
            int m = m0 + wid * 32 + lane;
#pragma unroll
            for (int j = 0; j < 32; j++) {
                int c = c0g + c0 + j;
                size_t off = ((size_t)b * C_IN + c) * N_TOK + m;
                out[off] = g * __uint_as_float(r[j]) + x[off];
            }
        }
    }
    __syncthreads();
    if (wid == 0) TC_DEALLOC(tmem, 256);
#else
    int tid = threadIdx.x;
    int b = blockIdx.z, m0 = blockIdx.x * 128, c0g = blockIdx.y * 256;
    float g = *gamma_p;
    const float* Sb = g_S + (size_t)b * N_TOK * N_TOK;
    for (int e = tid; e < 128 * 256; e += 256) {
        int m = m0 + (e & 127);
        int c = c0g + (e >> 7);
        const float* vr = g_v + ((size_t)b * C_IN + c) * N_TOK;
        const float* pr = Sb + (size_t)m * N_TOK;
        float s = 0.f;
        for (int n = 0; n < N_TOK; n++) s += vr[n] * pr[n];
        size_t off = ((size_t)b * C_IN + c) * N_TOK + m;
        out[off] = g * s + x[off];
    }
#endif
}

// ---------------- launch -----------------------------------------------------
extern "C" void kernel_launch(void* const* d_in, const int* in_sizes, int n_in,
                              void* d_out, int out_size) {
    const float* x     = (const float*)d_in[0];
    const float* Wq    = (const float*)d_in[1];
    const float* bq    = (const float*)d_in[2];
    const float* uq    = (const float*)d_in[3];
    const float* Wk    = (const float*)d_in[4];
    const float* bk    = (const float*)d_in[5];
    const float* uk    = (const float*)d_in[6];
    const float* Wv    = (const float*)d_in[7];
    const float* bv    = (const float*)d_in[8];
    const float* uv    = (const float*)d_in[9];
    const float* gamma = (const float*)d_in[10];
    float* out = (float*)d_out;

    cudaFuncSetAttribute(proj_mma, cudaFuncAttributeMaxDynamicSharedMemorySize, 197632);
    cudaFuncSetAttribute(qk_mma,   cudaFuncAttributeMaxDynamicSharedMemorySize, 99328);
    cudaFuncSetAttribute(av_mma,   cudaFuncAttributeMaxDynamicSharedMemorySize, 197632);

    sn_kernel<<<3, 512>>>(Wq, uq, bq, Wk, uk, bk, Wv, uv, bv);
    transpose_kernel<<<dim3(32, 16, BATCH), dim3(32, 8)>>>(x);
    proj_mma<<<dim3(8, 3, BATCH), 256, 197632>>>();
    qk_mma<<<dim3(8, 4, BATCH), 256, 99328>>>();
    softmax_kernel<<<dim3(N_TOK, BATCH), 256>>>();
    av_mma<<<dim3(8, 2, BATCH), 256, 197632>>>(x, gamma, out);
}

// round 8
// speedup vs baseline: 1.3934x; 1.3934x over previous
#include <cuda_runtime.h>
#include <cuda_bf16.h>
#include <math.h>
#include <stdint.h>

#define N_TOK 1024
#define C_IN  512
#define CQ    64
#define BATCH 32

#if defined(__CUDA_ARCH__)
#if defined(__CUDA_ARCH_FEAT_SM103_ALL)
#define USE_TCGEN05 1
#else
#define USE_TCGEN05 0
#endif
#else
#define USE_TCGEN05 0
#endif

// ---------------- scratch (device globals; no allocation allowed) ----------
__device__ __align__(128) __nv_bfloat16 g_Wn_hi[640 * C_IN];   // rows: q 0-63, k 64-127, v 128-639 (K-major)
__device__ __align__(128) __nv_bfloat16 g_Wn_lo[640 * C_IN];
__device__ __align__(128) float g_bias[640];
__device__ __align__(128) __nv_bfloat16 g_xT_hi[(size_t)BATCH * N_TOK * C_IN];  // [b][n][c]
__device__ __align__(128) __nv_bfloat16 g_xT_lo[(size_t)BATCH * N_TOK * C_IN];
__device__ __align__(128) __nv_bfloat16 g_qT_hi[(size_t)BATCH * N_TOK * CQ];    // [b][n][o]
__device__ __align__(128) __nv_bfloat16 g_qT_lo[(size_t)BATCH * N_TOK * CQ];
__device__ __align__(128) __nv_bfloat16 g_kT_hi[(size_t)BATCH * N_TOK * CQ];    // [b][m][o]
__device__ __align__(128) __nv_bfloat16 g_kT_lo[(size_t)BATCH * N_TOK * CQ];
__device__ __align__(128) __nv_bfloat16 g_v_hi [(size_t)BATCH * C_IN * N_TOK];  // [b][c][n]
__device__ __align__(128) __nv_bfloat16 g_v_lo [(size_t)BATCH * C_IN * N_TOK];
__device__ __align__(128) float         g_S    [(size_t)BATCH * N_TOK * N_TOK]; // [b][m][n]
__device__ __align__(128) __nv_bfloat16 g_P_hi [(size_t)BATCH * N_TOK * N_TOK]; // [b][m][n]
__device__ __align__(128) __nv_bfloat16 g_P_lo [(size_t)BATCH * N_TOK * N_TOK];

// ---------------- common helpers --------------------------------------------
__device__ __forceinline__ uint32_t cvta_smem(const void* p) {
    uint32_t a;
    asm("{ .reg .u64 t; cvta.to.shared.u64 t, %1; cvt.u32.u64 %0, t; }" : "=r"(a) : "l"(p));
    return a;
}
__device__ __forceinline__ void pack_split2(float a, float b, uint32_t& h, uint32_t& l) {
    __nv_bfloat16 ah = __float2bfloat16(a);
    __nv_bfloat16 bh = __float2bfloat16(b);
    __nv_bfloat16 al = __float2bfloat16(a - __bfloat162float(ah));
    __nv_bfloat16 bl = __float2bfloat16(b - __bfloat162float(bh));
    h = (uint32_t)__bfloat16_as_ushort(ah) | ((uint32_t)__bfloat16_as_ushort(bh) << 16);
    l = (uint32_t)__bfloat16_as_ushort(al) | ((uint32_t)__bfloat16_as_ushort(bl) << 16);
}
__device__ __forceinline__ void split1(float v, __nv_bfloat16& h, __nv_bfloat16& l) {
    h = __float2bfloat16(v);
    l = __float2bfloat16(v - __bfloat162float(h));
}

#if USE_TCGEN05
__device__ __forceinline__ int elect_one() {
    uint32_t pred;
    asm volatile("{\n\t.reg .pred p;\n\telect.sync _|p, 0xFFFFFFFF;\n\tselp.b32 %0, 1, 0, p;\n\t}" : "=r"(pred));
    return (int)pred;
}
#define MB_INIT(addr, cnt) \
    asm volatile("mbarrier.init.shared.b64 [%0], %1;" :: "r"(addr), "r"((uint32_t)(cnt)) : "memory")
#define MB_WAIT(addr, phv) do { \
    uint32_t _m = (addr), _p = (uint32_t)(phv), _d; \
    asm volatile("{\n\t.reg .pred p;\n\t" \
        "mbarrier.try_wait.parity.acquire.cta.shared::cta.b64 p, [%1], %2;\n\t" \
        "selp.b32 %0,1,0,p;\n\t}" : "=r"(_d) : "r"(_m), "r"(_p) : "memory"); \
    while (!_d) { \
        asm volatile("{\n\t.reg .pred p;\n\t" \
            "mbarrier.try_wait.parity.acquire.cta.shared::cta.b64 p, [%1], %2, 0x989680;\n\t" \
            "selp.b32 %0,1,0,p;\n\t}" : "=r"(_d) : "r"(_m), "r"(_p) : "memory"); \
    } \
} while (0)
#define TC_ALLOC(addr, n) \
    asm volatile("tcgen05.alloc.cta_group::1.sync.aligned.shared::cta.b32 [%0], %1;" :: "r"(addr), "r"((uint32_t)(n)) : "memory")
#define TC_RELINQ() \
    asm volatile("tcgen05.relinquish_alloc_permit.cta_group::1.sync.aligned;")
#define TC_DEALLOC(tm, n) \
    asm volatile("tcgen05.dealloc.cta_group::1.sync.aligned.b32 %0, %1;" :: "r"(tm), "r"((uint32_t)(n)))
#define TC_COMMIT(addr) \
    asm volatile("tcgen05.commit.cta_group::1.mbarrier::arrive::one.shared::cluster.b64 [%0];" :: "r"(addr) : "memory")
#define TC_FENCE_AFTER()  asm volatile("tcgen05.fence::after_thread_sync;" ::: "memory")
#define TC_WAIT_LD()      asm volatile("tcgen05.wait::ld.sync.aligned;" ::: "memory")
#define FENCE_ASYNC()     asm volatile("fence.proxy.async.shared::cta;" ::: "memory")
#define CP16(dst, src)  asm volatile("cp.async.cg.shared.global [%0], [%1], 16;" :: "r"(dst), "l"(src) : "memory")
#define CP_COMMIT()     asm volatile("cp.async.commit_group;" ::: "memory")
#define CP_WAIT0()      asm volatile("cp.async.wait_group 0;" ::: "memory")

#define LDTM32(r, tma) \
    asm volatile("tcgen05.ld.sync.aligned.32x32b.x32.b32 " \
        "{%0,%1,%2,%3,%4,%5,%6,%7,%8,%9,%10,%11,%12,%13,%14,%15," \
        "%16,%17,%18,%19,%20,%21,%22,%23,%24,%25,%26,%27,%28,%29,%30,%31}, [%32];" \
        : "=r"((r)[0]),"=r"((r)[1]),"=r"((r)[2]),"=r"((r)[3]),"=r"((r)[4]),"=r"((r)[5]),"=r"((r)[6]),"=r"((r)[7]), \
          "=r"((r)[8]),"=r"((r)[9]),"=r"((r)[10]),"=r"((r)[11]),"=r"((r)[12]),"=r"((r)[13]),"=r"((r)[14]),"=r"((r)[15]), \
          "=r"((r)[16]),"=r"((r)[17]),"=r"((r)[18]),"=r"((r)[19]),"=r"((r)[20]),"=r"((r)[21]),"=r"((r)[22]),"=r"((r)[23]), \
          "=r"((r)[24]),"=r"((r)[25]),"=r"((r)[26]),"=r"((r)[27]),"=r"((r)[28]),"=r"((r)[29]),"=r"((r)[30]),"=r"((r)[31]) \
        : "r"(tma))

__device__ __forceinline__ uint64_t smem_desc(uint32_t addr) {
    // SW128, version=1 (Blackwell), LBO=1, SBO=64
    return 0x4000404000010000ULL | (uint64_t)((addr >> 4) & 0x3FFF);
}
__device__ __forceinline__ void mma_bf16_ss(uint32_t d, uint64_t ad, uint64_t bd,
                                            uint32_t idesc, uint32_t en) {
    asm volatile(
        "{\n\t.reg .pred p;\n\tsetp.ne.u32 p, %4, 0;\n\t"
        "tcgen05.mma.cta_group::1.kind::f16 [%0], %1, %2, %3, {%5,%5,%5,%5}, p;\n\t}"
        :: "r"(d), "l"(ad), "l"(bd), "r"(idesc), "r"(en), "r"(0u) : "memory");
}
#define IDESC(NN) (0x8000490u | ((uint32_t)((NN) / 8) << 17))

// cp.async ROWS x 64 bf16 (one 128B swizzle row per row) from src (+k0 elems)
// into SW128 smem tile at dst.
__device__ __forceinline__ void copy_rows(const __nv_bfloat16* __restrict__ src,
                                          int stride, int k0, uint32_t dst,
                                          int rows, int tid) {
    for (int s = tid; s < rows * 8; s += 256) {
        int r = s >> 3, seg = s & 7;
        const char* sp = (const char*)(src + (size_t)r * stride + k0) + seg * 16;
        uint32_t off = (uint32_t)(r * 128 + seg * 16);
        uint32_t sw = off ^ ((off >> 3) & 0x70u);
        CP16(dst + sw, sp);
    }
}

// Issue one K=64 chunk: 3 split-products x 4 K-steps, accumulating into TMEM.
__device__ __forceinline__ void issue_chunk(uint32_t d, uint32_t ahi, uint32_t alo,
                                            uint32_t bhi, uint32_t blo,
                                            uint32_t idesc, bool first) {
    uint64_t AH = smem_desc(ahi), AL = smem_desc(alo);
    uint64_t BH = smem_desc(bhi), BL = smem_desc(blo);
#pragma unroll
    for (int ks = 0; ks < 4; ks++) mma_bf16_ss(d, AH + 2 * ks, BH + 2 * ks, idesc, (first && ks == 0) ? 0u : 1u);
#pragma unroll
    for (int ks = 0; ks < 4; ks++) mma_bf16_ss(d, AH + 2 * ks, BL + 2 * ks, idesc, 1u);
#pragma unroll
    for (int ks = 0; ks < 4; ks++) mma_bf16_ss(d, AL + 2 * ks, BH + 2 * ks, idesc, 1u);
}
#endif  // USE_TCGEN05

// ---------------- spectral norm ---------------------------------------------
__global__ void sn_kernel(const float* __restrict__ Wq, const float* __restrict__ uq, const float* __restrict__ bq,
                          const float* __restrict__ Wk, const float* __restrict__ uk, const float* __restrict__ bk,
                          const float* __restrict__ Wv, const float* __restrict__ uv, const float* __restrict__ bv) {
    const float* W; const float* u; const float* bias; int out; int dst;
    if (blockIdx.x == 0)      { W = Wq; u = uq; bias = bq; out = CQ;   dst = 0;   }
    else if (blockIdx.x == 1) { W = Wk; u = uk; bias = bk; out = CQ;   dst = 64;  }
    else                      { W = Wv; u = uv; bias = bv; out = C_IN; dst = 128; }

    __shared__ float su[C_IN];
    __shared__ float sv[C_IN];
    __shared__ float red[512];
    int tid = threadIdx.x;

    if (tid < out) { su[tid] = u[tid]; g_bias[dst + tid] = bias[tid]; }
    __syncthreads();

    float t = 0.f;
    for (int i = 0; i < out; i++) t += W[i * C_IN + tid] * su[i];
    red[tid] = t * t;
    __syncthreads();
    for (int s = 256; s > 0; s >>= 1) { if (tid < s) red[tid] += red[tid + s]; __syncthreads(); }
    float nv = sqrtf(red[0]);
    sv[tid] = t / nv;
    __syncthreads();

    float p = 0.f;
    for (int i = tid; i < out; i += blockDim.x) {
        float r = 0.f;
        for (int j = 0; j < C_IN; j++) r += W[i * C_IN + j] * sv[j];
        p += r * r;
    }
    red[tid] = p;
    __syncthreads();
    for (int s = 256; s > 0; s >>= 1) { if (tid < s) red[tid] += red[tid + s]; __syncthreads(); }
    float inv_sigma = rsqrtf(red[0]);

    for (int e = tid; e < out * C_IN; e += blockDim.x) {
        float val = W[e] * inv_sigma;
        __nv_bfloat16 h, l;
        split1(val, h, l);
        g_Wn_hi[(size_t)dst * C_IN + e] = h;
        g_Wn_lo[(size_t)dst * C_IN + e] = l;
    }
}

// ---------------- x transpose + split ----------------------------------------
__global__ void transpose_kernel(const float* __restrict__ x) {
    __shared__ float t[32][33];
    int b = blockIdx.z, c0 = blockIdx.y * 32, n0 = blockIdx.x * 32;
    int tx = threadIdx.x, ty = threadIdx.y;
    const float* src = x + (size_t)b * C_IN * N_TOK;
    size_t dbase = (size_t)b * N_TOK * C_IN;
#pragma unroll
    for (int i = ty; i < 32; i += 8) t[i][tx] = src[(size_t)(c0 + i) * N_TOK + n0 + tx];
    __syncthreads();
#pragma unroll
    for (int i = ty; i < 32; i += 8) {
        float val = t[tx][i];
        __nv_bfloat16 h, l;
        split1(val, h, l);
        size_t off = dbase + (size_t)(n0 + i) * C_IN + c0 + tx;
        g_xT_hi[off] = h;
        g_xT_lo[off] = l;
    }
}

// ---------------- proj: D[n=128][ocat tile] ---------------------------------
// grid (8, 3, BATCH): n0 = x*128, o0 = y*256, NN = y<2 ? 256 : 128
__global__ void __launch_bounds__(256) proj_mma() {
#if USE_TCGEN05
    extern __shared__ char dyn[];
    __shared__ uint32_t s_tmem;
    __shared__ uint64_t s_mb[2];
    __shared__ float s_bias[256];
    __shared__ float tb[4 * 32 * 33];

    int tid = threadIdx.x, wid = tid >> 5, lane = tid & 31;
    int b = blockIdx.z, n0 = blockIdx.x * 128, y = blockIdx.y, o0 = y * 256;
    int NN = (y < 2) ? 256 : 128;
    uint32_t idesc = IDESC(NN);

    uint32_t dynb = (cvta_smem(dyn) + 1023u) & ~1023u;
    uint32_t AHI[2], ALO[2], BHI[2], BLO[2];
#pragma unroll
    for (int p = 0; p < 2; p++) {
        uint32_t base = dynb + (uint32_t)p * 98304u;
        AHI[p] = base; ALO[p] = base + 16384u; BHI[p] = base + 32768u; BLO[p] = base + 65536u;
    }
    uint32_t mb0 = cvta_smem(&s_mb[0]), mb1 = cvta_smem(&s_mb[1]);

    if (wid == 0) { TC_ALLOC(cvta_smem(&s_tmem), 256); TC_RELINQ(); }
    if (tid == 0) { MB_INIT(mb0, 1); MB_INIT(mb1, 1); }
    for (int i = tid; i < NN; i += 256) s_bias[i] = g_bias[o0 + i];
    __syncthreads();
    uint32_t tmem = s_tmem;

    const __nv_bfloat16* Ah = g_xT_hi + ((size_t)b * N_TOK + n0) * C_IN;
    const __nv_bfloat16* Al = g_xT_lo + ((size_t)b * N_TOK + n0) * C_IN;
    const __nv_bfloat16* Bh = g_Wn_hi + (size_t)o0 * C_IN;
    const __nv_bfloat16* Bl = g_Wn_lo + (size_t)o0 * C_IN;

    int ph0 = 0, ph1 = 0;
    const int KT = C_IN / 64;
    for (int kt = 0; kt < KT; kt++) {
        int p = kt & 1;
        if (kt >= 2) {
            if (p == 0) { MB_WAIT(mb0, ph0); ph0 ^= 1; }
            else        { MB_WAIT(mb1, ph1); ph1 ^= 1; }
        }
        int k0 = kt * 64;
        copy_rows(Ah, C_IN, k0, AHI[p], 128, tid);
        copy_rows(Al, C_IN, k0, ALO[p], 128, tid);
        copy_rows(Bh, C_IN, k0, BHI[p], NN, tid);
        copy_rows(Bl, C_IN, k0, BLO[p], NN, tid);
        CP_COMMIT();
        CP_WAIT0();
        __syncthreads();
        if (wid == 0 && elect_one()) {
            FENCE_ASYNC();
            issue_chunk(tmem, AHI[p], ALO[p], BHI[p], BLO[p], idesc, kt == 0);
            TC_COMMIT(p == 0 ? mb0 : mb1);
        }
    }
    MB_WAIT(mb0, ph0);
    MB_WAIT(mb1, ph1);
    TC_FENCE_AFTER();
    __syncthreads();

    for (int c0 = 0; c0 < NN; c0 += 32) {
        bool dir = (o0 + c0) < 128;
        if (tid < 128) {
            uint32_t r[32];
            LDTM32(r, tmem + c0);
            TC_WAIT_LD();
            if (dir) {  // q/k region: write qT/kT hi/lo [n][o]
                int n = n0 + wid * 32 + lane;
                int oo = (c0 < 64) ? c0 : (c0 - 64);
                uint32_t* hi = (uint32_t*)((c0 < 64) ? g_qT_hi : g_kT_hi) + ((size_t)b * N_TOK + n) * 32;
                uint32_t* lo = (uint32_t*)((c0 < 64) ? g_qT_lo : g_kT_lo) + ((size_t)b * N_TOK + n) * 32;
#pragma unroll
                for (int j = 0; j < 32; j += 4) {
                    uint32_t h0, l0, h1, l1;
                    pack_split2(__uint_as_float(r[j + 0]) + s_bias[c0 + j + 0],
                                __uint_as_float(r[j + 1]) + s_bias[c0 + j + 1], h0, l0);
                    pack_split2(__uint_as_float(r[j + 2]) + s_bias[c0 + j + 2],
                                __uint_as_float(r[j + 3]) + s_bias[c0 + j + 3], h1, l1);
                    *(uint2*)(hi + ((oo + j) >> 1)) = make_uint2(h0, h1);
                    *(uint2*)(lo + ((oo + j) >> 1)) = make_uint2(l0, l1);
                }
            } else {    // v region: stage for transpose
                int cb = wid * 1056 + lane * 33;
#pragma unroll
                for (int j = 0; j < 32; j++) tb[cb + j] = __uint_as_float(r[j]);
            }
        }
        if (!dir) {
            __syncthreads();
            int cg = o0 + c0 - 128;
#pragma unroll
            for (int i = 0; i < 16; i++) {
                int rid = wid * 16 + i;
                int wsrc = rid >> 5, j = rid & 31;
                float val = tb[wsrc * 1056 + lane * 33 + j] + s_bias[c0 + j];
                __nv_bfloat16 h, l;
                split1(val, h, l);
                size_t off = ((size_t)b * C_IN + cg + j) * N_TOK + n0 + wsrc * 32 + lane;
                g_v_hi[off] = h;
                g_v_lo[off] = l;
            }
            __syncthreads();
        }
    }
    __syncthreads();
    if (wid == 0) TC_DEALLOC(tmem, 256);
#else
    int tid = threadIdx.x;
    int b = blockIdx.z, n0 = blockIdx.x * 128, y = blockIdx.y, o0 = y * 256;
    int NN = (y < 2) ? 256 : 128;
    for (int e = tid; e < 128 * NN; e += 256) {
        int n = n0 + (e & 127);
        int oc = o0 + (e >> 7);
        const __nv_bfloat16* xh = g_xT_hi + ((size_t)b * N_TOK + n) * C_IN;
        const __nv_bfloat16* xl = g_xT_lo + ((size_t)b * N_TOK + n) * C_IN;
        const __nv_bfloat16* wh = g_Wn_hi + (size_t)oc * C_IN;
        const __nv_bfloat16* wl = g_Wn_lo + (size_t)oc * C_IN;
        float s = 0.f;
        for (int c = 0; c < C_IN; c++) {
            float xa = __bfloat162float(xh[c]) + __bfloat162float(xl[c]);
            float wa = __bfloat162float(wh[c]) + __bfloat162float(wl[c]);
            s += xa * wa;
        }
        s += g_bias[oc];
        __nv_bfloat16 h, l;
        split1(s, h, l);
        if (oc < 64)       { size_t o = ((size_t)b * N_TOK + n) * CQ + oc;        g_qT_hi[o] = h; g_qT_lo[o] = l; }
        else if (oc < 128) { size_t o = ((size_t)b * N_TOK + n) * CQ + (oc - 64); g_kT_hi[o] = h; g_kT_lo[o] = l; }
        else               { size_t o = ((size_t)b * C_IN + (oc - 128)) * N_TOK + n; g_v_hi[o] = h; g_v_lo[o] = l; }
    }
#endif
}

// ---------------- qk: D[n=128][m=256] -> S[m][n] fp32 -----------------------
// grid (8, 4, BATCH)
__global__ void __launch_bounds__(256) qk_mma() {
#if USE_TCGEN05
    extern __shared__ char dyn[];
    __shared__ uint32_t s_tmem;
    __shared__ uint64_t s_mb;

    int tid = threadIdx.x, wid = tid >> 5, lane = tid & 31;
    int b = blockIdx.z, n0 = blockIdx.x * 128, m0 = blockIdx.y * 256;
    uint32_t idesc = IDESC(256);

    uint32_t dynb = (cvta_smem(dyn) + 1023u) & ~1023u;
    uint32_t AHI = dynb, ALO = dynb + 16384u, BHI = dynb + 32768u, BLO = dynb + 65536u;
    uint32_t mb = cvta_smem(&s_mb);

    if (wid == 0) { TC_ALLOC(cvta_smem(&s_tmem), 256); TC_RELINQ(); }
    if (tid == 0) MB_INIT(mb, 1);
    __syncthreads();
    uint32_t tmem = s_tmem;

    copy_rows(g_qT_hi + ((size_t)b * N_TOK + n0) * CQ, CQ, 0, AHI, 128, tid);
    copy_rows(g_qT_lo + ((size_t)b * N_TOK + n0) * CQ, CQ, 0, ALO, 128, tid);
    copy_rows(g_kT_hi + ((size_t)b * N_TOK + m0) * CQ, CQ, 0, BHI, 256, tid);
    copy_rows(g_kT_lo + ((size_t)b * N_TOK + m0) * CQ, CQ, 0, BLO, 256, tid);
    CP_COMMIT();
    CP_WAIT0();
    __syncthreads();
    if (wid == 0 && elect_one()) {
        FENCE_ASYNC();
        issue_chunk(tmem, AHI, ALO, BHI, BLO, idesc, true);
        TC_COMMIT(mb);
    }
    MB_WAIT(mb, 0);
    TC_FENCE_AFTER();

    float* Sb = g_S + (size_t)b * N_TOK * N_TOK;
    for (int c0 = 0; c0 < 256; c0 += 32) {
        if (tid < 128) {
            uint32_t r[32];
            LDTM32(r, tmem + c0);
            TC_WAIT_LD();
            int n = n0 + wid * 32 + lane;
#pragma unroll
            for (int j = 0; j < 32; j++)
                Sb[(size_t)(m0 + c0 + j) * N_TOK + n] = __uint_as_float(r[j]);
        }
    }
    __syncthreads();
    if (wid == 0) TC_DEALLOC(tmem, 256);
#else
    int tid = threadIdx.x;
    int b = blockIdx.z, n0 = blockIdx.x * 128, m0 = blockIdx.y * 256;
    float* Sb = g_S + (size_t)b * N_TOK * N_TOK;
    for (int e = tid; e < 128 * 256; e += 256) {
        int n = n0 + (e & 127);
        int m = m0 + (e >> 7);
        const __nv_bfloat16* qh = g_qT_hi + ((size_t)b * N_TOK + n) * CQ;
        const __nv_bfloat16* ql = g_qT_lo + ((size_t)b * N_TOK + n) * CQ;
        const __nv_bfloat16* kh = g_kT_hi + ((size_t)b * N_TOK + m) * CQ;
        const __nv_bfloat16* kl = g_kT_lo + ((size_t)b * N_TOK + m) * CQ;
        float s = 0.f;
        for (int o = 0; o < CQ; o++)
            s += (__bfloat162float(qh[o]) + __bfloat162float(ql[o])) *
                 (__bfloat162float(kh[o]) + __bfloat162float(kl[o]));
        Sb[(size_t)m * N_TOK + n] = s;
    }
#endif
}

// ---------------- row softmax -> P hi/lo ------------------------------------
__global__ void __launch_bounds__(256) softmax_kernel() {
    int b = blockIdx.y, m = blockIdx.x;
    const float* row = g_S + ((size_t)b * N_TOK + m) * N_TOK;
    int tid = threadIdx.x;
    __shared__ float smr[8];

    float4 v = ((const float4*)row)[tid];
    float mx = fmaxf(fmaxf(v.x, v.y), fmaxf(v.z, v.w));
#pragma unroll
    for (int s = 16; s; s >>= 1) mx = fmaxf(mx, __shfl_xor_sync(0xffffffffu, mx, s));
    if ((tid & 31) == 0) smr[tid >> 5] = mx;
    __syncthreads();
    mx = smr[0];
#pragma unroll
    for (int w = 1; w < 8; w++) mx = fmaxf(mx, smr[w]);
    __syncthreads();

    v.x = __expf(v.x - mx); v.y = __expf(v.y - mx);
    v.z = __expf(v.z - mx); v.w = __expf(v.w - mx);
    float s4 = v.x + v.y + v.z + v.w;
#pragma unroll
    for (int s = 16; s; s >>= 1) s4 += __shfl_xor_sync(0xffffffffu, s4, s);
    if ((tid & 31) == 0) smr[tid >> 5] = s4;
    __syncthreads();
    float tot = 0.f;
#pragma unroll
    for (int w = 0; w < 8; w++) tot += smr[w];
    float inv = 1.f / tot;
    v.x *= inv; v.y *= inv; v.z *= inv; v.w *= inv;

    uint32_t h0, l0, h1, l1;
    pack_split2(v.x, v.y, h0, l0);
    pack_split2(v.z, v.w, h1, l1);
    size_t ro = ((size_t)b * N_TOK + m) * 512;
    ((uint2*)((uint32_t*)g_P_hi + ro))[tid] = make_uint2(h0, h1);
    ((uint2*)((uint32_t*)g_P_lo + ro))[tid] = make_uint2(l0, l1);
}

// ---------------- av: D[m=128][c=256], out = gamma*D + x --------------------
// grid (8, 2, BATCH)
__global__ void __launch_bounds__(256) av_mma(const float* __restrict__ x,
                                              const float* __restrict__ gamma_p,
                                              float* __restrict__ out) {
#if USE_TCGEN05
    extern __shared__ char dyn[];
    __shared__ uint32_t s_tmem;
    __shared__ uint64_t s_mb[2];

    int tid = threadIdx.x, wid = tid >> 5, lane = tid & 31;
    int b = blockIdx.z, m0 = blockIdx.x * 128, c0g = blockIdx.y * 256;
    uint32_t idesc = IDESC(256);

    uint32_t dynb = (cvta_smem(dyn) + 1023u) & ~1023u;
    uint32_t AHI[2], ALO[2], BHI[2], BLO[2];
#pragma unroll
    for (int p = 0; p < 2; p++) {
        uint32_t base = dynb + (uint32_t)p * 98304u;
        AHI[p] = base; ALO[p] = base + 16384u; BHI[p] = base + 32768u; BLO[p] = base + 65536u;
    }
    uint32_t mb0 = cvta_smem(&s_mb[0]), mb1 = cvta_smem(&s_mb[1]);

    if (wid == 0) { TC_ALLOC(cvta_smem(&s_tmem), 256); TC_RELINQ(); }
    if (tid == 0) { MB_INIT(mb0, 1); MB_INIT(mb1, 1); }
    __syncthreads();
    uint32_t tmem = s_tmem;

    const __nv_bfloat16* Ah = g_P_hi + ((size_t)b * N_TOK + m0) * N_TOK;
    const __nv_bfloat16* Al = g_P_lo + ((size_t)b * N_TOK + m0) * N_TOK;
    const __nv_bfloat16* Bh = g_v_hi + ((size_t)b * C_IN + c0g) * N_TOK;
    const __nv_bfloat16* Bl = g_v_lo + ((size_t)b * C_IN + c0g) * N_TOK;

    int ph0 = 0, ph1 = 0;
    const int KT = N_TOK / 64;
    for (int kt = 0; kt < KT; kt++) {
        int p = kt & 1;
        if (kt >= 2) {
            if (p == 0) { MB_WAIT(mb0, ph0); ph0 ^= 1; }
            else        { MB_WAIT(mb1, ph1); ph1 ^= 1; }
        }
        int k0 = kt * 64;
        copy_rows(Ah, N_TOK, k0, AHI[p], 128, tid);
        copy_rows(Al, N_TOK, k0, ALO[p], 128, tid);
        copy_rows(Bh, N_TOK, k0, BHI[p], 256, tid);
        copy_rows(Bl, N_TOK, k0, BLO[p], 256, tid);
        CP_COMMIT();
        CP_WAIT0();
        __syncthreads();
        if (wid == 0 && elect_one()) {
            FENCE_ASYNC();
            issue_chunk(tmem, AHI[p], ALO[p], BHI[p], BLO[p], idesc, kt == 0);
            TC_COMMIT(p == 0 ? mb0 : mb1);
        }
    }
    MB_WAIT(mb0, ph0);
    MB_WAIT(mb1, ph1);
    TC_FENCE_AFTER();

    float g = *gamma_p;
    for (int c0 = 0; c0 < 256; c0 += 32) {
        if (tid < 128) {
            uint32_t r[32];
            LDTM32(r, tmem + c0);
            TC_WAIT_LD();
            int m = m0 + wid * 32 + lane;
#pragma unroll
            for (int j = 0; j < 32; j++) {
                int c = c0g + c0 + j;
                size_t off = ((size_t)b * C_IN + c) * N_TOK + m;
                out[off] = g * __uint_as_float(r[j]) + x[off];
            }
        }
    }
    __syncthreads();
    if (wid == 0) TC_DEALLOC(tmem, 256);
#else
    int tid = threadIdx.x;
    int b = blockIdx.z, m0 = blockIdx.x * 128, c0g = blockIdx.y * 256;
    float g = *gamma_p;
    for (int e = tid; e < 128 * 256; e += 256) {
        int m = m0 + (e & 127);
        int c = c0g + (e >> 7);
        const __nv_bfloat16* vh = g_v_hi + ((size_t)b * C_IN + c) * N_TOK;
        const __nv_bfloat16* vl = g_v_lo + ((size_t)b * C_IN + c) * N_TOK;
        const __nv_bfloat16* ph = g_P_hi + ((size_t)b * N_TOK + m) * N_TOK;
        const __nv_bfloat16* pl = g_P_lo + ((size_t)b * N_TOK + m) * N_TOK;
        float s = 0.f;
        for (int n = 0; n < N_TOK; n++)
            s += (__bfloat162float(vh[n]) + __bfloat162float(vl[n])) *
                 (__bfloat162float(ph[n]) + __bfloat162float(pl[n]));
        size_t off = ((size_t)b * C_IN + c) * N_TOK + m;
        out[off] = g * s + x[off];
    }
#endif
}

// ---------------- launch -----------------------------------------------------
extern "C" void kernel_launch(void* const* d_in, const int* in_sizes, int n_in,
                              void* d_out, int out_size) {
    const float* x     = (const float*)d_in[0];
    const float* Wq    = (const float*)d_in[1];
    const float* bq    = (const float*)d_in[2];
    const float* uq    = (const float*)d_in[3];
    const float* Wk    = (const float*)d_in[4];
    const float* bk    = (const float*)d_in[5];
    const float* uk    = (const float*)d_in[6];
    const float* Wv    = (const float*)d_in[7];
    const float* bv    = (const float*)d_in[8];
    const float* uv    = (const float*)d_in[9];
    const float* gamma = (const float*)d_in[10];
    float* out = (float*)d_out;

    cudaFuncSetAttribute(proj_mma, cudaFuncAttributeMaxDynamicSharedMemorySize, 197632);
    cudaFuncSetAttribute(qk_mma,   cudaFuncAttributeMaxDynamicSharedMemorySize, 99328);
    cudaFuncSetAttribute(av_mma,   cudaFuncAttributeMaxDynamicSharedMemorySize, 197632);

    sn_kernel<<<3, 512>>>(Wq, uq, bq, Wk, uk, bk, Wv, uv, bv);
    transpose_kernel<<<dim3(32, 16, BATCH), dim3(32, 8)>>>(x);
    proj_mma<<<dim3(8, 3, BATCH), 256, 197632>>>();
    qk_mma<<<dim3(8, 4, BATCH), 256, 99328>>>();
    softmax_kernel<<<dim3(N_TOK, BATCH), 256>>>();
    av_mma<<<dim3(8, 2, BATCH), 256, 197632>>>(x, gamma, out);
}

// round 9
// speedup vs baseline: 1.4175x; 1.0173x over previous
#include <cuda_runtime.h>
#include <cuda_bf16.h>
#include <math.h>
#include <stdint.h>

#define N_TOK 1024
#define C_IN  512
#define CQ    64
#define BATCH 32

#if defined(__CUDA_ARCH__)
#if defined(__CUDA_ARCH_FEAT_SM103_ALL)
#define USE_TCGEN05 1
#else
#define USE_TCGEN05 0
#endif
#else
#define USE_TCGEN05 0
#endif

// ---------------- scratch (device globals; no allocation allowed) ----------
__device__ __align__(128) __nv_bfloat16 g_Wn_hi[640 * C_IN];   // rows: q 0-63, k 64-127, v 128-639 (K-major)
__device__ __align__(128) __nv_bfloat16 g_Wn_lo[640 * C_IN];
__device__ __align__(128) float g_bias[640];
__device__ __align__(128) __nv_bfloat16 g_xT_hi[(size_t)BATCH * N_TOK * C_IN];  // [b][n][c]
__device__ __align__(128) __nv_bfloat16 g_xT_lo[(size_t)BATCH * N_TOK * C_IN];
__device__ __align__(128) __nv_bfloat16 g_qT_hi[(size_t)BATCH * N_TOK * CQ];    // [b][n][o]
__device__ __align__(128) __nv_bfloat16 g_qT_lo[(size_t)BATCH * N_TOK * CQ];
__device__ __align__(128) __nv_bfloat16 g_kT_hi[(size_t)BATCH * N_TOK * CQ];    // [b][m][o]
__device__ __align__(128) __nv_bfloat16 g_kT_lo[(size_t)BATCH * N_TOK * CQ];
__device__ __align__(128) __nv_bfloat16 g_v_hi [(size_t)BATCH * C_IN * N_TOK];  // [b][c][n]
__device__ __align__(128) __nv_bfloat16 g_v_lo [(size_t)BATCH * C_IN * N_TOK];
__device__ __align__(128) float         g_S    [(size_t)BATCH * N_TOK * N_TOK]; // [b][m][n]
__device__ __align__(128) __nv_bfloat16 g_P_hi [(size_t)BATCH * N_TOK * N_TOK]; // [b][m][n]
__device__ __align__(128) __nv_bfloat16 g_P_lo [(size_t)BATCH * N_TOK * N_TOK];

// ---------------- common helpers --------------------------------------------
__device__ __forceinline__ uint32_t cvta_smem(const void* p) {
    uint32_t a;
    asm("{ .reg .u64 t; cvta.to.shared.u64 t, %1; cvt.u32.u64 %0, t; }" : "=r"(a) : "l"(p));
    return a;
}
__device__ __forceinline__ void pack_split2(float a, float b, uint32_t& h, uint32_t& l) {
    __nv_bfloat16 ah = __float2bfloat16(a);
    __nv_bfloat16 bh = __float2bfloat16(b);
    __nv_bfloat16 al = __float2bfloat16(a - __bfloat162float(ah));
    __nv_bfloat16 bl = __float2bfloat16(b - __bfloat162float(bh));
    h = (uint32_t)__bfloat16_as_ushort(ah) | ((uint32_t)__bfloat16_as_ushort(bh) << 16);
    l = (uint32_t)__bfloat16_as_ushort(al) | ((uint32_t)__bfloat16_as_ushort(bl) << 16);
}
__device__ __forceinline__ void split1(float v, __nv_bfloat16& h, __nv_bfloat16& l) {
    h = __float2bfloat16(v);
    l = __float2bfloat16(v - __bfloat162float(h));
}

#if USE_TCGEN05
__device__ __forceinline__ int elect_one() {
    uint32_t pred;
    asm volatile("{\n\t.reg .pred p;\n\telect.sync _|p, 0xFFFFFFFF;\n\tselp.b32 %0, 1, 0, p;\n\t}" : "=r"(pred));
    return (int)pred;
}
#define MB_INIT(addr, cnt) \
    asm volatile("mbarrier.init.shared.b64 [%0], %1;" :: "r"(addr), "r"((uint32_t)(cnt)) : "memory")
#define MB_WAIT(addr, phv) do { \
    uint32_t _m = (addr), _p = (uint32_t)(phv), _d; \
    asm volatile("{\n\t.reg .pred p;\n\t" \
        "mbarrier.try_wait.parity.acquire.cta.shared::cta.b64 p, [%1], %2;\n\t" \
        "selp.b32 %0,1,0,p;\n\t}" : "=r"(_d) : "r"(_m), "r"(_p) : "memory"); \
    while (!_d) { \
        asm volatile("{\n\t.reg .pred p;\n\t" \
            "mbarrier.try_wait.parity.acquire.cta.shared::cta.b64 p, [%1], %2, 0x989680;\n\t" \
            "selp.b32 %0,1,0,p;\n\t}" : "=r"(_d) : "r"(_m), "r"(_p) : "memory"); \
    } \
} while (0)
#define TC_ALLOC(addr, n) \
    asm volatile("tcgen05.alloc.cta_group::1.sync.aligned.shared::cta.b32 [%0], %1;" :: "r"(addr), "r"((uint32_t)(n)) : "memory")
#define TC_RELINQ() \
    asm volatile("tcgen05.relinquish_alloc_permit.cta_group::1.sync.aligned;")
#define TC_DEALLOC(tm, n) \
    asm volatile("tcgen05.dealloc.cta_group::1.sync.aligned.b32 %0, %1;" :: "r"(tm), "r"((uint32_t)(n)))
#define TC_COMMIT(addr) \
    asm volatile("tcgen05.commit.cta_group::1.mbarrier::arrive::one.shared::cluster.b64 [%0];" :: "r"(addr) : "memory")
#define TC_FENCE_AFTER()  asm volatile("tcgen05.fence::after_thread_sync;" ::: "memory")
#define TC_WAIT_LD()      asm volatile("tcgen05.wait::ld.sync.aligned;" ::: "memory")
#define FENCE_ASYNC()     asm volatile("fence.proxy.async.shared::cta;" ::: "memory")
#define CP16(dst, src)  asm volatile("cp.async.cg.shared.global [%0], [%1], 16;" :: "r"(dst), "l"(src) : "memory")
#define CP_COMMIT()     asm volatile("cp.async.commit_group;" ::: "memory")
#define CP_WAIT0()      asm volatile("cp.async.wait_group 0;" ::: "memory")

#define LDTM32(r, tma) \
    asm volatile("tcgen05.ld.sync.aligned.32x32b.x32.b32 " \
        "{%0,%1,%2,%3,%4,%5,%6,%7,%8,%9,%10,%11,%12,%13,%14,%15," \
        "%16,%17,%18,%19,%20,%21,%22,%23,%24,%25,%26,%27,%28,%29,%30,%31}, [%32];" \
        : "=r"((r)[0]),"=r"((r)[1]),"=r"((r)[2]),"=r"((r)[3]),"=r"((r)[4]),"=r"((r)[5]),"=r"((r)[6]),"=r"((r)[7]), \
          "=r"((r)[8]),"=r"((r)[9]),"=r"((r)[10]),"=r"((r)[11]),"=r"((r)[12]),"=r"((r)[13]),"=r"((r)[14]),"=r"((r)[15]), \
          "=r"((r)[16]),"=r"((r)[17]),"=r"((r)[18]),"=r"((r)[19]),"=r"((r)[20]),"=r"((r)[21]),"=r"((r)[22]),"=r"((r)[23]), \
          "=r"((r)[24]),"=r"((r)[25]),"=r"((r)[26]),"=r"((r)[27]),"=r"((r)[28]),"=r"((r)[29]),"=r"((r)[30]),"=r"((r)[31]) \
        : "r"(tma))

// SW128 desc (128B rows): layout 2, version 1, SBO=64, LBO=1
__device__ __forceinline__ uint64_t smem_desc(uint32_t addr) {
    return 0x4000404000010000ULL | (uint64_t)((addr >> 4) & 0x3FFF);
}
// SW64 desc (64B rows): layout 4, version 1, SBO=32, LBO=1
__device__ __forceinline__ uint64_t smem_desc64(uint32_t addr) {
    return 0x8000402000010000ULL | (uint64_t)((addr >> 4) & 0x3FFF);
}
__device__ __forceinline__ void mma_bf16_ss(uint32_t d, uint64_t ad, uint64_t bd,
                                            uint32_t idesc, uint32_t en) {
    asm volatile(
        "{\n\t.reg .pred p;\n\tsetp.ne.u32 p, %4, 0;\n\t"
        "tcgen05.mma.cta_group::1.kind::f16 [%0], %1, %2, %3, {%5,%5,%5,%5}, p;\n\t}"
        :: "r"(d), "l"(ad), "l"(bd), "r"(idesc), "r"(en), "r"(0u) : "memory");
}
#define IDESC(NN) (0x8000490u | ((uint32_t)((NN) / 8) << 17))

// ---- SW128 (128B rows, K-chunk 64) copy: rows x 8 segs of 16B ----
__device__ __forceinline__ void copy_rows(const __nv_bfloat16* __restrict__ src,
                                          int stride, int k0, uint32_t dst,
                                          int rows, int tid) {
    for (int s = tid; s < rows * 8; s += 256) {
        int r = s >> 3, seg = s & 7;
        const char* sp = (const char*)(src + (size_t)r * stride + k0) + seg * 16;
        uint32_t off = (uint32_t)(r * 128 + seg * 16);
        uint32_t sw = off ^ ((off >> 3) & 0x70u);
        CP16(dst + sw, sp);
    }
}
// ---- SW64 (64B rows, K-chunk 32) copy: rows x 4 segs of 16B ----
__device__ __forceinline__ void copy_rows64(const __nv_bfloat16* __restrict__ src,
                                            int stride, int k0, uint32_t dst,
                                            int rows, int tid) {
    for (int s = tid; s < rows * 4; s += 256) {
        int r = s >> 2, seg = s & 3;
        const char* sp = (const char*)(src + (size_t)r * stride + k0) + seg * 16;
        uint32_t off = (uint32_t)(r * 64 + seg * 16);
        uint32_t sw = off ^ ((off >> 3) & 0x30u);
        CP16(dst + sw, sp);
    }
}

// SW128 chunk (K=64): 3 products x 4 K-steps
__device__ __forceinline__ void issue_chunk(uint32_t d, uint32_t ahi, uint32_t alo,
                                            uint32_t bhi, uint32_t blo,
                                            uint32_t idesc, bool first) {
    uint64_t AH = smem_desc(ahi), AL = smem_desc(alo);
    uint64_t BH = smem_desc(bhi), BL = smem_desc(blo);
#pragma unroll
    for (int ks = 0; ks < 4; ks++) mma_bf16_ss(d, AH + 2 * ks, BH + 2 * ks, idesc, (first && ks == 0) ? 0u : 1u);
#pragma unroll
    for (int ks = 0; ks < 4; ks++) mma_bf16_ss(d, AH + 2 * ks, BL + 2 * ks, idesc, 1u);
#pragma unroll
    for (int ks = 0; ks < 4; ks++) mma_bf16_ss(d, AL + 2 * ks, BH + 2 * ks, idesc, 1u);
}

// SW64 chunk (K=32): per N-half (256 cols): 3 products x 2 K-steps
__device__ __forceinline__ void issue_chunk64(uint32_t d, uint32_t ahi, uint32_t alo,
                                              uint32_t bhi, uint32_t blo,
                                              int halves, uint32_t idesc, bool first) {
    uint64_t AH = smem_desc64(ahi), AL = smem_desc64(alo);
#pragma unroll
    for (int h = 0; h < 2; h++) {
        if (h >= halves) break;
        uint64_t BH = smem_desc64(bhi + (uint32_t)h * 16384u);
        uint64_t BL = smem_desc64(blo + (uint32_t)h * 16384u);
        uint32_t dd = d + (uint32_t)h * 256u;
#pragma unroll
        for (int ks = 0; ks < 2; ks++) mma_bf16_ss(dd, AH + 2 * ks, BH + 2 * ks, idesc, (first && ks == 0) ? 0u : 1u);
#pragma unroll
        for (int ks = 0; ks < 2; ks++) mma_bf16_ss(dd, AH + 2 * ks, BL + 2 * ks, idesc, 1u);
#pragma unroll
        for (int ks = 0; ks < 2; ks++) mma_bf16_ss(dd, AL + 2 * ks, BH + 2 * ks, idesc, 1u);
    }
}
#endif  // USE_TCGEN05

// ---------------- spectral norm ---------------------------------------------
__global__ void sn_kernel(const float* __restrict__ Wq, const float* __restrict__ uq, const float* __restrict__ bq,
                          const float* __restrict__ Wk, const float* __restrict__ uk, const float* __restrict__ bk,
                          const float* __restrict__ Wv, const float* __restrict__ uv, const float* __restrict__ bv) {
    const float* W; const float* u; const float* bias; int out; int dst;
    if (blockIdx.x == 0)      { W = Wq; u = uq; bias = bq; out = CQ;   dst = 0;   }
    else if (blockIdx.x == 1) { W = Wk; u = uk; bias = bk; out = CQ;   dst = 64;  }
    else                      { W = Wv; u = uv; bias = bv; out = C_IN; dst = 128; }

    __shared__ float su[C_IN];
    __shared__ float sv[C_IN];
    __shared__ float red[512];
    int tid = threadIdx.x;

    if (tid < out) { su[tid] = u[tid]; g_bias[dst + tid] = bias[tid]; }
    __syncthreads();

    float t = 0.f;
    for (int i = 0; i < out; i++) t += W[i * C_IN + tid] * su[i];
    red[tid] = t * t;
    __syncthreads();
    for (int s = 256; s > 0; s >>= 1) { if (tid < s) red[tid] += red[tid + s]; __syncthreads(); }
    float nv = sqrtf(red[0]);
    sv[tid] = t / nv;
    __syncthreads();

    float p = 0.f;
    for (int i = tid; i < out; i += blockDim.x) {
        float r = 0.f;
        for (int j = 0; j < C_IN; j++) r += W[i * C_IN + j] * sv[j];
        p += r * r;
    }
    red[tid] = p;
    __syncthreads();
    for (int s = 256; s > 0; s >>= 1) { if (tid < s) red[tid] += red[tid + s]; __syncthreads(); }
    float inv_sigma = rsqrtf(red[0]);

    for (int e = tid; e < out * C_IN; e += blockDim.x) {
        float val = W[e] * inv_sigma;
        __nv_bfloat16 h, l;
        split1(val, h, l);
        g_Wn_hi[(size_t)dst * C_IN + e] = h;
        g_Wn_lo[(size_t)dst * C_IN + e] = l;
    }
}

// ---------------- x transpose + split ----------------------------------------
__global__ void transpose_kernel(const float* __restrict__ x) {
    __shared__ float t[32][33];
    int b = blockIdx.z, c0 = blockIdx.y * 32, n0 = blockIdx.x * 32;
    int tx = threadIdx.x, ty = threadIdx.y;
    const float* src = x + (size_t)b * C_IN * N_TOK;
    size_t dbase = (size_t)b * N_TOK * C_IN;
#pragma unroll
    for (int i = ty; i < 32; i += 8) t[i][tx] = src[(size_t)(c0 + i) * N_TOK + n0 + tx];
    __syncthreads();
#pragma unroll
    for (int i = ty; i < 32; i += 8) {
        float val = t[tx][i];
        __nv_bfloat16 h, l;
        split1(val, h, l);
        size_t off = dbase + (size_t)(n0 + i) * C_IN + c0 + tx;
        g_xT_hi[off] = h;
        g_xT_lo[off] = l;
    }
}

// ---------------- proj: D[n=128][o up to 512] -------------------------------
// grid (8, 2, BATCH): n0 = x*128; y=0: o0=0, NN=512; y=1: o0=512, NN=128
// smem/buffer: AHI 8K | ALO 8K | BHI 32K | BLO 32K  (80KB), x2 buffers
__global__ void __launch_bounds__(256) proj_mma() {
#if USE_TCGEN05
    extern __shared__ char dyn[];
    __shared__ uint32_t s_tmem;
    __shared__ uint64_t s_mb[2];
    __shared__ float s_bias[512];
    __shared__ float tb[4 * 32 * 33];

    int tid = threadIdx.x, wid = tid >> 5, lane = tid & 31;
    int b = blockIdx.z, n0 = blockIdx.x * 128, y = blockIdx.y;
    int o0 = y * 512;
    int NN = (y == 0) ? 512 : 128;
    int halves = (y == 0) ? 2 : 1;
    uint32_t idesc = (y == 0) ? IDESC(256) : IDESC(128);

    uint32_t dynb = (cvta_smem(dyn) + 1023u) & ~1023u;
    uint32_t AHI[2], ALO[2], BHI[2], BLO[2];
#pragma unroll
    for (int p = 0; p < 2; p++) {
        uint32_t base = dynb + (uint32_t)p * 81920u;
        AHI[p] = base; ALO[p] = base + 8192u; BHI[p] = base + 16384u; BLO[p] = base + 49152u;
    }
    uint32_t mb0 = cvta_smem(&s_mb[0]), mb1 = cvta_smem(&s_mb[1]);

    if (wid == 0) { TC_ALLOC(cvta_smem(&s_tmem), 512); TC_RELINQ(); }
    if (tid == 0) { MB_INIT(mb0, 1); MB_INIT(mb1, 1); }
    for (int i = tid; i < NN; i += 256) s_bias[i] = g_bias[o0 + i];
    __syncthreads();
    uint32_t tmem = s_tmem;

    const __nv_bfloat16* Ah = g_xT_hi + ((size_t)b * N_TOK + n0) * C_IN;
    const __nv_bfloat16* Al = g_xT_lo + ((size_t)b * N_TOK + n0) * C_IN;
    const __nv_bfloat16* Bh = g_Wn_hi + (size_t)o0 * C_IN;
    const __nv_bfloat16* Bl = g_Wn_lo + (size_t)o0 * C_IN;

    int ph0 = 0, ph1 = 0;
    const int KT = C_IN / 32;
    for (int kt = 0; kt < KT; kt++) {
        int p = kt & 1;
        if (kt >= 2) {
            if (p == 0) { MB_WAIT(mb0, ph0); ph0 ^= 1; }
            else        { MB_WAIT(mb1, ph1); ph1 ^= 1; }
        }
        int k0 = kt * 32;
        copy_rows64(Ah, C_IN, k0, AHI[p], 128, tid);
        copy_rows64(Al, C_IN, k0, ALO[p], 128, tid);
        copy_rows64(Bh, C_IN, k0, BHI[p], NN, tid);
        copy_rows64(Bl, C_IN, k0, BLO[p], NN, tid);
        CP_COMMIT();
        CP_WAIT0();
        __syncthreads();
        if (wid == 0 && elect_one()) {
            FENCE_ASYNC();
            issue_chunk64(tmem, AHI[p], ALO[p], BHI[p], BLO[p], halves, idesc, kt == 0);
            TC_COMMIT(p == 0 ? mb0 : mb1);
        }
    }
    MB_WAIT(mb0, ph0);
    MB_WAIT(mb1, ph1);
    TC_FENCE_AFTER();
    __syncthreads();

    for (int c0 = 0; c0 < NN; c0 += 32) {
        int oc0 = o0 + c0;
        bool dir = oc0 < 128;
        if (tid < 128) {
            uint32_t r[32];
            LDTM32(r, tmem + c0);
            TC_WAIT_LD();
            if (dir) {  // q/k region (y==0, c0<128)
                int n = n0 + wid * 32 + lane;
                int oo = (oc0 < 64) ? oc0 : (oc0 - 64);
                uint32_t* hi = (uint32_t*)((oc0 < 64) ? g_qT_hi : g_kT_hi) + ((size_t)b * N_TOK + n) * 32;
                uint32_t* lo = (uint32_t*)((oc0 < 64) ? g_qT_lo : g_kT_lo) + ((size_t)b * N_TOK + n) * 32;
#pragma unroll
                for (int j = 0; j < 32; j += 4) {
                    uint32_t h0, l0, h1, l1;
                    pack_split2(__uint_as_float(r[j + 0]) + s_bias[c0 + j + 0],
                                __uint_as_float(r[j + 1]) + s_bias[c0 + j + 1], h0, l0);
                    pack_split2(__uint_as_float(r[j + 2]) + s_bias[c0 + j + 2],
                                __uint_as_float(r[j + 3]) + s_bias[c0 + j + 3], h1, l1);
                    *(uint2*)(hi + ((oo + j) >> 1)) = make_uint2(h0, h1);
                    *(uint2*)(lo + ((oo + j) >> 1)) = make_uint2(l0, l1);
                }
            } else {    // v region: stage for transpose
                int cb = wid * 1056 + lane * 33;
#pragma unroll
                for (int j = 0; j < 32; j++) tb[cb + j] = __uint_as_float(r[j]);
            }
        }
        if (!dir) {
            __syncthreads();
            int cg = oc0 - 128;
#pragma unroll
            for (int i = 0; i < 16; i++) {
                int rid = wid * 16 + i;
                int wsrc = rid >> 5, j = rid & 31;
                float val = tb[wsrc * 1056 + lane * 33 + j] + s_bias[c0 + j];
                __nv_bfloat16 h, l;
                split1(val, h, l);
                size_t off = ((size_t)b * C_IN + cg + j) * N_TOK + n0 + wsrc * 32 + lane;
                g_v_hi[off] = h;
                g_v_lo[off] = l;
            }
            __syncthreads();
        }
    }
    __syncthreads();
    if (wid == 0) TC_DEALLOC(tmem, 512);
#else
    int tid = threadIdx.x;
    int b = blockIdx.z, n0 = blockIdx.x * 128, y = blockIdx.y, o0 = y * 512;
    int NN = (y == 0) ? 512 : 128;
    for (int e = tid; e < 128 * NN; e += 256) {
        int n = n0 + (e & 127);
        int oc = o0 + (e >> 7);
        const __nv_bfloat16* xh = g_xT_hi + ((size_t)b * N_TOK + n) * C_IN;
        const __nv_bfloat16* xl = g_xT_lo + ((size_t)b * N_TOK + n) * C_IN;
        const __nv_bfloat16* wh = g_Wn_hi + (size_t)oc * C_IN;
        const __nv_bfloat16* wl = g_Wn_lo + (size_t)oc * C_IN;
        float s = 0.f;
        for (int c = 0; c < C_IN; c++) {
            float xa = __bfloat162float(xh[c]) + __bfloat162float(xl[c]);
            float wa = __bfloat162float(wh[c]) + __bfloat162float(wl[c]);
            s += xa * wa;
        }
        s += g_bias[oc];
        __nv_bfloat16 h, l;
        split1(s, h, l);
        if (oc < 64)       { size_t o = ((size_t)b * N_TOK + n) * CQ + oc;        g_qT_hi[o] = h; g_qT_lo[o] = l; }
        else if (oc < 128) { size_t o = ((size_t)b * N_TOK + n) * CQ + (oc - 64); g_kT_hi[o] = h; g_kT_lo[o] = l; }
        else               { size_t o = ((size_t)b * C_IN + (oc - 128)) * N_TOK + n; g_v_hi[o] = h; g_v_lo[o] = l; }
    }
#endif
}

// ---------------- qk: D[n=128][m=256] -> S[m][n] fp32 (SW128, K=64) ---------
// grid (8, 4, BATCH)
__global__ void __launch_bounds__(256) qk_mma() {
#if USE_TCGEN05
    extern __shared__ char dyn[];
    __shared__ uint32_t s_tmem;
    __shared__ uint64_t s_mb;

    int tid = threadIdx.x, wid = tid >> 5, lane = tid & 31;
    int b = blockIdx.z, n0 = blockIdx.x * 128, m0 = blockIdx.y * 256;
    uint32_t idesc = IDESC(256);

    uint32_t dynb = (cvta_smem(dyn) + 1023u) & ~1023u;
    uint32_t AHI = dynb, ALO = dynb + 16384u, BHI = dynb + 32768u, BLO = dynb + 65536u;
    uint32_t mb = cvta_smem(&s_mb);

    if (wid == 0) { TC_ALLOC(cvta_smem(&s_tmem), 256); TC_RELINQ(); }
    if (tid == 0) MB_INIT(mb, 1);
    __syncthreads();
    uint32_t tmem = s_tmem;

    copy_rows(g_qT_hi + ((size_t)b * N_TOK + n0) * CQ, CQ, 0, AHI, 128, tid);
    copy_rows(g_qT_lo + ((size_t)b * N_TOK + n0) * CQ, CQ, 0, ALO, 128, tid);
    copy_rows(g_kT_hi + ((size_t)b * N_TOK + m0) * CQ, CQ, 0, BHI, 256, tid);
    copy_rows(g_kT_lo + ((size_t)b * N_TOK + m0) * CQ, CQ, 0, BLO, 256, tid);
    CP_COMMIT();
    CP_WAIT0();
    __syncthreads();
    if (wid == 0 && elect_one()) {
        FENCE_ASYNC();
        issue_chunk(tmem, AHI, ALO, BHI, BLO, idesc, true);
        TC_COMMIT(mb);
    }
    MB_WAIT(mb, 0);
    TC_FENCE_AFTER();

    float* Sb = g_S + (size_t)b * N_TOK * N_TOK;
    for (int c0 = 0; c0 < 256; c0 += 32) {
        if (tid < 128) {
            uint32_t r[32];
            LDTM32(r, tmem + c0);
            TC_WAIT_LD();
            int n = n0 + wid * 32 + lane;
#pragma unroll
            for (int j = 0; j < 32; j++)
                Sb[(size_t)(m0 + c0 + j) * N_TOK + n] = __uint_as_float(r[j]);
        }
    }
    __syncthreads();
    if (wid == 0) TC_DEALLOC(tmem, 256);
#else
    int tid = threadIdx.x;
    int b = blockIdx.z, n0 = blockIdx.x * 128, m0 = blockIdx.y * 256;
    float* Sb = g_S + (size_t)b * N_TOK * N_TOK;
    for (int e = tid; e < 128 * 256; e += 256) {
        int n = n0 + (e & 127);
        int m = m0 + (e >> 7);
        const __nv_bfloat16* qh = g_qT_hi + ((size_t)b * N_TOK + n) * CQ;
        const __nv_bfloat16* ql = g_qT_lo + ((size_t)b * N_TOK + n) * CQ;
        const __nv_bfloat16* kh = g_kT_hi + ((size_t)b * N_TOK + m) * CQ;
        const __nv_bfloat16* kl = g_kT_lo + ((size_t)b * N_TOK + m) * CQ;
        float s = 0.f;
        for (int o = 0; o < CQ; o++)
            s += (__bfloat162float(qh[o]) + __bfloat162float(ql[o])) *
                 (__bfloat162float(kh[o]) + __bfloat162float(kl[o]));
        Sb[(size_t)m * N_TOK + n] = s;
    }
#endif
}

// ---------------- row softmax -> P hi/lo ------------------------------------
__global__ void __launch_bounds__(256) softmax_kernel() {
    int b = blockIdx.y, m = blockIdx.x;
    const float* row = g_S + ((size_t)b * N_TOK + m) * N_TOK;
    int tid = threadIdx.x;
    __shared__ float smr[8];

    float4 v = ((const float4*)row)[tid];
    float mx = fmaxf(fmaxf(v.x, v.y), fmaxf(v.z, v.w));
#pragma unroll
    for (int s = 16; s; s >>= 1) mx = fmaxf(mx, __shfl_xor_sync(0xffffffffu, mx, s));
    if ((tid & 31) == 0) smr[tid >> 5] = mx;
    __syncthreads();
    mx = smr[0];
#pragma unroll
    for (int w = 1; w < 8; w++) mx = fmaxf(mx, smr[w]);
    __syncthreads();

    v.x = __expf(v.x - mx); v.y = __expf(v.y - mx);
    v.z = __expf(v.z - mx); v.w = __expf(v.w - mx);
    float s4 = v.x + v.y + v.z + v.w;
#pragma unroll
    for (int s = 16; s; s >>= 1) s4 += __shfl_xor_sync(0xffffffffu, s4, s);
    if ((tid & 31) == 0) smr[tid >> 5] = s4;
    __syncthreads();
    float tot = 0.f;
#pragma unroll
    for (int w = 0; w < 8; w++) tot += smr[w];
    float inv = 1.f / tot;
    v.x *= inv; v.y *= inv; v.z *= inv; v.w *= inv;

    uint32_t h0, l0, h1, l1;
    pack_split2(v.x, v.y, h0, l0);
    pack_split2(v.z, v.w, h1, l1);
    size_t ro = ((size_t)b * N_TOK + m) * 512;
    ((uint2*)((uint32_t*)g_P_hi + ro))[tid] = make_uint2(h0, h1);
    ((uint2*)((uint32_t*)g_P_lo + ro))[tid] = make_uint2(l0, l1);
}

// ---------------- av: D[m=128][c=512], out = gamma*D + x (SW64, K=32) -------
// grid (8, 1, BATCH): m0 = x*128
__global__ void __launch_bounds__(256) av_mma(const float* __restrict__ x,
                                              const float* __restrict__ gamma_p,
                                              float* __restrict__ out) {
#if USE_TCGEN05
    extern __shared__ char dyn[];
    __shared__ uint32_t s_tmem;
    __shared__ uint64_t s_mb[2];

    int tid = threadIdx.x, wid = tid >> 5, lane = tid & 31;
    int b = blockIdx.z, m0 = blockIdx.x * 128;
    uint32_t idesc = IDESC(256);

    uint32_t dynb = (cvta_smem(dyn) + 1023u) & ~1023u;
    uint32_t AHI[2], ALO[2], BHI[2], BLO[2];
#pragma unroll
    for (int p = 0; p < 2; p++) {
        uint32_t base = dynb + (uint32_t)p * 81920u;
        AHI[p] = base; ALO[p] = base + 8192u; BHI[p] = base + 16384u; BLO[p] = base + 49152u;
    }
    uint32_t mb0 = cvta_smem(&s_mb[0]), mb1 = cvta_smem(&s_mb[1]);

    if (wid == 0) { TC_ALLOC(cvta_smem(&s_tmem), 512); TC_RELINQ(); }
    if (tid == 0) { MB_INIT(mb0, 1); MB_INIT(mb1, 1); }
    __syncthreads();
    uint32_t tmem = s_tmem;

    const __nv_bfloat16* Ah = g_P_hi + ((size_t)b * N_TOK + m0) * N_TOK;
    const __nv_bfloat16* Al = g_P_lo + ((size_t)b * N_TOK + m0) * N_TOK;
    const __nv_bfloat16* Bh = g_v_hi + (size_t)b * C_IN * N_TOK;
    const __nv_bfloat16* Bl = g_v_lo + (size_t)b * C_IN * N_TOK;

    int ph0 = 0, ph1 = 0;
    const int KT = N_TOK / 32;
    for (int kt = 0; kt < KT; kt++) {
        int p = kt & 1;
        if (kt >= 2) {
            if (p == 0) { MB_WAIT(mb0, ph0); ph0 ^= 1; }
            else        { MB_WAIT(mb1, ph1); ph1 ^= 1; }
        }
        int k0 = kt * 32;
        copy_rows64(Ah, N_TOK, k0, AHI[p], 128, tid);
        copy_rows64(Al, N_TOK, k0, ALO[p], 128, tid);
        copy_rows64(Bh, N_TOK, k0, BHI[p], 512, tid);
        copy_rows64(Bl, N_TOK, k0, BLO[p], 512, tid);
        CP_COMMIT();
        CP_WAIT0();
        __syncthreads();
        if (wid == 0 && elect_one()) {
            FENCE_ASYNC();
            issue_chunk64(tmem, AHI[p], ALO[p], BHI[p], BLO[p], 2, idesc, kt == 0);
            TC_COMMIT(p == 0 ? mb0 : mb1);
        }
    }
    MB_WAIT(mb0, ph0);
    MB_WAIT(mb1, ph1);
    TC_FENCE_AFTER();

    float g = *gamma_p;
    for (int c0 = 0; c0 < 512; c0 += 32) {
        if (tid < 128) {
            uint32_t r[32];
            LDTM32(r, tmem + c0);
            TC_WAIT_LD();
            int m = m0 + wid * 32 + lane;
#pragma unroll
            for (int j = 0; j < 32; j++) {
                int c = c0 + j;
                size_t off = ((size_t)b * C_IN + c) * N_TOK + m;
                out[off] = g * __uint_as_float(r[j]) + x[off];
            }
        }
    }
    __syncthreads();
    if (wid == 0) TC_DEALLOC(tmem, 512);
#else
    int tid = threadIdx.x;
    int b = blockIdx.z, m0 = blockIdx.x * 128;
    float g = *gamma_p;
    for (int e = tid; e < 128 * 512; e += 256) {
        int m = m0 + (e & 127);
        int c = e >> 7;
        const __nv_bfloat16* vh = g_v_hi + ((size_t)b * C_IN + c) * N_TOK;
        const __nv_bfloat16* vl = g_v_lo + ((size_t)b * C_IN + c) * N_TOK;
        const __nv_bfloat16* ph = g_P_hi + ((size_t)b * N_TOK + m) * N_TOK;
        const __nv_bfloat16* pl = g_P_lo + ((size_t)b * N_TOK + m) * N_TOK;
        float s = 0.f;
        for (int n = 0; n < N_TOK; n++)
            s += (__bfloat162float(vh[n]) + __bfloat162float(vl[n])) *
                 (__bfloat162float(ph[n]) + __bfloat162float(pl[n]));
        size_t off = ((size_t)b * C_IN + c) * N_TOK + m;
        out[off] = g * s + x[off];
    }
#endif
}

// ---------------- launch -----------------------------------------------------
extern "C" void kernel_launch(void* const* d_in, const int* in_sizes, int n_in,
                              void* d_out, int out_size) {
    const float* x     = (const float*)d_in[0];
    const float* Wq    = (const float*)d_in[1];
    const float* bq    = (const float*)d_in[2];
    const float* uq    = (const float*)d_in[3];
    const float* Wk    = (const float*)d_in[4];
    const float* bk    = (const float*)d_in[5];
    const float* uk    = (const float*)d_in[6];
    const float* Wv    = (const float*)d_in[7];
    const float* bv    = (const float*)d_in[8];
    const float* uv    = (const float*)d_in[9];
    const float* gamma = (const float*)d_in[10];
    float* out = (float*)d_out;

    cudaFuncSetAttribute(proj_mma, cudaFuncAttributeMaxDynamicSharedMemorySize, 164864);
    cudaFuncSetAttribute(qk_mma,   cudaFuncAttributeMaxDynamicSharedMemorySize, 99328);
    cudaFuncSetAttribute(av_mma,   cudaFuncAttributeMaxDynamicSharedMemorySize, 164864);

    sn_kernel<<<3, 512>>>(Wq, uq, bq, Wk, uk, bk, Wv, uv, bv);
    transpose_kernel<<<dim3(32, 16, BATCH), dim3(32, 8)>>>(x);
    proj_mma<<<dim3(8, 2, BATCH), 256, 164864>>>();
    qk_mma<<<dim3(8, 4, BATCH), 256, 99328>>>();
    softmax_kernel<<<dim3(N_TOK, BATCH), 256>>>();
    av_mma<<<dim3(8, 1, BATCH), 256, 164864>>>(x, gamma, out);
}

// round 10
// speedup vs baseline: 1.4299x; 1.0088x over previous
#include <cuda_runtime.h>
#include <cuda_bf16.h>
#include <math.h>
#include <stdint.h>

#define N_TOK 1024
#define C_IN  512
#define CQ    64
#define BATCH 32

#if defined(__CUDA_ARCH__)
#if defined(__CUDA_ARCH_FEAT_SM103_ALL)
#define USE_TCGEN05 1
#else
#define USE_TCGEN05 0
#endif
#else
#define USE_TCGEN05 0
#endif

// ---------------- scratch (device globals; no allocation allowed) ----------
__device__ __align__(128) __nv_bfloat16 g_Wn_hi[640 * C_IN];   // rows: q 0-63, k 64-127, v 128-639 (K-major)
__device__ __align__(128) __nv_bfloat16 g_Wn_lo[640 * C_IN];
__device__ __align__(128) float g_bias[640];
__device__ __align__(128) __nv_bfloat16 g_xT_hi[(size_t)BATCH * N_TOK * C_IN];  // [b][n][c]
__device__ __align__(128) __nv_bfloat16 g_xT_lo[(size_t)BATCH * N_TOK * C_IN];
__device__ __align__(128) __nv_bfloat16 g_qT_hi[(size_t)BATCH * N_TOK * CQ];    // [b][n][o]
__device__ __align__(128) __nv_bfloat16 g_qT_lo[(size_t)BATCH * N_TOK * CQ];
__device__ __align__(128) __nv_bfloat16 g_kT_hi[(size_t)BATCH * N_TOK * CQ];    // [b][m][o]
__device__ __align__(128) __nv_bfloat16 g_kT_lo[(size_t)BATCH * N_TOK * CQ];
__device__ __align__(128) __nv_bfloat16 g_v_hi [(size_t)BATCH * C_IN * N_TOK];  // [b][c][n]
__device__ __align__(128) __nv_bfloat16 g_v_lo [(size_t)BATCH * C_IN * N_TOK];
__device__ __align__(128) float         g_S    [(size_t)BATCH * N_TOK * N_TOK]; // [b][m][n]
__device__ __align__(128) __nv_bfloat16 g_P_hi [(size_t)BATCH * N_TOK * N_TOK]; // [b][m][n]
__device__ __align__(128) __nv_bfloat16 g_P_lo [(size_t)BATCH * N_TOK * N_TOK];

// ---------------- common helpers --------------------------------------------
__device__ __forceinline__ uint32_t cvta_smem(const void* p) {
    uint32_t a;
    asm("{ .reg .u64 t; cvta.to.shared.u64 t, %1; cvt.u32.u64 %0, t; }" : "=r"(a) : "l"(p));
    return a;
}
__device__ __forceinline__ void pack_split2(float a, float b, uint32_t& h, uint32_t& l) {
    __nv_bfloat16 ah = __float2bfloat16(a);
    __nv_bfloat16 bh = __float2bfloat16(b);
    __nv_bfloat16 al = __float2bfloat16(a - __bfloat162float(ah));
    __nv_bfloat16 bl = __float2bfloat16(b - __bfloat162float(bh));
    h = (uint32_t)__bfloat16_as_ushort(ah) | ((uint32_t)__bfloat16_as_ushort(bh) << 16);
    l = (uint32_t)__bfloat16_as_ushort(al) | ((uint32_t)__bfloat16_as_ushort(bl) << 16);
}
__device__ __forceinline__ void split1(float v, __nv_bfloat16& h, __nv_bfloat16& l) {
    h = __float2bfloat16(v);
    l = __float2bfloat16(v - __bfloat162float(h));
}

#if USE_TCGEN05
__device__ __forceinline__ int elect_one() {
    uint32_t pred;
    asm volatile("{\n\t.reg .pred p;\n\telect.sync _|p, 0xFFFFFFFF;\n\tselp.b32 %0, 1, 0, p;\n\t}" : "=r"(pred));
    return (int)pred;
}
#define MB_INIT(addr, cnt) \
    asm volatile("mbarrier.init.shared.b64 [%0], %1;" :: "r"(addr), "r"((uint32_t)(cnt)) : "memory")
#define MB_WAIT(addr, phv) do { \
    uint32_t _m = (addr), _p = (uint32_t)(phv), _d; \
    asm volatile("{\n\t.reg .pred p;\n\t" \
        "mbarrier.try_wait.parity.acquire.cta.shared::cta.b64 p, [%1], %2;\n\t" \
        "selp.b32 %0,1,0,p;\n\t}" : "=r"(_d) : "r"(_m), "r"(_p) : "memory"); \
    while (!_d) { \
        asm volatile("{\n\t.reg .pred p;\n\t" \
            "mbarrier.try_wait.parity.acquire.cta.shared::cta.b64 p, [%1], %2, 0x989680;\n\t" \
            "selp.b32 %0,1,0,p;\n\t}" : "=r"(_d) : "r"(_m), "r"(_p) : "memory"); \
    } \
} while (0)
#define TC_ALLOC(addr, n) \
    asm volatile("tcgen05.alloc.cta_group::1.sync.aligned.shared::cta.b32 [%0], %1;" :: "r"(addr), "r"((uint32_t)(n)) : "memory")
#define TC_RELINQ() \
    asm volatile("tcgen05.relinquish_alloc_permit.cta_group::1.sync.aligned;")
#define TC_DEALLOC(tm, n) \
    asm volatile("tcgen05.dealloc.cta_group::1.sync.aligned.b32 %0, %1;" :: "r"(tm), "r"((uint32_t)(n)))
#define TC_COMMIT(addr) \
    asm volatile("tcgen05.commit.cta_group::1.mbarrier::arrive::one.shared::cluster.b64 [%0];" :: "r"(addr) : "memory")
#define TC_FENCE_AFTER()  asm volatile("tcgen05.fence::after_thread_sync;" ::: "memory")
#define TC_WAIT_LD()      asm volatile("tcgen05.wait::ld.sync.aligned;" ::: "memory")
#define FENCE_ASYNC()     asm volatile("fence.proxy.async.shared::cta;" ::: "memory")
#define CP16(dst, src)  asm volatile("cp.async.cg.shared.global [%0], [%1], 16;" :: "r"(dst), "l"(src) : "memory")
#define CP_COMMIT()     asm volatile("cp.async.commit_group;" ::: "memory")
#define CP_WAIT0()      asm volatile("cp.async.wait_group 0;" ::: "memory")
#define CP_WAIT2()      asm volatile("cp.async.wait_group 2;" ::: "memory")

#define LDTM32(r, tma) \
    asm volatile("tcgen05.ld.sync.aligned.32x32b.x32.b32 " \
        "{%0,%1,%2,%3,%4,%5,%6,%7,%8,%9,%10,%11,%12,%13,%14,%15," \
        "%16,%17,%18,%19,%20,%21,%22,%23,%24,%25,%26,%27,%28,%29,%30,%31}, [%32];" \
        : "=r"((r)[0]),"=r"((r)[1]),"=r"((r)[2]),"=r"((r)[3]),"=r"((r)[4]),"=r"((r)[5]),"=r"((r)[6]),"=r"((r)[7]), \
          "=r"((r)[8]),"=r"((r)[9]),"=r"((r)[10]),"=r"((r)[11]),"=r"((r)[12]),"=r"((r)[13]),"=r"((r)[14]),"=r"((r)[15]), \
          "=r"((r)[16]),"=r"((r)[17]),"=r"((r)[18]),"=r"((r)[19]),"=r"((r)[20]),"=r"((r)[21]),"=r"((r)[22]),"=r"((r)[23]), \
          "=r"((r)[24]),"=r"((r)[25]),"=r"((r)[26]),"=r"((r)[27]),"=r"((r)[28]),"=r"((r)[29]),"=r"((r)[30]),"=r"((r)[31]) \
        : "r"(tma))

// SW128 desc (128B rows): layout 2, version 1, SBO=64, LBO=1
__device__ __forceinline__ uint64_t smem_desc(uint32_t addr) {
    return 0x4000404000010000ULL | (uint64_t)((addr >> 4) & 0x3FFF);
}
// SW64 desc (64B rows): layout 4, version 1, SBO=32, LBO=1
__device__ __forceinline__ uint64_t smem_desc64(uint32_t addr) {
    return 0x8000402000010000ULL | (uint64_t)((addr >> 4) & 0x3FFF);
}
__device__ __forceinline__ void mma_bf16_ss(uint32_t d, uint64_t ad, uint64_t bd,
                                            uint32_t idesc, uint32_t en) {
    asm volatile(
        "{\n\t.reg .pred p;\n\tsetp.ne.u32 p, %4, 0;\n\t"
        "tcgen05.mma.cta_group::1.kind::f16 [%0], %1, %2, %3, {%5,%5,%5,%5}, p;\n\t}"
        :: "r"(d), "l"(ad), "l"(bd), "r"(idesc), "r"(en), "r"(0u) : "memory");
}
#define IDESC(NN) (0x8000490u | ((uint32_t)((NN) / 8) << 17))

// ---- SW128 (128B rows, K-chunk 64) copy ----
__device__ __forceinline__ void copy_rows(const __nv_bfloat16* __restrict__ src,
                                          int stride, int k0, uint32_t dst,
                                          int rows, int tid) {
    for (int s = tid; s < rows * 8; s += 256) {
        int r = s >> 3, seg = s & 7;
        const char* sp = (const char*)(src + (size_t)r * stride + k0) + seg * 16;
        uint32_t off = (uint32_t)(r * 128 + seg * 16);
        uint32_t sw = off ^ ((off >> 3) & 0x70u);
        CP16(dst + sw, sp);
    }
}
// ---- SW64 (64B rows, K-chunk 32) copy ----
__device__ __forceinline__ void copy_rows64(const __nv_bfloat16* __restrict__ src,
                                            int stride, int k0, uint32_t dst,
                                            int rows, int tid) {
    for (int s = tid; s < rows * 4; s += 256) {
        int r = s >> 2, seg = s & 3;
        const char* sp = (const char*)(src + (size_t)r * stride + k0) + seg * 16;
        uint32_t off = (uint32_t)(r * 64 + seg * 16);
        uint32_t sw = off ^ ((off >> 3) & 0x30u);
        CP16(dst + sw, sp);
    }
}

// SW128 chunk (K=64): 3 products x 4 K-steps
__device__ __forceinline__ void issue_chunk(uint32_t d, uint32_t ahi, uint32_t alo,
                                            uint32_t bhi, uint32_t blo,
                                            uint32_t idesc, bool first) {
    uint64_t AH = smem_desc(ahi), AL = smem_desc(alo);
    uint64_t BH = smem_desc(bhi), BL = smem_desc(blo);
#pragma unroll
    for (int ks = 0; ks < 4; ks++) mma_bf16_ss(d, AH + 2 * ks, BH + 2 * ks, idesc, (first && ks == 0) ? 0u : 1u);
#pragma unroll
    for (int ks = 0; ks < 4; ks++) mma_bf16_ss(d, AH + 2 * ks, BL + 2 * ks, idesc, 1u);
#pragma unroll
    for (int ks = 0; ks < 4; ks++) mma_bf16_ss(d, AL + 2 * ks, BH + 2 * ks, idesc, 1u);
}

// SW64 chunk (K=32): 3 products x 2 K-steps, single N<=256 tile
__device__ __forceinline__ void issue_chunk32(uint32_t d, uint32_t ahi, uint32_t alo,
                                              uint32_t bhi, uint32_t blo,
                                              uint32_t idesc, bool first) {
    uint64_t AH = smem_desc64(ahi), AL = smem_desc64(alo);
    uint64_t BH = smem_desc64(bhi), BL = smem_desc64(blo);
#pragma unroll
    for (int ks = 0; ks < 2; ks++) mma_bf16_ss(d, AH + 2 * ks, BH + 2 * ks, idesc, (first && ks == 0) ? 0u : 1u);
#pragma unroll
    for (int ks = 0; ks < 2; ks++) mma_bf16_ss(d, AH + 2 * ks, BL + 2 * ks, idesc, 1u);
#pragma unroll
    for (int ks = 0; ks < 2; ks++) mma_bf16_ss(d, AL + 2 * ks, BH + 2 * ks, idesc, 1u);
}
#endif  // USE_TCGEN05

// ---------------- spectral norm ---------------------------------------------
__global__ void sn_kernel(const float* __restrict__ Wq, const float* __restrict__ uq, const float* __restrict__ bq,
                          const float* __restrict__ Wk, const float* __restrict__ uk, const float* __restrict__ bk,
                          const float* __restrict__ Wv, const float* __restrict__ uv, const float* __restrict__ bv) {
    const float* W; const float* u; const float* bias; int out; int dst;
    if (blockIdx.x == 0)      { W = Wq; u = uq; bias = bq; out = CQ;   dst = 0;   }
    else if (blockIdx.x == 1) { W = Wk; u = uk; bias = bk; out = CQ;   dst = 64;  }
    else                      { W = Wv; u = uv; bias = bv; out = C_IN; dst = 128; }

    __shared__ float su[C_IN];
    __shared__ float sv[C_IN];
    __shared__ float red[512];
    int tid = threadIdx.x;

    if (tid < out) { su[tid] = u[tid]; g_bias[dst + tid] = bias[tid]; }
    __syncthreads();

    float t = 0.f;
    for (int i = 0; i < out; i++) t += W[i * C_IN + tid] * su[i];
    red[tid] = t * t;
    __syncthreads();
    for (int s = 256; s > 0; s >>= 1) { if (tid < s) red[tid] += red[tid + s]; __syncthreads(); }
    float nv = sqrtf(red[0]);
    sv[tid] = t / nv;
    __syncthreads();

    float p = 0.f;
    for (int i = tid; i < out; i += blockDim.x) {
        float r = 0.f;
        for (int j = 0; j < C_IN; j++) r += W[i * C_IN + j] * sv[j];
        p += r * r;
    }
    red[tid] = p;
    __syncthreads();
    for (int s = 256; s > 0; s >>= 1) { if (tid < s) red[tid] += red[tid + s]; __syncthreads(); }
    float inv_sigma = rsqrtf(red[0]);

    for (int e = tid; e < out * C_IN; e += blockDim.x) {
        float val = W[e] * inv_sigma;
        __nv_bfloat16 h, l;
        split1(val, h, l);
        g_Wn_hi[(size_t)dst * C_IN + e] = h;
        g_Wn_lo[(size_t)dst * C_IN + e] = l;
    }
}

// ---------------- x transpose + split ----------------------------------------
__global__ void transpose_kernel(const float* __restrict__ x) {
    __shared__ float t[32][33];
    int b = blockIdx.z, c0 = blockIdx.y * 32, n0 = blockIdx.x * 32;
    int tx = threadIdx.x, ty = threadIdx.y;
    const float* src = x + (size_t)b * C_IN * N_TOK;
    size_t dbase = (size_t)b * N_TOK * C_IN;
#pragma unroll
    for (int i = ty; i < 32; i += 8) t[i][tx] = src[(size_t)(c0 + i) * N_TOK + n0 + tx];
    __syncthreads();
#pragma unroll
    for (int i = ty; i < 32; i += 8) {
        float val = t[tx][i];
        __nv_bfloat16 h, l;
        split1(val, h, l);
        size_t off = dbase + (size_t)(n0 + i) * C_IN + c0 + tx;
        g_xT_hi[off] = h;
        g_xT_lo[off] = l;
    }
}

// ---------------- proj: D[n=128][o 256-tile], 4-stage pipeline ---------------
// grid (8, 3, BATCH): n0 = x*128, o0 = y*256, NN = (y<2)?256:128
// buffer (48KB): AHI 8K | ALO 8K | BHI 16K | BLO 16K ; 4 buffers = 192KB
__global__ void __launch_bounds__(256) proj_mma() {
#if USE_TCGEN05
    extern __shared__ char dyn[];
    __shared__ uint32_t s_tmem;
    __shared__ uint64_t s_mb[4];
    __shared__ float s_bias[256];
    __shared__ float tb[4 * 32 * 33];

    int tid = threadIdx.x, wid = tid >> 5, lane = tid & 31;
    int b = blockIdx.z, n0 = blockIdx.x * 128, y = blockIdx.y;
    int o0 = y * 256;
    int NN = (y < 2) ? 256 : 128;
    uint32_t idesc = IDESC(NN);

    uint32_t dynb = (cvta_smem(dyn) + 1023u) & ~1023u;
    uint32_t mba[4];
#pragma unroll
    for (int i = 0; i < 4; i++) mba[i] = cvta_smem(&s_mb[i]);

    if (wid == 0) { TC_ALLOC(cvta_smem(&s_tmem), 256); TC_RELINQ(); }
    if (tid == 0) { MB_INIT(mba[0], 1); MB_INIT(mba[1], 1); MB_INIT(mba[2], 1); MB_INIT(mba[3], 1); }
    for (int i = tid; i < NN; i += 256) s_bias[i] = g_bias[o0 + i];
    __syncthreads();
    uint32_t tmem = s_tmem;

    const __nv_bfloat16* Ah = g_xT_hi + ((size_t)b * N_TOK + n0) * C_IN;
    const __nv_bfloat16* Al = g_xT_lo + ((size_t)b * N_TOK + n0) * C_IN;
    const __nv_bfloat16* Bh = g_Wn_hi + (size_t)o0 * C_IN;
    const __nv_bfloat16* Bl = g_Wn_lo + (size_t)o0 * C_IN;

    auto copyset = [&](int ck) {
        uint32_t base = dynb + (uint32_t)(ck & 3) * 49152u;
        int k0 = ck * 32;
        copy_rows64(Ah, C_IN, k0, base, 128, tid);
        copy_rows64(Al, C_IN, k0, base + 8192u, 128, tid);
        copy_rows64(Bh, C_IN, k0, base + 16384u, NN, tid);
        copy_rows64(Bl, C_IN, k0, base + 32768u, NN, tid);
        CP_COMMIT();
    };

    const int KT = C_IN / 32;   // 16
    copyset(0);
    copyset(1);
    for (int kt = 0; kt < KT; kt++) {
        if (kt >= 2) MB_WAIT(mba[(kt - 2) & 3], ((kt - 2) >> 2) & 1);
        if (kt + 2 < KT) copyset(kt + 2); else CP_COMMIT();
        CP_WAIT2();
        __syncthreads();
        if (wid == 0 && elect_one()) {
            uint32_t base = dynb + (uint32_t)(kt & 3) * 49152u;
            FENCE_ASYNC();
            issue_chunk32(tmem, base, base + 8192u, base + 16384u, base + 32768u, idesc, kt == 0);
            TC_COMMIT(mba[kt & 3]);
        }
    }
    MB_WAIT(mba[(KT - 2) & 3], ((KT - 2) >> 2) & 1);
    MB_WAIT(mba[(KT - 1) & 3], ((KT - 1) >> 2) & 1);
    TC_FENCE_AFTER();
    __syncthreads();

    for (int c0 = 0; c0 < NN; c0 += 32) {
        int oc0 = o0 + c0;
        bool dir = oc0 < 128;
        if (tid < 128) {
            uint32_t r[32];
            LDTM32(r, tmem + c0);
            TC_WAIT_LD();
            if (dir) {  // q/k region (y==0, c0<128)
                int n = n0 + wid * 32 + lane;
                int oo = (oc0 < 64) ? oc0 : (oc0 - 64);
                uint32_t* hi = (uint32_t*)((oc0 < 64) ? g_qT_hi : g_kT_hi) + ((size_t)b * N_TOK + n) * 32;
                uint32_t* lo = (uint32_t*)((oc0 < 64) ? g_qT_lo : g_kT_lo) + ((size_t)b * N_TOK + n) * 32;
#pragma unroll
                for (int j = 0; j < 32; j += 4) {
                    uint32_t h0, l0, h1, l1;
                    pack_split2(__uint_as_float(r[j + 0]) + s_bias[c0 + j + 0],
                                __uint_as_float(r[j + 1]) + s_bias[c0 + j + 1], h0, l0);
                    pack_split2(__uint_as_float(r[j + 2]) + s_bias[c0 + j + 2],
                                __uint_as_float(r[j + 3]) + s_bias[c0 + j + 3], h1, l1);
                    *(uint2*)(hi + ((oo + j) >> 1)) = make_uint2(h0, h1);
                    *(uint2*)(lo + ((oo + j) >> 1)) = make_uint2(l0, l1);
                }
            } else {    // v region: stage for transpose
                int cb = wid * 1056 + lane * 33;
#pragma unroll
                for (int j = 0; j < 32; j++) tb[cb + j] = __uint_as_float(r[j]);
            }
        }
        if (!dir) {
            __syncthreads();
            int cg = oc0 - 128;
#pragma unroll
            for (int i = 0; i < 16; i++) {
                int rid = wid * 16 + i;
                int wsrc = rid >> 5, j = rid & 31;
                float val = tb[wsrc * 1056 + lane * 33 + j] + s_bias[c0 + j];
                __nv_bfloat16 h, l;
                split1(val, h, l);
                size_t off = ((size_t)b * C_IN + cg + j) * N_TOK + n0 + wsrc * 32 + lane;
                g_v_hi[off] = h;
                g_v_lo[off] = l;
            }
            __syncthreads();
        }
    }
    __syncthreads();
    if (wid == 0) TC_DEALLOC(tmem, 256);
#else
    int tid = threadIdx.x;
    int b = blockIdx.z, n0 = blockIdx.x * 128, y = blockIdx.y, o0 = y * 256;
    int NN = (y < 2) ? 256 : 128;
    for (int e = tid; e < 128 * NN; e += 256) {
        int n = n0 + (e & 127);
        int oc = o0 + (e >> 7);
        const __nv_bfloat16* xh = g_xT_hi + ((size_t)b * N_TOK + n) * C_IN;
        const __nv_bfloat16* xl = g_xT_lo + ((size_t)b * N_TOK + n) * C_IN;
        const __nv_bfloat16* wh = g_Wn_hi + (size_t)oc * C_IN;
        const __nv_bfloat16* wl = g_Wn_lo + (size_t)oc * C_IN;
        float s = 0.f;
        for (int c = 0; c < C_IN; c++) {
            float xa = __bfloat162float(xh[c]) + __bfloat162float(xl[c]);
            float wa = __bfloat162float(wh[c]) + __bfloat162float(wl[c]);
            s += xa * wa;
        }
        s += g_bias[oc];
        __nv_bfloat16 h, l;
        split1(s, h, l);
        if (oc < 64)       { size_t o = ((size_t)b * N_TOK + n) * CQ + oc;        g_qT_hi[o] = h; g_qT_lo[o] = l; }
        else if (oc < 128) { size_t o = ((size_t)b * N_TOK + n) * CQ + (oc - 64); g_kT_hi[o] = h; g_kT_lo[o] = l; }
        else               { size_t o = ((size_t)b * C_IN + (oc - 128)) * N_TOK + n; g_v_hi[o] = h; g_v_lo[o] = l; }
    }
#endif
}

// ---------------- qk: D[n=128][m=256] -> S[m][n] fp32 (SW128, K=64) ---------
// grid (8, 4, BATCH)
__global__ void __launch_bounds__(256) qk_mma() {
#if USE_TCGEN05
    extern __shared__ char dyn[];
    __shared__ uint32_t s_tmem;
    __shared__ uint64_t s_mb;

    int tid = threadIdx.x, wid = tid >> 5, lane = tid & 31;
    int b = blockIdx.z, n0 = blockIdx.x * 128, m0 = blockIdx.y * 256;
    uint32_t idesc = IDESC(256);

    uint32_t dynb = (cvta_smem(dyn) + 1023u) & ~1023u;
    uint32_t AHI = dynb, ALO = dynb + 16384u, BHI = dynb + 32768u, BLO = dynb + 65536u;
    uint32_t mb = cvta_smem(&s_mb);

    if (wid == 0) { TC_ALLOC(cvta_smem(&s_tmem), 256); TC_RELINQ(); }
    if (tid == 0) MB_INIT(mb, 1);
    __syncthreads();
    uint32_t tmem = s_tmem;

    copy_rows(g_qT_hi + ((size_t)b * N_TOK + n0) * CQ, CQ, 0, AHI, 128, tid);
    copy_rows(g_qT_lo + ((size_t)b * N_TOK + n0) * CQ, CQ, 0, ALO, 128, tid);
    copy_rows(g_kT_hi + ((size_t)b * N_TOK + m0) * CQ, CQ, 0, BHI, 256, tid);
    copy_rows(g_kT_lo + ((size_t)b * N_TOK + m0) * CQ, CQ, 0, BLO, 256, tid);
    CP_COMMIT();
    CP_WAIT0();
    __syncthreads();
    if (wid == 0 && elect_one()) {
        FENCE_ASYNC();
        issue_chunk(tmem, AHI, ALO, BHI, BLO, idesc, true);
        TC_COMMIT(mb);
    }
    MB_WAIT(mb, 0);
    TC_FENCE_AFTER();

    float* Sb = g_S + (size_t)b * N_TOK * N_TOK;
    for (int c0 = 0; c0 < 256; c0 += 32) {
        if (tid < 128) {
            uint32_t r[32];
            LDTM32(r, tmem + c0);
            TC_WAIT_LD();
            int n = n0 + wid * 32 + lane;
#pragma unroll
            for (int j = 0; j < 32; j++)
                Sb[(size_t)(m0 + c0 + j) * N_TOK + n] = __uint_as_float(r[j]);
        }
    }
    __syncthreads();
    if (wid == 0) TC_DEALLOC(tmem, 256);
#else
    int tid = threadIdx.x;
    int b = blockIdx.z, n0 = blockIdx.x * 128, m0 = blockIdx.y * 256;
    float* Sb = g_S + (size_t)b * N_TOK * N_TOK;
    for (int e = tid; e < 128 * 256; e += 256) {
        int n = n0 + (e & 127);
        int m = m0 + (e >> 7);
        const __nv_bfloat16* qh = g_qT_hi + ((size_t)b * N_TOK + n) * CQ;
        const __nv_bfloat16* ql = g_qT_lo + ((size_t)b * N_TOK + n) * CQ;
        const __nv_bfloat16* kh = g_kT_hi + ((size_t)b * N_TOK + m) * CQ;
        const __nv_bfloat16* kl = g_kT_lo + ((size_t)b * N_TOK + m) * CQ;
        float s = 0.f;
        for (int o = 0; o < CQ; o++)
            s += (__bfloat162float(qh[o]) + __bfloat162float(ql[o])) *
                 (__bfloat162float(kh[o]) + __bfloat162float(kl[o]));
        Sb[(size_t)m * N_TOK + n] = s;
    }
#endif
}

// ---------------- row softmax -> P hi/lo ------------------------------------
__global__ void __launch_bounds__(256) softmax_kernel() {
    int b = blockIdx.y, m = blockIdx.x;
    const float* row = g_S + ((size_t)b * N_TOK + m) * N_TOK;
    int tid = threadIdx.x;
    __shared__ float smr[8];

    float4 v = ((const float4*)row)[tid];
    float mx = fmaxf(fmaxf(v.x, v.y), fmaxf(v.z, v.w));
#pragma unroll
    for (int s = 16; s; s >>= 1) mx = fmaxf(mx, __shfl_xor_sync(0xffffffffu, mx, s));
    if ((tid & 31) == 0) smr[tid >> 5] = mx;
    __syncthreads();
    mx = smr[0];
#pragma unroll
    for (int w = 1; w < 8; w++) mx = fmaxf(mx, smr[w]);
    __syncthreads();

    v.x = __expf(v.x - mx); v.y = __expf(v.y - mx);
    v.z = __expf(v.z - mx); v.w = __expf(v.w - mx);
    float s4 = v.x + v.y + v.z + v.w;
#pragma unroll
    for (int s = 16; s; s >>= 1) s4 += __shfl_xor_sync(0xffffffffu, s4, s);
    if ((tid & 31) == 0) smr[tid >> 5] = s4;
    __syncthreads();
    float tot = 0.f;
#pragma unroll
    for (int w = 0; w < 8; w++) tot += smr[w];
    float inv = 1.f / tot;
    v.x *= inv; v.y *= inv; v.z *= inv; v.w *= inv;

    uint32_t h0, l0, h1, l1;
    pack_split2(v.x, v.y, h0, l0);
    pack_split2(v.z, v.w, h1, l1);
    size_t ro = ((size_t)b * N_TOK + m) * 512;
    ((uint2*)((uint32_t*)g_P_hi + ro))[tid] = make_uint2(h0, h1);
    ((uint2*)((uint32_t*)g_P_lo + ro))[tid] = make_uint2(l0, l1);
}

// ---------------- av: D[m=128][c=256], 4-stage pipeline ---------------------
// grid (8, 2, BATCH): m0 = x*128, c0g = y*256
__global__ void __launch_bounds__(256) av_mma(const float* __restrict__ x,
                                              const float* __restrict__ gamma_p,
                                              float* __restrict__ out) {
#if USE_TCGEN05
    extern __shared__ char dyn[];
    __shared__ uint32_t s_tmem;
    __shared__ uint64_t s_mb[4];

    int tid = threadIdx.x, wid = tid >> 5, lane = tid & 31;
    int b = blockIdx.z, m0 = blockIdx.x * 128, c0g = blockIdx.y * 256;
    uint32_t idesc = IDESC(256);

    uint32_t dynb = (cvta_smem(dyn) + 1023u) & ~1023u;
    uint32_t mba[4];
#pragma unroll
    for (int i = 0; i < 4; i++) mba[i] = cvta_smem(&s_mb[i]);

    if (wid == 0) { TC_ALLOC(cvta_smem(&s_tmem), 256); TC_RELINQ(); }
    if (tid == 0) { MB_INIT(mba[0], 1); MB_INIT(mba[1], 1); MB_INIT(mba[2], 1); MB_INIT(mba[3], 1); }
    __syncthreads();
    uint32_t tmem = s_tmem;

    const __nv_bfloat16* Ah = g_P_hi + ((size_t)b * N_TOK + m0) * N_TOK;
    const __nv_bfloat16* Al = g_P_lo + ((size_t)b * N_TOK + m0) * N_TOK;
    const __nv_bfloat16* Bh = g_v_hi + ((size_t)b * C_IN + c0g) * N_TOK;
    const __nv_bfloat16* Bl = g_v_lo + ((size_t)b * C_IN + c0g) * N_TOK;

    auto copyset = [&](int ck) {
        uint32_t base = dynb + (uint32_t)(ck & 3) * 49152u;
        int k0 = ck * 32;
        copy_rows64(Ah, N_TOK, k0, base, 128, tid);
        copy_rows64(Al, N_TOK, k0, base + 8192u, 128, tid);
        copy_rows64(Bh, N_TOK, k0, base + 16384u, 256, tid);
        copy_rows64(Bl, N_TOK, k0, base + 32768u, 256, tid);
        CP_COMMIT();
    };

    const int KT = N_TOK / 32;   // 32
    copyset(0);
    copyset(1);
    for (int kt = 0; kt < KT; kt++) {
        if (kt >= 2) MB_WAIT(mba[(kt - 2) & 3], ((kt - 2) >> 2) & 1);
        if (kt + 2 < KT) copyset(kt + 2); else CP_COMMIT();
        CP_WAIT2();
        __syncthreads();
        if (wid == 0 && elect_one()) {
            uint32_t base = dynb + (uint32_t)(kt & 3) * 49152u;
            FENCE_ASYNC();
            issue_chunk32(tmem, base, base + 8192u, base + 16384u, base + 32768u, idesc, kt == 0);
            TC_COMMIT(mba[kt & 3]);
        }
    }
    MB_WAIT(mba[(KT - 2) & 3], ((KT - 2) >> 2) & 1);
    MB_WAIT(mba[(KT - 1) & 3], ((KT - 1) >> 2) & 1);
    TC_FENCE_AFTER();

    float g = *gamma_p;
    for (int c0 = 0; c0 < 256; c0 += 32) {
        if (tid < 128) {
            uint32_t r[32];
            LDTM32(r, tmem + c0);
            TC_WAIT_LD();
            int m = m0 + wid * 32 + lane;
#pragma unroll
            for (int j = 0; j < 32; j++) {
                int c = c0g + c0 + j;
                size_t off = ((size_t)b * C_IN + c) * N_TOK + m;
                out[off] = g * __uint_as_float(r[j]) + x[off];
            }
        }
    }
    __syncthreads();
    if (wid == 0) TC_DEALLOC(tmem, 256);
#else
    int tid = threadIdx.x;
    int b = blockIdx.z, m0 = blockIdx.x * 128, c0g = blockIdx.y * 256;
    float g = *gamma_p;
    for (int e = tid; e < 128 * 256; e += 256) {
        int m = m0 + (e & 127);
        int c = c0g + (e >> 7);
        const __nv_bfloat16* vh = g_v_hi + ((size_t)b * C_IN + c) * N_TOK;
        const __nv_bfloat16* vl = g_v_lo + ((size_t)b * C_IN + c) * N_TOK;
        const __nv_bfloat16* ph = g_P_hi + ((size_t)b * N_TOK + m) * N_TOK;
        const __nv_bfloat16* pl = g_P_lo + ((size_t)b * N_TOK + m) * N_TOK;
        float s = 0.f;
        for (int n = 0; n < N_TOK; n++)
            s += (__bfloat162float(vh[n]) + __bfloat162float(vl[n])) *
                 (__bfloat162float(ph[n]) + __bfloat162float(pl[n]));
        size_t off = ((size_t)b * C_IN + c) * N_TOK + m;
        out[off] = g * s + x[off];
    }
#endif
}

// ---------------- launch -----------------------------------------------------
extern "C" void kernel_launch(void* const* d_in, const int* in_sizes, int n_in,
                              void* d_out, int out_size) {
    const float* x     = (const float*)d_in[0];
    const float* Wq    = (const float*)d_in[1];
    const float* bq    = (const float*)d_in[2];
    const float* uq    = (const float*)d_in[3];
    const float* Wk    = (const float*)d_in[4];
    const float* bk    = (const float*)d_in[5];
    const float* uk    = (const float*)d_in[6];
    const float* Wv    = (const float*)d_in[7];
    const float* bv    = (const float*)d_in[8];
    const float* uv    = (const float*)d_in[9];
    const float* gamma = (const float*)d_in[10];
    float* out = (float*)d_out;

    cudaFuncSetAttribute(proj_mma, cudaFuncAttributeMaxDynamicSharedMemorySize, 197632);
    cudaFuncSetAttribute(qk_mma,   cudaFuncAttributeMaxDynamicSharedMemorySize, 99328);
    cudaFuncSetAttribute(av_mma,   cudaFuncAttributeMaxDynamicSharedMemorySize, 197632);

    sn_kernel<<<3, 512>>>(Wq, uq, bq, Wk, uk, bk, Wv, uv, bv);
    transpose_kernel<<<dim3(32, 16, BATCH), dim3(32, 8)>>>(x);
    proj_mma<<<dim3(8, 3, BATCH), 256, 197632>>>();
    qk_mma<<<dim3(8, 4, BATCH), 256, 99328>>>();
    softmax_kernel<<<dim3(N_TOK, BATCH), 256>>>();
    av_mma<<<dim3(8, 2, BATCH), 256, 197632>>>(x, gamma, out);
}

// round 11
// speedup vs baseline: 1.4957x; 1.0460x over previous
#include <cuda_runtime.h>
#include <cuda_bf16.h>
#include <math.h>
#include <stdint.h>

#define N_TOK 1024
#define C_IN  512
#define CQ    64
#define BATCH 32

#if defined(__CUDA_ARCH__)
#if defined(__CUDA_ARCH_FEAT_SM103_ALL)
#define USE_TCGEN05 1
#else
#define USE_TCGEN05 0
#endif
#else
#define USE_TCGEN05 0
#endif

// ---------------- scratch (device globals; no allocation allowed) ----------
__device__ __align__(128) __nv_bfloat16 g_Wn_hi[640 * C_IN];   // rows: q 0-63, k 64-127, v 128-639 (K-major)
__device__ __align__(128) __nv_bfloat16 g_Wn_lo[640 * C_IN];
__device__ __align__(128) float g_bias[640];
__device__ __align__(128) __nv_bfloat16 g_xT_hi[(size_t)BATCH * N_TOK * C_IN];  // [b][n][c]
__device__ __align__(128) __nv_bfloat16 g_xT_lo[(size_t)BATCH * N_TOK * C_IN];
__device__ __align__(128) __nv_bfloat16 g_qT_hi[(size_t)BATCH * N_TOK * CQ];    // [b][n][o]
__device__ __align__(128) __nv_bfloat16 g_qT_lo[(size_t)BATCH * N_TOK * CQ];
__device__ __align__(128) __nv_bfloat16 g_kT_hi[(size_t)BATCH * N_TOK * CQ];    // [b][m][o]
__device__ __align__(128) __nv_bfloat16 g_kT_lo[(size_t)BATCH * N_TOK * CQ];
__device__ __align__(128) __nv_bfloat16 g_v_hi [(size_t)BATCH * C_IN * N_TOK];  // [b][c][n]
__device__ __align__(128) __nv_bfloat16 g_v_lo [(size_t)BATCH * C_IN * N_TOK];
__device__ __align__(128) __nv_bfloat16 g_P_hi [(size_t)BATCH * N_TOK * N_TOK]; // [b][m][n] unnormalized exp(S)
__device__ __align__(128) __nv_bfloat16 g_P_lo [(size_t)BATCH * N_TOK * N_TOK];
__device__ __align__(128) float         g_rsum [(size_t)BATCH * N_TOK];         // [b][m] row sums

// ---------------- common helpers --------------------------------------------
__device__ __forceinline__ uint32_t cvta_smem(const void* p) {
    uint32_t a;
    asm("{ .reg .u64 t; cvta.to.shared.u64 t, %1; cvt.u32.u64 %0, t; }" : "=r"(a) : "l"(p));
    return a;
}
__device__ __forceinline__ void pack_split2(float a, float b, uint32_t& h, uint32_t& l) {
    __nv_bfloat16 ah = __float2bfloat16(a);
    __nv_bfloat16 bh = __float2bfloat16(b);
    __nv_bfloat16 al = __float2bfloat16(a - __bfloat162float(ah));
    __nv_bfloat16 bl = __float2bfloat16(b - __bfloat162float(bh));
    h = (uint32_t)__bfloat16_as_ushort(ah) | ((uint32_t)__bfloat16_as_ushort(bh) << 16);
    l = (uint32_t)__bfloat16_as_ushort(al) | ((uint32_t)__bfloat16_as_ushort(bl) << 16);
}
__device__ __forceinline__ void split1(float v, __nv_bfloat16& h, __nv_bfloat16& l) {
    h = __float2bfloat16(v);
    l = __float2bfloat16(v - __bfloat162float(h));
}

#if USE_TCGEN05
__device__ __forceinline__ int elect_one() {
    uint32_t pred;
    asm volatile("{\n\t.reg .pred p;\n\telect.sync _|p, 0xFFFFFFFF;\n\tselp.b32 %0, 1, 0, p;\n\t}" : "=r"(pred));
    return (int)pred;
}
#define MB_INIT(addr, cnt) \
    asm volatile("mbarrier.init.shared.b64 [%0], %1;" :: "r"(addr), "r"((uint32_t)(cnt)) : "memory")
#define MB_WAIT(addr, phv) do { \
    uint32_t _m = (addr), _p = (uint32_t)(phv), _d; \
    asm volatile("{\n\t.reg .pred p;\n\t" \
        "mbarrier.try_wait.parity.acquire.cta.shared::cta.b64 p, [%1], %2;\n\t" \
        "selp.b32 %0,1,0,p;\n\t}" : "=r"(_d) : "r"(_m), "r"(_p) : "memory"); \
    while (!_d) { \
        asm volatile("{\n\t.reg .pred p;\n\t" \
            "mbarrier.try_wait.parity.acquire.cta.shared::cta.b64 p, [%1], %2, 0x989680;\n\t" \
            "selp.b32 %0,1,0,p;\n\t}" : "=r"(_d) : "r"(_m), "r"(_p) : "memory"); \
    } \
} while (0)
#define TC_ALLOC(addr, n) \
    asm volatile("tcgen05.alloc.cta_group::1.sync.aligned.shared::cta.b32 [%0], %1;" :: "r"(addr), "r"((uint32_t)(n)) : "memory")
#define TC_RELINQ() \
    asm volatile("tcgen05.relinquish_alloc_permit.cta_group::1.sync.aligned;")
#define TC_DEALLOC(tm, n) \
    asm volatile("tcgen05.dealloc.cta_group::1.sync.aligned.b32 %0, %1;" :: "r"(tm), "r"((uint32_t)(n)))
#define TC_COMMIT(addr) \
    asm volatile("tcgen05.commit.cta_group::1.mbarrier::arrive::one.shared::cluster.b64 [%0];" :: "r"(addr) : "memory")
#define TC_FENCE_AFTER()   asm volatile("tcgen05.fence::after_thread_sync;" ::: "memory")
#define TC_FENCE_BEFORE()  asm volatile("tcgen05.fence::before_thread_sync;" ::: "memory")
#define TC_WAIT_LD()       asm volatile("tcgen05.wait::ld.sync.aligned;" ::: "memory")
#define FENCE_ASYNC()      asm volatile("fence.proxy.async.shared::cta;" ::: "memory")
#define CP16(dst, src)  asm volatile("cp.async.cg.shared.global [%0], [%1], 16;" :: "r"(dst), "l"(src) : "memory")
#define CP_COMMIT()     asm volatile("cp.async.commit_group;" ::: "memory")
#define CP_WAIT0()      asm volatile("cp.async.wait_group 0;" ::: "memory")
#define CP_WAIT2()      asm volatile("cp.async.wait_group 2;" ::: "memory")

#define LDTM32(r, tma) \
    asm volatile("tcgen05.ld.sync.aligned.32x32b.x32.b32 " \
        "{%0,%1,%2,%3,%4,%5,%6,%7,%8,%9,%10,%11,%12,%13,%14,%15," \
        "%16,%17,%18,%19,%20,%21,%22,%23,%24,%25,%26,%27,%28,%29,%30,%31}, [%32];" \
        : "=r"((r)[0]),"=r"((r)[1]),"=r"((r)[2]),"=r"((r)[3]),"=r"((r)[4]),"=r"((r)[5]),"=r"((r)[6]),"=r"((r)[7]), \
          "=r"((r)[8]),"=r"((r)[9]),"=r"((r)[10]),"=r"((r)[11]),"=r"((r)[12]),"=r"((r)[13]),"=r"((r)[14]),"=r"((r)[15]), \
          "=r"((r)[16]),"=r"((r)[17]),"=r"((r)[18]),"=r"((r)[19]),"=r"((r)[20]),"=r"((r)[21]),"=r"((r)[22]),"=r"((r)[23]), \
          "=r"((r)[24]),"=r"((r)[25]),"=r"((r)[26]),"=r"((r)[27]),"=r"((r)[28]),"=r"((r)[29]),"=r"((r)[30]),"=r"((r)[31]) \
        : "r"(tma))

// SW128 desc (128B rows): layout 2, version 1, SBO=64, LBO=1
__device__ __forceinline__ uint64_t smem_desc(uint32_t addr) {
    return 0x4000404000010000ULL | (uint64_t)((addr >> 4) & 0x3FFF);
}
// SW64 desc (64B rows): layout 4, version 1, SBO=32, LBO=1
__device__ __forceinline__ uint64_t smem_desc64(uint32_t addr) {
    return 0x8000402000010000ULL | (uint64_t)((addr >> 4) & 0x3FFF);
}
__device__ __forceinline__ void mma_bf16_ss(uint32_t d, uint64_t ad, uint64_t bd,
                                            uint32_t idesc, uint32_t en) {
    asm volatile(
        "{\n\t.reg .pred p;\n\tsetp.ne.u32 p, %4, 0;\n\t"
        "tcgen05.mma.cta_group::1.kind::f16 [%0], %1, %2, %3, {%5,%5,%5,%5}, p;\n\t}"
        :: "r"(d), "l"(ad), "l"(bd), "r"(idesc), "r"(en), "r"(0u) : "memory");
}
#define IDESC(NN) (0x8000490u | ((uint32_t)((NN) / 8) << 17))

// ---- SW128 (128B rows, K-chunk 64) copy ----
__device__ __forceinline__ void copy_rows(const __nv_bfloat16* __restrict__ src,
                                          int stride, int k0, uint32_t dst,
                                          int rows, int tid) {
    for (int s = tid; s < rows * 8; s += 256) {
        int r = s >> 3, seg = s & 7;
        const char* sp = (const char*)(src + (size_t)r * stride + k0) + seg * 16;
        uint32_t off = (uint32_t)(r * 128 + seg * 16);
        uint32_t sw = off ^ ((off >> 3) & 0x70u);
        CP16(dst + sw, sp);
    }
}
// ---- SW64 (64B rows, K-chunk 32) copy ----
__device__ __forceinline__ void copy_rows64(const __nv_bfloat16* __restrict__ src,
                                            int stride, int k0, uint32_t dst,
                                            int rows, int tid) {
    for (int s = tid; s < rows * 4; s += 256) {
        int r = s >> 2, seg = s & 3;
        const char* sp = (const char*)(src + (size_t)r * stride + k0) + seg * 16;
        uint32_t off = (uint32_t)(r * 64 + seg * 16);
        uint32_t sw = off ^ ((off >> 3) & 0x30u);
        CP16(dst + sw, sp);
    }
}

// SW64 chunk (K=32): 3 products x 2 K-steps, single N<=256 tile
__device__ __forceinline__ void issue_chunk32(uint32_t d, uint32_t ahi, uint32_t alo,
                                              uint32_t bhi, uint32_t blo,
                                              uint32_t idesc, bool first) {
    uint64_t AH = smem_desc64(ahi), AL = smem_desc64(alo);
    uint64_t BH = smem_desc64(bhi), BL = smem_desc64(blo);
#pragma unroll
    for (int ks = 0; ks < 2; ks++) mma_bf16_ss(d, AH + 2 * ks, BH + 2 * ks, idesc, (first && ks == 0) ? 0u : 1u);
#pragma unroll
    for (int ks = 0; ks < 2; ks++) mma_bf16_ss(d, AH + 2 * ks, BL + 2 * ks, idesc, 1u);
#pragma unroll
    for (int ks = 0; ks < 2; ks++) mma_bf16_ss(d, AL + 2 * ks, BH + 2 * ks, idesc, 1u);
}

// qks: one K=64 shot across N=512 (2 x N=256 tiles), D cols 0..511
__device__ __forceinline__ void issue_qks(uint32_t tmem, uint32_t ahi, uint32_t alo,
                                          uint32_t bhi, uint32_t blo, uint32_t idesc) {
    uint64_t AH = smem_desc(ahi), AL = smem_desc(alo);
#pragma unroll
    for (int nt = 0; nt < 2; nt++) {
        uint64_t BH = smem_desc(bhi + (uint32_t)nt * 32768u);
        uint64_t BL = smem_desc(blo + (uint32_t)nt * 32768u);
        uint32_t d = tmem + (uint32_t)nt * 256u;
#pragma unroll
        for (int ks = 0; ks < 4; ks++) mma_bf16_ss(d, AH + 2 * ks, BH + 2 * ks, idesc, ks == 0 ? 0u : 1u);
#pragma unroll
        for (int ks = 0; ks < 4; ks++) mma_bf16_ss(d, AH + 2 * ks, BL + 2 * ks, idesc, 1u);
#pragma unroll
        for (int ks = 0; ks < 4; ks++) mma_bf16_ss(d, AL + 2 * ks, BH + 2 * ks, idesc, 1u);
    }
}
#endif  // USE_TCGEN05

// ---------------- spectral norm ---------------------------------------------
__global__ void sn_kernel(const float* __restrict__ Wq, const float* __restrict__ uq, const float* __restrict__ bq,
                          const float* __restrict__ Wk, const float* __restrict__ uk, const float* __restrict__ bk,
                          const float* __restrict__ Wv, const float* __restrict__ uv, const float* __restrict__ bv) {
    const float* W; const float* u; const float* bias; int out; int dst;
    if (blockIdx.x == 0)      { W = Wq; u = uq; bias = bq; out = CQ;   dst = 0;   }
    else if (blockIdx.x == 1) { W = Wk; u = uk; bias = bk; out = CQ;   dst = 64;  }
    else                      { W = Wv; u = uv; bias = bv; out = C_IN; dst = 128; }

    __shared__ float su[C_IN];
    __shared__ float sv[C_IN];
    __shared__ float red[512];
    int tid = threadIdx.x;

    if (tid < out) { su[tid] = u[tid]; g_bias[dst + tid] = bias[tid]; }
    __syncthreads();

    float t = 0.f;
    for (int i = 0; i < out; i++) t += W[i * C_IN + tid] * su[i];
    red[tid] = t * t;
    __syncthreads();
    for (int s = 256; s > 0; s >>= 1) { if (tid < s) red[tid] += red[tid + s]; __syncthreads(); }
    float nv = sqrtf(red[0]);
    sv[tid] = t / nv;
    __syncthreads();

    float p = 0.f;
    for (int i = tid; i < out; i += blockDim.x) {
        float r = 0.f;
        for (int j = 0; j < C_IN; j++) r += W[i * C_IN + j] * sv[j];
        p += r * r;
    }
    red[tid] = p;
    __syncthreads();
    for (int s = 256; s > 0; s >>= 1) { if (tid < s) red[tid] += red[tid + s]; __syncthreads(); }
    float inv_sigma = rsqrtf(red[0]);

    for (int e = tid; e < out * C_IN; e += blockDim.x) {
        float val = W[e] * inv_sigma;
        __nv_bfloat16 h, l;
        split1(val, h, l);
        g_Wn_hi[(size_t)dst * C_IN + e] = h;
        g_Wn_lo[(size_t)dst * C_IN + e] = l;
    }
}

// ---------------- x transpose + split ----------------------------------------
__global__ void transpose_kernel(const float* __restrict__ x) {
    __shared__ float t[32][33];
    int b = blockIdx.z, c0 = blockIdx.y * 32, n0 = blockIdx.x * 32;
    int tx = threadIdx.x, ty = threadIdx.y;
    const float* src = x + (size_t)b * C_IN * N_TOK;
    size_t dbase = (size_t)b * N_TOK * C_IN;
#pragma unroll
    for (int i = ty; i < 32; i += 8) t[i][tx] = src[(size_t)(c0 + i) * N_TOK + n0 + tx];
    __syncthreads();
#pragma unroll
    for (int i = ty; i < 32; i += 8) {
        float val = t[tx][i];
        __nv_bfloat16 h, l;
        split1(val, h, l);
        size_t off = dbase + (size_t)(n0 + i) * C_IN + c0 + tx;
        g_xT_hi[off] = h;
        g_xT_lo[off] = l;
    }
}

// ---------------- proj: D[n=128][o 256-tile], 4-stage pipeline ---------------
// grid (8, 3, BATCH): n0 = x*128, o0 = y*256, NN = (y<2)?256:128
__global__ void __launch_bounds__(256) proj_mma() {
#if USE_TCGEN05
    extern __shared__ char dyn[];
    __shared__ uint32_t s_tmem;
    __shared__ uint64_t s_mb[4];
    __shared__ float s_bias[256];
    __shared__ float tb[4 * 32 * 33];

    int tid = threadIdx.x, wid = tid >> 5, lane = tid & 31;
    int b = blockIdx.z, n0 = blockIdx.x * 128, y = blockIdx.y;
    int o0 = y * 256;
    int NN = (y < 2) ? 256 : 128;
    uint32_t idesc = IDESC(NN);

    uint32_t dynb = (cvta_smem(dyn) + 1023u) & ~1023u;
    uint32_t mba[4];
#pragma unroll
    for (int i = 0; i < 4; i++) mba[i] = cvta_smem(&s_mb[i]);

    if (wid == 0) { TC_ALLOC(cvta_smem(&s_tmem), 256); TC_RELINQ(); }
    if (tid == 0) { MB_INIT(mba[0], 1); MB_INIT(mba[1], 1); MB_INIT(mba[2], 1); MB_INIT(mba[3], 1); }
    for (int i = tid; i < NN; i += 256) s_bias[i] = g_bias[o0 + i];
    __syncthreads();
    uint32_t tmem = s_tmem;

    const __nv_bfloat16* Ah = g_xT_hi + ((size_t)b * N_TOK + n0) * C_IN;
    const __nv_bfloat16* Al = g_xT_lo + ((size_t)b * N_TOK + n0) * C_IN;
    const __nv_bfloat16* Bh = g_Wn_hi + (size_t)o0 * C_IN;
    const __nv_bfloat16* Bl = g_Wn_lo + (size_t)o0 * C_IN;

    auto copyset = [&](int ck) {
        uint32_t base = dynb + (uint32_t)(ck & 3) * 49152u;
        int k0 = ck * 32;
        copy_rows64(Ah, C_IN, k0, base, 128, tid);
        copy_rows64(Al, C_IN, k0, base + 8192u, 128, tid);
        copy_rows64(Bh, C_IN, k0, base + 16384u, NN, tid);
        copy_rows64(Bl, C_IN, k0, base + 32768u, NN, tid);
        CP_COMMIT();
    };

    const int KT = C_IN / 32;   // 16
    copyset(0);
    copyset(1);
    for (int kt = 0; kt < KT; kt++) {
        if (kt >= 2) MB_WAIT(mba[(kt - 2) & 3], ((kt - 2) >> 2) & 1);
        if (kt + 2 < KT) copyset(kt + 2); else CP_COMMIT();
        CP_WAIT2();
        __syncthreads();
        if (wid == 0 && elect_one()) {
            uint32_t base = dynb + (uint32_t)(kt & 3) * 49152u;
            FENCE_ASYNC();
            issue_chunk32(tmem, base, base + 8192u, base + 16384u, base + 32768u, idesc, kt == 0);
            TC_COMMIT(mba[kt & 3]);
        }
    }
    MB_WAIT(mba[(KT - 2) & 3], ((KT - 2) >> 2) & 1);
    MB_WAIT(mba[(KT - 1) & 3], ((KT - 1) >> 2) & 1);
    TC_FENCE_AFTER();
    __syncthreads();

    for (int c0 = 0; c0 < NN; c0 += 32) {
        int oc0 = o0 + c0;
        bool dir = oc0 < 128;
        if (tid < 128) {
            uint32_t r[32];
            LDTM32(r, tmem + c0);
            TC_WAIT_LD();
            if (dir) {
                int n = n0 + wid * 32 + lane;
                int oo = (oc0 < 64) ? oc0 : (oc0 - 64);
                uint32_t* hi = (uint32_t*)((oc0 < 64) ? g_qT_hi : g_kT_hi) + ((size_t)b * N_TOK + n) * 32;
                uint32_t* lo = (uint32_t*)((oc0 < 64) ? g_qT_lo : g_kT_lo) + ((size_t)b * N_TOK + n) * 32;
#pragma unroll
                for (int j = 0; j < 32; j += 4) {
                    uint32_t h0, l0, h1, l1;
                    pack_split2(__uint_as_float(r[j + 0]) + s_bias[c0 + j + 0],
                                __uint_as_float(r[j + 1]) + s_bias[c0 + j + 1], h0, l0);
                    pack_split2(__uint_as_float(r[j + 2]) + s_bias[c0 + j + 2],
                                __uint_as_float(r[j + 3]) + s_bias[c0 + j + 3], h1, l1);
                    *(uint2*)(hi + ((oo + j) >> 1)) = make_uint2(h0, h1);
                    *(uint2*)(lo + ((oo + j) >> 1)) = make_uint2(l0, l1);
                }
            } else {
                int cb = wid * 1056 + lane * 33;
#pragma unroll
                for (int j = 0; j < 32; j++) tb[cb + j] = __uint_as_float(r[j]);
            }
        }
        if (!dir) {
            __syncthreads();
            int cg = oc0 - 128;
#pragma unroll
            for (int i = 0; i < 16; i++) {
                int rid = wid * 16 + i;
                int wsrc = rid >> 5, j = rid & 31;
                float val = tb[wsrc * 1056 + lane * 33 + j] + s_bias[c0 + j];
                __nv_bfloat16 h, l;
                split1(val, h, l);
                size_t off = ((size_t)b * C_IN + cg + j) * N_TOK + n0 + wsrc * 32 + lane;
                g_v_hi[off] = h;
                g_v_lo[off] = l;
            }
            __syncthreads();
        }
    }
    __syncthreads();
    if (wid == 0) TC_DEALLOC(tmem, 256);
#else
    int tid = threadIdx.x;
    int b = blockIdx.z, n0 = blockIdx.x * 128, y = blockIdx.y, o0 = y * 256;
    int NN = (y < 2) ? 256 : 128;
    for (int e = tid; e < 128 * NN; e += 256) {
        int n = n0 + (e & 127);
        int oc = o0 + (e >> 7);
        const __nv_bfloat16* xh = g_xT_hi + ((size_t)b * N_TOK + n) * C_IN;
        const __nv_bfloat16* xl = g_xT_lo + ((size_t)b * N_TOK + n) * C_IN;
        const __nv_bfloat16* wh = g_Wn_hi + (size_t)oc * C_IN;
        const __nv_bfloat16* wl = g_Wn_lo + (size_t)oc * C_IN;
        float s = 0.f;
        for (int c = 0; c < C_IN; c++) {
            float xa = __bfloat162float(xh[c]) + __bfloat162float(xl[c]);
            float wa = __bfloat162float(wh[c]) + __bfloat162float(wl[c]);
            s += xa * wa;
        }
        s += g_bias[oc];
        __nv_bfloat16 h, l;
        split1(s, h, l);
        if (oc < 64)       { size_t o = ((size_t)b * N_TOK + n) * CQ + oc;        g_qT_hi[o] = h; g_qT_lo[o] = l; }
        else if (oc < 128) { size_t o = ((size_t)b * N_TOK + n) * CQ + (oc - 64); g_kT_hi[o] = h; g_kT_lo[o] = l; }
        else               { size_t o = ((size_t)b * C_IN + (oc - 128)) * N_TOK + n; g_v_hi[o] = h; g_v_lo[o] = l; }
    }
#endif
}

// ---------------- qks: fused QK^T + exp + row-sum -----------------------------
// grid (8, BATCH): m0 = x*128. Two halves of n (512 each): D[m=128][n=512] in TMEM,
// epilogue applies exp (no max-subtract), writes unnormalized P hi/lo + row sums.
__global__ void __launch_bounds__(256) qks_mma() {
#if USE_TCGEN05
    extern __shared__ char dyn[];
    __shared__ uint32_t s_tmem;
    __shared__ uint64_t s_mb[2];

    int tid = threadIdx.x, wid = tid >> 5, lane = tid & 31;
    int b = blockIdx.y, m0 = blockIdx.x * 128;
    uint32_t idesc = IDESC(256);

    uint32_t dynb = (cvta_smem(dyn) + 1023u) & ~1023u;
    uint32_t AHI = dynb, ALO = dynb + 16384u, BHI = dynb + 32768u, BLO = dynb + 98304u;
    uint32_t mb0 = cvta_smem(&s_mb[0]), mb1 = cvta_smem(&s_mb[1]);

    if (wid == 0) { TC_ALLOC(cvta_smem(&s_tmem), 512); TC_RELINQ(); }
    if (tid == 0) { MB_INIT(mb0, 1); MB_INIT(mb1, 1); }
    __syncthreads();
    uint32_t tmem = s_tmem;

    const __nv_bfloat16* Kh = g_kT_hi + ((size_t)b * N_TOK + m0) * CQ;
    const __nv_bfloat16* Kl = g_kT_lo + ((size_t)b * N_TOK + m0) * CQ;
    const __nv_bfloat16* Qh = g_qT_hi + (size_t)b * N_TOK * CQ;
    const __nv_bfloat16* Ql = g_qT_lo + (size_t)b * N_TOK * CQ;

    // A (kT block) + B half0 (qT rows 0..511)
    copy_rows(Kh, CQ, 0, AHI, 128, tid);
    copy_rows(Kl, CQ, 0, ALO, 128, tid);
    copy_rows(Qh, CQ, 0, BHI, 512, tid);
    copy_rows(Ql, CQ, 0, BLO, 512, tid);
    CP_COMMIT();
    CP_WAIT0();
    __syncthreads();
    if (wid == 0 && elect_one()) {
        FENCE_ASYNC();
        issue_qks(tmem, AHI, ALO, BHI, BLO, idesc);
        TC_COMMIT(mb0);
    }
    MB_WAIT(mb0, 0);
    TC_FENCE_AFTER();

    // kick off B half1 copies (B smem free: half0 MMA complete)
    copy_rows(Qh + (size_t)512 * CQ, CQ, 0, BHI, 512, tid);
    copy_rows(Ql + (size_t)512 * CQ, CQ, 0, BLO, 512, tid);
    CP_COMMIT();

    float rsum = 0.f;
    int m = m0 + wid * 32 + lane;
    uint32_t* Ph = (uint32_t*)g_P_hi + ((size_t)b * N_TOK + m) * 512;
    uint32_t* Pl = (uint32_t*)g_P_lo + ((size_t)b * N_TOK + m) * 512;

    // process half0
    if (tid < 128) {
        for (int c0 = 0; c0 < 512; c0 += 32) {
            uint32_t r[32];
            LDTM32(r, tmem + c0);
            TC_WAIT_LD();
            uint32_t hb[16], lb[16];
#pragma unroll
            for (int j = 0; j < 32; j += 2) {
                float e0 = __expf(__uint_as_float(r[j]));
                float e1 = __expf(__uint_as_float(r[j + 1]));
                rsum += e0 + e1;
                pack_split2(e0, e1, hb[j >> 1], lb[j >> 1]);
            }
            int base = c0 >> 1;
#pragma unroll
            for (int q = 0; q < 4; q++) {
                *(uint4*)(Ph + base + q * 4) = make_uint4(hb[q*4], hb[q*4+1], hb[q*4+2], hb[q*4+3]);
                *(uint4*)(Pl + base + q * 4) = make_uint4(lb[q*4], lb[q*4+1], lb[q*4+2], lb[q*4+3]);
            }
        }
    }
    TC_FENCE_BEFORE();
    CP_WAIT0();
    __syncthreads();
    if (wid == 0 && elect_one()) {
        FENCE_ASYNC();
        TC_FENCE_AFTER();
        issue_qks(tmem, AHI, ALO, BHI, BLO, idesc);
        TC_COMMIT(mb1);
    }
    MB_WAIT(mb1, 0);
    TC_FENCE_AFTER();

    // process half1
    if (tid < 128) {
        for (int c0 = 0; c0 < 512; c0 += 32) {
            uint32_t r[32];
            LDTM32(r, tmem + c0);
            TC_WAIT_LD();
            uint32_t hb[16], lb[16];
#pragma unroll
            for (int j = 0; j < 32; j += 2) {
                float e0 = __expf(__uint_as_float(r[j]));
                float e1 = __expf(__uint_as_float(r[j + 1]));
                rsum += e0 + e1;
                pack_split2(e0, e1, hb[j >> 1], lb[j >> 1]);
            }
            int base = 256 + (c0 >> 1);
#pragma unroll
            for (int q = 0; q < 4; q++) {
                *(uint4*)(Ph + base + q * 4) = make_uint4(hb[q*4], hb[q*4+1], hb[q*4+2], hb[q*4+3]);
                *(uint4*)(Pl + base + q * 4) = make_uint4(lb[q*4], lb[q*4+1], lb[q*4+2], lb[q*4+3]);
            }
        }
        g_rsum[(size_t)b * N_TOK + m] = rsum;
    }
    __syncthreads();
    if (wid == 0) TC_DEALLOC(tmem, 512);
#else
    int tid = threadIdx.x;
    int b = blockIdx.y, m0 = blockIdx.x * 128;
    if (tid < 128) {
        int m = m0 + tid;
        const __nv_bfloat16* kh = g_kT_hi + ((size_t)b * N_TOK + m) * CQ;
        const __nv_bfloat16* kl = g_kT_lo + ((size_t)b * N_TOK + m) * CQ;
        float rsum = 0.f;
        for (int n = 0; n < N_TOK; n++) {
            const __nv_bfloat16* qh = g_qT_hi + ((size_t)b * N_TOK + n) * CQ;
            const __nv_bfloat16* ql = g_qT_lo + ((size_t)b * N_TOK + n) * CQ;
            float s = 0.f;
            for (int o = 0; o < CQ; o++)
                s += (__bfloat162float(qh[o]) + __bfloat162float(ql[o])) *
                     (__bfloat162float(kh[o]) + __bfloat162float(kl[o]));
            float e = __expf(s);
            rsum += e;
            __nv_bfloat16 h, l;
            split1(e, h, l);
            size_t off = ((size_t)b * N_TOK + m) * N_TOK + n;
            g_P_hi[off] = h;
            g_P_lo[off] = l;
        }
        g_rsum[(size_t)b * N_TOK + m] = rsum;
    }
#endif
}

// ---------------- av: D[m=128][c=256], epilogue /rsum -----------------------
// grid (8, 2, BATCH): m0 = x*128, c0g = y*256
__global__ void __launch_bounds__(256) av_mma(const float* __restrict__ x,
                                              const float* __restrict__ gamma_p,
                                              float* __restrict__ out) {
#if USE_TCGEN05
    extern __shared__ char dyn[];
    __shared__ uint32_t s_tmem;
    __shared__ uint64_t s_mb[4];

    int tid = threadIdx.x, wid = tid >> 5, lane = tid & 31;
    int b = blockIdx.z, m0 = blockIdx.x * 128, c0g = blockIdx.y * 256;
    uint32_t idesc = IDESC(256);

    uint32_t dynb = (cvta_smem(dyn) + 1023u) & ~1023u;
    uint32_t mba[4];
#pragma unroll
    for (int i = 0; i < 4; i++) mba[i] = cvta_smem(&s_mb[i]);

    if (wid == 0) { TC_ALLOC(cvta_smem(&s_tmem), 256); TC_RELINQ(); }
    if (tid == 0) { MB_INIT(mba[0], 1); MB_INIT(mba[1], 1); MB_INIT(mba[2], 1); MB_INIT(mba[3], 1); }
    __syncthreads();
    uint32_t tmem = s_tmem;

    const __nv_bfloat16* Ah = g_P_hi + ((size_t)b * N_TOK + m0) * N_TOK;
    const __nv_bfloat16* Al = g_P_lo + ((size_t)b * N_TOK + m0) * N_TOK;
    const __nv_bfloat16* Bh = g_v_hi + ((size_t)b * C_IN + c0g) * N_TOK;
    const __nv_bfloat16* Bl = g_v_lo + ((size_t)b * C_IN + c0g) * N_TOK;

    auto copyset = [&](int ck) {
        uint32_t base = dynb + (uint32_t)(ck & 3) * 49152u;
        int k0 = ck * 32;
        copy_rows64(Ah, N_TOK, k0, base, 128, tid);
        copy_rows64(Al, N_TOK, k0, base + 8192u, 128, tid);
        copy_rows64(Bh, N_TOK, k0, base + 16384u, 256, tid);
        copy_rows64(Bl, N_TOK, k0, base + 32768u, 256, tid);
        CP_COMMIT();
    };

    const int KT = N_TOK / 32;   // 32
    copyset(0);
    copyset(1);
    for (int kt = 0; kt < KT; kt++) {
        if (kt >= 2) MB_WAIT(mba[(kt - 2) & 3], ((kt - 2) >> 2) & 1);
        if (kt + 2 < KT) copyset(kt + 2); else CP_COMMIT();
        CP_WAIT2();
        __syncthreads();
        if (wid == 0 && elect_one()) {
            uint32_t base = dynb + (uint32_t)(kt & 3) * 49152u;
            FENCE_ASYNC();
            issue_chunk32(tmem, base, base + 8192u, base + 16384u, base + 32768u, idesc, kt == 0);
            TC_COMMIT(mba[kt & 3]);
        }
    }
    MB_WAIT(mba[(KT - 2) & 3], ((KT - 2) >> 2) & 1);
    MB_WAIT(mba[(KT - 1) & 3], ((KT - 1) >> 2) & 1);
    TC_FENCE_AFTER();

    float g = *gamma_p;
    int m = m0 + wid * 32 + lane;
    float ginv = (tid < 128) ? (g / g_rsum[(size_t)b * N_TOK + m]) : 0.f;
    for (int c0 = 0; c0 < 256; c0 += 32) {
        if (tid < 128) {
            uint32_t r[32];
            LDTM32(r, tmem + c0);
            TC_WAIT_LD();
#pragma unroll
            for (int j = 0; j < 32; j++) {
                int c = c0g + c0 + j;
                size_t off = ((size_t)b * C_IN + c) * N_TOK + m;
                out[off] = ginv * __uint_as_float(r[j]) + x[off];
            }
        }
    }
    __syncthreads();
    if (wid == 0) TC_DEALLOC(tmem, 256);
#else
    int tid = threadIdx.x;
    int b = blockIdx.z, m0 = blockIdx.x * 128, c0g = blockIdx.y * 256;
    float g = *gamma_p;
    for (int e = tid; e < 128 * 256; e += 256) {
        int m = m0 + (e & 127);
        int c = c0g + (e >> 7);
        const __nv_bfloat16* vh = g_v_hi + ((size_t)b * C_IN + c) * N_TOK;
        const __nv_bfloat16* vl = g_v_lo + ((size_t)b * C_IN + c) * N_TOK;
        const __nv_bfloat16* ph = g_P_hi + ((size_t)b * N_TOK + m) * N_TOK;
        const __nv_bfloat16* pl = g_P_lo + ((size_t)b * N_TOK + m) * N_TOK;
        float s = 0.f;
        for (int n = 0; n < N_TOK; n++)
            s += (__bfloat162float(vh[n]) + __bfloat162float(vl[n])) *
                 (__bfloat162float(ph[n]) + __bfloat162float(pl[n]));
        size_t off = ((size_t)b * C_IN + c) * N_TOK + m;
        out[off] = g * s / g_rsum[(size_t)b * N_TOK + m] + x[off];
    }
#endif
}

// ---------------- launch -----------------------------------------------------
extern "C" void kernel_launch(void* const* d_in, const int* in_sizes, int n_in,
                              void* d_out, int out_size) {
    const float* x     = (const float*)d_in[0];
    const float* Wq    = (const float*)d_in[1];
    const float* bq    = (const float*)d_in[2];
    const float* uq    = (const float*)d_in[3];
    const float* Wk    = (const float*)d_in[4];
    const float* bk    = (const float*)d_in[5];
    const float* uk    = (const float*)d_in[6];
    const float* Wv    = (const float*)d_in[7];
    const float* bv    = (const float*)d_in[8];
    const float* uv    = (const float*)d_in[9];
    const float* gamma = (const float*)d_in[10];
    float* out = (float*)d_out;

    cudaFuncSetAttribute(proj_mma, cudaFuncAttributeMaxDynamicSharedMemorySize, 197632);
    cudaFuncSetAttribute(qks_mma,  cudaFuncAttributeMaxDynamicSharedMemorySize, 164864);
    cudaFuncSetAttribute(av_mma,   cudaFuncAttributeMaxDynamicSharedMemorySize, 197632);

    sn_kernel<<<3, 512>>>(Wq, uq, bq, Wk, uk, bk, Wv, uv, bv);
    transpose_kernel<<<dim3(32, 16, BATCH), dim3(32, 8)>>>(x);
    proj_mma<<<dim3(8, 3, BATCH), 256, 197632>>>();
    qks_mma<<<dim3(8, BATCH), 256, 164864>>>();
    av_mma<<<dim3(8, 2, BATCH), 256, 197632>>>(x, gamma, out);
}

// round 12
// speedup vs baseline: 1.8320x; 1.2248x over previous
#include <cuda_runtime.h>
#include <cuda_bf16.h>
#include <math.h>
#include <stdint.h>

#define N_TOK 1024
#define C_IN  512
#define CQ    64
#define BATCH 32

#if defined(__CUDA_ARCH__)
#if defined(__CUDA_ARCH_FEAT_SM103_ALL)
#define USE_TCGEN05 1
#else
#define USE_TCGEN05 0
#endif
#else
#define USE_TCGEN05 0
#endif

// ---------------- scratch (device globals; no allocation allowed) ----------
__device__ __align__(128) __nv_bfloat16 g_Wn_hi[640 * C_IN];   // rows: q 0-63, k 64-127, v 128-639 (K-major)
__device__ __align__(128) __nv_bfloat16 g_Wn_lo[640 * C_IN];
__device__ __align__(128) float g_bias[640];
__device__ __align__(128) __nv_bfloat16 g_xT_hi[(size_t)BATCH * N_TOK * C_IN];  // [b][n][c]
__device__ __align__(128) __nv_bfloat16 g_xT_lo[(size_t)BATCH * N_TOK * C_IN];
__device__ __align__(128) __nv_bfloat16 g_qT_hi[(size_t)BATCH * N_TOK * CQ];    // [b][n][o]
__device__ __align__(128) __nv_bfloat16 g_qT_lo[(size_t)BATCH * N_TOK * CQ];
__device__ __align__(128) __nv_bfloat16 g_kT_hi[(size_t)BATCH * N_TOK * CQ];    // [b][m][o]
__device__ __align__(128) __nv_bfloat16 g_kT_lo[(size_t)BATCH * N_TOK * CQ];
__device__ __align__(128) __nv_bfloat16 g_v_hi [(size_t)BATCH * C_IN * N_TOK];  // [b][c][n]
__device__ __align__(128) __nv_bfloat16 g_v_lo [(size_t)BATCH * C_IN * N_TOK];
__device__ __align__(128) __nv_bfloat16 g_P_hi [(size_t)BATCH * N_TOK * N_TOK]; // [b][m][n] unnormalized exp(S)
__device__ __align__(128) __nv_bfloat16 g_P_lo [(size_t)BATCH * N_TOK * N_TOK];
__device__ __align__(128) float         g_rsum [(size_t)BATCH * N_TOK];         // [b][m] row sums

// ---------------- common helpers --------------------------------------------
__device__ __forceinline__ uint32_t cvta_smem(const void* p) {
    uint32_t a;
    asm("{ .reg .u64 t; cvta.to.shared.u64 t, %1; cvt.u32.u64 %0, t; }" : "=r"(a) : "l"(p));
    return a;
}
__device__ __forceinline__ void pack_split2(float a, float b, uint32_t& h, uint32_t& l) {
    __nv_bfloat16 ah = __float2bfloat16(a);
    __nv_bfloat16 bh = __float2bfloat16(b);
    __nv_bfloat16 al = __float2bfloat16(a - __bfloat162float(ah));
    __nv_bfloat16 bl = __float2bfloat16(b - __bfloat162float(bh));
    h = (uint32_t)__bfloat16_as_ushort(ah) | ((uint32_t)__bfloat16_as_ushort(bh) << 16);
    l = (uint32_t)__bfloat16_as_ushort(al) | ((uint32_t)__bfloat16_as_ushort(bl) << 16);
}
__device__ __forceinline__ void split1(float v, __nv_bfloat16& h, __nv_bfloat16& l) {
    h = __float2bfloat16(v);
    l = __float2bfloat16(v - __bfloat162float(h));
}

#if USE_TCGEN05
__device__ __forceinline__ int elect_one() {
    uint32_t pred;
    asm volatile("{\n\t.reg .pred p;\n\telect.sync _|p, 0xFFFFFFFF;\n\tselp.b32 %0, 1, 0, p;\n\t}" : "=r"(pred));
    return (int)pred;
}
#define MB_INIT(addr, cnt) \
    asm volatile("mbarrier.init.shared.b64 [%0], %1;" :: "r"(addr), "r"((uint32_t)(cnt)) : "memory")
#define MB_WAIT(addr, phv) do { \
    uint32_t _m = (addr), _p = (uint32_t)(phv), _d; \
    asm volatile("{\n\t.reg .pred p;\n\t" \
        "mbarrier.try_wait.parity.acquire.cta.shared::cta.b64 p, [%1], %2;\n\t" \
        "selp.b32 %0,1,0,p;\n\t}" : "=r"(_d) : "r"(_m), "r"(_p) : "memory"); \
    while (!_d) { \
        asm volatile("{\n\t.reg .pred p;\n\t" \
            "mbarrier.try_wait.parity.acquire.cta.shared::cta.b64 p, [%1], %2, 0x989680;\n\t" \
            "selp.b32 %0,1,0,p;\n\t}" : "=r"(_d) : "r"(_m), "r"(_p) : "memory"); \
    } \
} while (0)
#define TC_ALLOC(addr, n) \
    asm volatile("tcgen05.alloc.cta_group::1.sync.aligned.shared::cta.b32 [%0], %1;" :: "r"(addr), "r"((uint32_t)(n)) : "memory")
#define TC_RELINQ() \
    asm volatile("tcgen05.relinquish_alloc_permit.cta_group::1.sync.aligned;")
#define TC_DEALLOC(tm, n) \
    asm volatile("tcgen05.dealloc.cta_group::1.sync.aligned.b32 %0, %1;" :: "r"(tm), "r"((uint32_t)(n)))
#define TC_COMMIT(addr) \
    asm volatile("tcgen05.commit.cta_group::1.mbarrier::arrive::one.shared::cluster.b64 [%0];" :: "r"(addr) : "memory")
#define TC_FENCE_AFTER()   asm volatile("tcgen05.fence::after_thread_sync;" ::: "memory")
#define TC_FENCE_BEFORE()  asm volatile("tcgen05.fence::before_thread_sync;" ::: "memory")
#define TC_WAIT_LD()       asm volatile("tcgen05.wait::ld.sync.aligned;" ::: "memory")
#define FENCE_ASYNC()      asm volatile("fence.proxy.async.shared::cta;" ::: "memory")
#define CP16(dst, src)  asm volatile("cp.async.cg.shared.global [%0], [%1], 16;" :: "r"(dst), "l"(src) : "memory")
#define CP_COMMIT()     asm volatile("cp.async.commit_group;" ::: "memory")
#define CP_WAIT0()      asm volatile("cp.async.wait_group 0;" ::: "memory")

#define LDTM32(r, tma) \
    asm volatile("tcgen05.ld.sync.aligned.32x32b.x32.b32 " \
        "{%0,%1,%2,%3,%4,%5,%6,%7,%8,%9,%10,%11,%12,%13,%14,%15," \
        "%16,%17,%18,%19,%20,%21,%22,%23,%24,%25,%26,%27,%28,%29,%30,%31}, [%32];" \
        : "=r"((r)[0]),"=r"((r)[1]),"=r"((r)[2]),"=r"((r)[3]),"=r"((r)[4]),"=r"((r)[5]),"=r"((r)[6]),"=r"((r)[7]), \
          "=r"((r)[8]),"=r"((r)[9]),"=r"((r)[10]),"=r"((r)[11]),"=r"((r)[12]),"=r"((r)[13]),"=r"((r)[14]),"=r"((r)[15]), \
          "=r"((r)[16]),"=r"((r)[17]),"=r"((r)[18]),"=r"((r)[19]),"=r"((r)[20]),"=r"((r)[21]),"=r"((r)[22]),"=r"((r)[23]), \
          "=r"((r)[24]),"=r"((r)[25]),"=r"((r)[26]),"=r"((r)[27]),"=r"((r)[28]),"=r"((r)[29]),"=r"((r)[30]),"=r"((r)[31]) \
        : "r"(tma))

// SW128 desc (128B rows): layout 2, version 1, SBO=64, LBO=1
__device__ __forceinline__ uint64_t smem_desc(uint32_t addr) {
    return 0x4000404000010000ULL | (uint64_t)((addr >> 4) & 0x3FFF);
}
// SW64 desc (64B rows): layout 4, version 1, SBO=32, LBO=1
__device__ __forceinline__ uint64_t smem_desc64(uint32_t addr) {
    return 0x8000402000010000ULL | (uint64_t)((addr >> 4) & 0x3FFF);
}
__device__ __forceinline__ void mma_bf16_ss(uint32_t d, uint64_t ad, uint64_t bd,
                                            uint32_t idesc, uint32_t en) {
    asm volatile(
        "{\n\t.reg .pred p;\n\tsetp.ne.u32 p, %4, 0;\n\t"
        "tcgen05.mma.cta_group::1.kind::f16 [%0], %1, %2, %3, {%5,%5,%5,%5}, p;\n\t}"
        :: "r"(d), "l"(ad), "l"(bd), "r"(idesc), "r"(en), "r"(0u) : "memory");
}
#define IDESC(NN) (0x8000490u | ((uint32_t)((NN) / 8) << 17))

// ---- SW128 (128B rows, K-chunk 64) copy ----
__device__ __forceinline__ void copy_rows(const __nv_bfloat16* __restrict__ src,
                                          int stride, int k0, uint32_t dst,
                                          int rows, int tid) {
    for (int s = tid; s < rows * 8; s += 256) {
        int r = s >> 3, seg = s & 7;
        const char* sp = (const char*)(src + (size_t)r * stride + k0) + seg * 16;
        uint32_t off = (uint32_t)(r * 128 + seg * 16);
        uint32_t sw = off ^ ((off >> 3) & 0x70u);
        CP16(dst + sw, sp);
    }
}
// ---- SW64 (64B rows, K-chunk 32) copy ----
__device__ __forceinline__ void copy_rows64(const __nv_bfloat16* __restrict__ src,
                                            int stride, int k0, uint32_t dst,
                                            int rows, int tid) {
    for (int s = tid; s < rows * 4; s += 256) {
        int r = s >> 2, seg = s & 3;
        const char* sp = (const char*)(src + (size_t)r * stride + k0) + seg * 16;
        uint32_t off = (uint32_t)(r * 64 + seg * 16);
        uint32_t sw = off ^ ((off >> 3) & 0x30u);
        CP16(dst + sw, sp);
    }
}

// SW64 chunk (K=32): 3 products x 2 K-steps, single N<=256 tile
__device__ __forceinline__ void issue_chunk32(uint32_t d, uint32_t ahi, uint32_t alo,
                                              uint32_t bhi, uint32_t blo,
                                              uint32_t idesc, bool first) {
    uint64_t AH = smem_desc64(ahi), AL = smem_desc64(alo);
    uint64_t BH = smem_desc64(bhi), BL = smem_desc64(blo);
#pragma unroll
    for (int ks = 0; ks < 2; ks++) mma_bf16_ss(d, AH + 2 * ks, BH + 2 * ks, idesc, (first && ks == 0) ? 0u : 1u);
#pragma unroll
    for (int ks = 0; ks < 2; ks++) mma_bf16_ss(d, AH + 2 * ks, BL + 2 * ks, idesc, 1u);
#pragma unroll
    for (int ks = 0; ks < 2; ks++) mma_bf16_ss(d, AL + 2 * ks, BH + 2 * ks, idesc, 1u);
}

// qks: one K=64 shot across N=512 (2 x N=256 tiles), D cols 0..511
__device__ __forceinline__ void issue_qks(uint32_t tmem, uint32_t ahi, uint32_t alo,
                                          uint32_t bhi, uint32_t blo, uint32_t idesc) {
    uint64_t AH = smem_desc(ahi), AL = smem_desc(alo);
#pragma unroll
    for (int nt = 0; nt < 2; nt++) {
        uint64_t BH = smem_desc(bhi + (uint32_t)nt * 32768u);
        uint64_t BL = smem_desc(blo + (uint32_t)nt * 32768u);
        uint32_t d = tmem + (uint32_t)nt * 256u;
#pragma unroll
        for (int ks = 0; ks < 4; ks++) mma_bf16_ss(d, AH + 2 * ks, BH + 2 * ks, idesc, ks == 0 ? 0u : 1u);
#pragma unroll
        for (int ks = 0; ks < 4; ks++) mma_bf16_ss(d, AH + 2 * ks, BL + 2 * ks, idesc, 1u);
#pragma unroll
        for (int ks = 0; ks < 4; ks++) mma_bf16_ss(d, AL + 2 * ks, BH + 2 * ks, idesc, 1u);
    }
}
#endif  // USE_TCGEN05

// ---------------- spectral norm ---------------------------------------------
__global__ void sn_kernel(const float* __restrict__ Wq, const float* __restrict__ uq, const float* __restrict__ bq,
                          const float* __restrict__ Wk, const float* __restrict__ uk, const float* __restrict__ bk,
                          const float* __restrict__ Wv, const float* __restrict__ uv, const float* __restrict__ bv) {
    const float* W; const float* u; const float* bias; int out; int dst;
    if (blockIdx.x == 0)      { W = Wq; u = uq; bias = bq; out = CQ;   dst = 0;   }
    else if (blockIdx.x == 1) { W = Wk; u = uk; bias = bk; out = CQ;   dst = 64;  }
    else                      { W = Wv; u = uv; bias = bv; out = C_IN; dst = 128; }

    __shared__ float su[C_IN];
    __shared__ float sv[C_IN];
    __shared__ float red[512];
    int tid = threadIdx.x;

    if (tid < out) { su[tid] = u[tid]; g_bias[dst + tid] = bias[tid]; }
    __syncthreads();

    float t = 0.f;
    for (int i = 0; i < out; i++) t += W[i * C_IN + tid] * su[i];
    red[tid] = t * t;
    __syncthreads();
    for (int s = 256; s > 0; s >>= 1) { if (tid < s) red[tid] += red[tid + s]; __syncthreads(); }
    float nv = sqrtf(red[0]);
    sv[tid] = t / nv;
    __syncthreads();

    float p = 0.f;
    for (int i = tid; i < out; i += blockDim.x) {
        float r = 0.f;
        for (int j = 0; j < C_IN; j++) r += W[i * C_IN + j] * sv[j];
        p += r * r;
    }
    red[tid] = p;
    __syncthreads();
    for (int s = 256; s > 0; s >>= 1) { if (tid < s) red[tid] += red[tid + s]; __syncthreads(); }
    float inv_sigma = rsqrtf(red[0]);

    for (int e = tid; e < out * C_IN; e += blockDim.x) {
        float val = W[e] * inv_sigma;
        __nv_bfloat16 h, l;
        split1(val, h, l);
        g_Wn_hi[(size_t)dst * C_IN + e] = h;
        g_Wn_lo[(size_t)dst * C_IN + e] = l;
    }
}

// ---------------- x transpose + split ----------------------------------------
__global__ void transpose_kernel(const float* __restrict__ x) {
    __shared__ float t[32][33];
    int b = blockIdx.z, c0 = blockIdx.y * 32, n0 = blockIdx.x * 32;
    int tx = threadIdx.x, ty = threadIdx.y;
    const float* src = x + (size_t)b * C_IN * N_TOK;
    size_t dbase = (size_t)b * N_TOK * C_IN;
#pragma unroll
    for (int i = ty; i < 32; i += 8) t[i][tx] = src[(size_t)(c0 + i) * N_TOK + n0 + tx];
    __syncthreads();
#pragma unroll
    for (int i = ty; i < 32; i += 8) {
        float val = t[tx][i];
        __nv_bfloat16 h, l;
        split1(val, h, l);
        size_t off = dbase + (size_t)(n0 + i) * C_IN + c0 + tx;
        g_xT_hi[off] = h;
        g_xT_lo[off] = l;
    }
}

// ---------------- proj: D[n=128][o 256-tile], 2-buffer, 2 CTAs/SM -----------
// grid (8, 3, BATCH): n0 = x*128, o0 = y*256, NN = (y<2)?256:128
// buffer (48KB): AHI 8K | ALO 8K | BHI 16K | BLO 16K ; 2 buffers = 96KB
__global__ void __launch_bounds__(256, 2) proj_mma() {
#if USE_TCGEN05
    extern __shared__ char dyn[];
    __shared__ uint32_t s_tmem;
    __shared__ uint64_t s_mb[2];
    __shared__ float s_bias[256];

    int tid = threadIdx.x, wid = tid >> 5, lane = tid & 31;
    int b = blockIdx.z, n0 = blockIdx.x * 128, y = blockIdx.y;
    int o0 = y * 256;
    int NN = (y < 2) ? 256 : 128;
    uint32_t idesc = IDESC(NN);

    uint32_t dynb = (cvta_smem(dyn) + 1023u) & ~1023u;
    uint32_t mb0 = cvta_smem(&s_mb[0]), mb1 = cvta_smem(&s_mb[1]);

    if (wid == 0) { TC_ALLOC(cvta_smem(&s_tmem), 256); TC_RELINQ(); }
    if (tid == 0) { MB_INIT(mb0, 1); MB_INIT(mb1, 1); }
    for (int i = tid; i < NN; i += 256) s_bias[i] = g_bias[o0 + i];
    __syncthreads();
    uint32_t tmem = s_tmem;

    const __nv_bfloat16* Ah = g_xT_hi + ((size_t)b * N_TOK + n0) * C_IN;
    const __nv_bfloat16* Al = g_xT_lo + ((size_t)b * N_TOK + n0) * C_IN;
    const __nv_bfloat16* Bh = g_Wn_hi + (size_t)o0 * C_IN;
    const __nv_bfloat16* Bl = g_Wn_lo + (size_t)o0 * C_IN;

    int ph0 = 0, ph1 = 0;
    const int KT = C_IN / 32;   // 16
    for (int kt = 0; kt < KT; kt++) {
        int p = kt & 1;
        if (kt >= 2) {
            if (p == 0) { MB_WAIT(mb0, ph0); ph0 ^= 1; }
            else        { MB_WAIT(mb1, ph1); ph1 ^= 1; }
        }
        uint32_t base = dynb + (uint32_t)p * 49152u;
        int k0 = kt * 32;
        copy_rows64(Ah, C_IN, k0, base, 128, tid);
        copy_rows64(Al, C_IN, k0, base + 8192u, 128, tid);
        copy_rows64(Bh, C_IN, k0, base + 16384u, NN, tid);
        copy_rows64(Bl, C_IN, k0, base + 32768u, NN, tid);
        CP_COMMIT();
        CP_WAIT0();
        __syncthreads();
        if (wid == 0 && elect_one()) {
            FENCE_ASYNC();
            issue_chunk32(tmem, base, base + 8192u, base + 16384u, base + 32768u, idesc, kt == 0);
            TC_COMMIT(p == 0 ? mb0 : mb1);
        }
    }
    MB_WAIT(mb0, ph0);
    MB_WAIT(mb1, ph1);
    TC_FENCE_AFTER();
    __syncthreads();

    float* tb = (float*)dyn;   // reuse pipeline buffers for transpose staging
    for (int c0 = 0; c0 < NN; c0 += 32) {
        int oc0 = o0 + c0;
        bool dir = oc0 < 128;
        if (tid < 128) {
            uint32_t r[32];
            LDTM32(r, tmem + c0);
            TC_WAIT_LD();
            if (dir) {
                int n = n0 + wid * 32 + lane;
                int oo = (oc0 < 64) ? oc0 : (oc0 - 64);
                uint32_t* hi = (uint32_t*)((oc0 < 64) ? g_qT_hi : g_kT_hi) + ((size_t)b * N_TOK + n) * 32;
                uint32_t* lo = (uint32_t*)((oc0 < 64) ? g_qT_lo : g_kT_lo) + ((size_t)b * N_TOK + n) * 32;
#pragma unroll
                for (int j = 0; j < 32; j += 4) {
                    uint32_t h0, l0, h1, l1;
                    pack_split2(__uint_as_float(r[j + 0]) + s_bias[c0 + j + 0],
                                __uint_as_float(r[j + 1]) + s_bias[c0 + j + 1], h0, l0);
                    pack_split2(__uint_as_float(r[j + 2]) + s_bias[c0 + j + 2],
                                __uint_as_float(r[j + 3]) + s_bias[c0 + j + 3], h1, l1);
                    *(uint2*)(hi + ((oo + j) >> 1)) = make_uint2(h0, h1);
                    *(uint2*)(lo + ((oo + j) >> 1)) = make_uint2(l0, l1);
                }
            } else {
                int cb = wid * 1056 + lane * 33;
#pragma unroll
                for (int j = 0; j < 32; j++) tb[cb + j] = __uint_as_float(r[j]);
            }
        }
        if (!dir) {
            __syncthreads();
            int cg = oc0 - 128;
#pragma unroll
            for (int i = 0; i < 16; i++) {
                int rid = wid * 16 + i;
                int wsrc = rid >> 5, j = rid & 31;
                float val = tb[wsrc * 1056 + lane * 33 + j] + s_bias[c0 + j];
                __nv_bfloat16 h, l;
                split1(val, h, l);
                size_t off = ((size_t)b * C_IN + cg + j) * N_TOK + n0 + wsrc * 32 + lane;
                g_v_hi[off] = h;
                g_v_lo[off] = l;
            }
            __syncthreads();
        }
    }
    __syncthreads();
    if (wid == 0) TC_DEALLOC(tmem, 256);
#else
    int tid = threadIdx.x;
    int b = blockIdx.z, n0 = blockIdx.x * 128, y = blockIdx.y, o0 = y * 256;
    int NN = (y < 2) ? 256 : 128;
    for (int e = tid; e < 128 * NN; e += 256) {
        int n = n0 + (e & 127);
        int oc = o0 + (e >> 7);
        const __nv_bfloat16* xh = g_xT_hi + ((size_t)b * N_TOK + n) * C_IN;
        const __nv_bfloat16* xl = g_xT_lo + ((size_t)b * N_TOK + n) * C_IN;
        const __nv_bfloat16* wh = g_Wn_hi + (size_t)oc * C_IN;
        const __nv_bfloat16* wl = g_Wn_lo + (size_t)oc * C_IN;
        float s = 0.f;
        for (int c = 0; c < C_IN; c++) {
            float xa = __bfloat162float(xh[c]) + __bfloat162float(xl[c]);
            float wa = __bfloat162float(wh[c]) + __bfloat162float(wl[c]);
            s += xa * wa;
        }
        s += g_bias[oc];
        __nv_bfloat16 h, l;
        split1(s, h, l);
        if (oc < 64)       { size_t o = ((size_t)b * N_TOK + n) * CQ + oc;        g_qT_hi[o] = h; g_qT_lo[o] = l; }
        else if (oc < 128) { size_t o = ((size_t)b * N_TOK + n) * CQ + (oc - 64); g_kT_hi[o] = h; g_kT_lo[o] = l; }
        else               { size_t o = ((size_t)b * C_IN + (oc - 128)) * N_TOK + n; g_v_hi[o] = h; g_v_lo[o] = l; }
    }
#endif
}

// ---------------- qks: fused QK^T + exp + row-sum -----------------------------
// grid (8, BATCH): m0 = x*128. Two halves of n (512 each): D[m=128][n=512] in TMEM,
// epilogue applies exp (no max-subtract), writes unnormalized P hi/lo + row sums.
__global__ void __launch_bounds__(256) qks_mma() {
#if USE_TCGEN05
    extern __shared__ char dyn[];
    __shared__ uint32_t s_tmem;
    __shared__ uint64_t s_mb[2];

    int tid = threadIdx.x, wid = tid >> 5, lane = tid & 31;
    int b = blockIdx.y, m0 = blockIdx.x * 128;
    uint32_t idesc = IDESC(256);

    uint32_t dynb = (cvta_smem(dyn) + 1023u) & ~1023u;
    uint32_t AHI = dynb, ALO = dynb + 16384u, BHI = dynb + 32768u, BLO = dynb + 98304u;
    uint32_t mb0 = cvta_smem(&s_mb[0]), mb1 = cvta_smem(&s_mb[1]);

    if (wid == 0) { TC_ALLOC(cvta_smem(&s_tmem), 512); TC_RELINQ(); }
    if (tid == 0) { MB_INIT(mb0, 1); MB_INIT(mb1, 1); }
    __syncthreads();
    uint32_t tmem = s_tmem;

    const __nv_bfloat16* Kh = g_kT_hi + ((size_t)b * N_TOK + m0) * CQ;
    const __nv_bfloat16* Kl = g_kT_lo + ((size_t)b * N_TOK + m0) * CQ;
    const __nv_bfloat16* Qh = g_qT_hi + (size_t)b * N_TOK * CQ;
    const __nv_bfloat16* Ql = g_qT_lo + (size_t)b * N_TOK * CQ;

    copy_rows(Kh, CQ, 0, AHI, 128, tid);
    copy_rows(Kl, CQ, 0, ALO, 128, tid);
    copy_rows(Qh, CQ, 0, BHI, 512, tid);
    copy_rows(Ql, CQ, 0, BLO, 512, tid);
    CP_COMMIT();
    CP_WAIT0();
    __syncthreads();
    if (wid == 0 && elect_one()) {
        FENCE_ASYNC();
        issue_qks(tmem, AHI, ALO, BHI, BLO, idesc);
        TC_COMMIT(mb0);
    }
    MB_WAIT(mb0, 0);
    TC_FENCE_AFTER();

    copy_rows(Qh + (size_t)512 * CQ, CQ, 0, BHI, 512, tid);
    copy_rows(Ql + (size_t)512 * CQ, CQ, 0, BLO, 512, tid);
    CP_COMMIT();

    float rsum = 0.f;
    int m = m0 + wid * 32 + lane;
    uint32_t* Ph = (uint32_t*)g_P_hi + ((size_t)b * N_TOK + m) * 512;
    uint32_t* Pl = (uint32_t*)g_P_lo + ((size_t)b * N_TOK + m) * 512;

    if (tid < 128) {
        for (int c0 = 0; c0 < 512; c0 += 32) {
            uint32_t r[32];
            LDTM32(r, tmem + c0);
            TC_WAIT_LD();
            uint32_t hb[16], lb[16];
#pragma unroll
            for (int j = 0; j < 32; j += 2) {
                float e0 = __expf(__uint_as_float(r[j]));
                float e1 = __expf(__uint_as_float(r[j + 1]));
                rsum += e0 + e1;
                pack_split2(e0, e1, hb[j >> 1], lb[j >> 1]);
            }
            int base = c0 >> 1;
#pragma unroll
            for (int q = 0; q < 4; q++) {
                *(uint4*)(Ph + base + q * 4) = make_uint4(hb[q*4], hb[q*4+1], hb[q*4+2], hb[q*4+3]);
                *(uint4*)(Pl + base + q * 4) = make_uint4(lb[q*4], lb[q*4+1], lb[q*4+2], lb[q*4+3]);
            }
        }
    }
    TC_FENCE_BEFORE();
    CP_WAIT0();
    __syncthreads();
    if (wid == 0 && elect_one()) {
        FENCE_ASYNC();
        TC_FENCE_AFTER();
        issue_qks(tmem, AHI, ALO, BHI, BLO, idesc);
        TC_COMMIT(mb1);
    }
    MB_WAIT(mb1, 0);
    TC_FENCE_AFTER();

    if (tid < 128) {
        for (int c0 = 0; c0 < 512; c0 += 32) {
            uint32_t r[32];
            LDTM32(r, tmem + c0);
            TC_WAIT_LD();
            uint32_t hb[16], lb[16];
#pragma unroll
            for (int j = 0; j < 32; j += 2) {
                float e0 = __expf(__uint_as_float(r[j]));
                float e1 = __expf(__uint_as_float(r[j + 1]));
                rsum += e0 + e1;
                pack_split2(e0, e1, hb[j >> 1], lb[j >> 1]);
            }
            int base = 256 + (c0 >> 1);
#pragma unroll
            for (int q = 0; q < 4; q++) {
                *(uint4*)(Ph + base + q * 4) = make_uint4(hb[q*4], hb[q*4+1], hb[q*4+2], hb[q*4+3]);
                *(uint4*)(Pl + base + q * 4) = make_uint4(lb[q*4], lb[q*4+1], lb[q*4+2], lb[q*4+3]);
            }
        }
        g_rsum[(size_t)b * N_TOK + m] = rsum;
    }
    __syncthreads();
    if (wid == 0) TC_DEALLOC(tmem, 512);
#else
    int tid = threadIdx.x;
    int b = blockIdx.y, m0 = blockIdx.x * 128;
    if (tid < 128) {
        int m = m0 + tid;
        const __nv_bfloat16* kh = g_kT_hi + ((size_t)b * N_TOK + m) * CQ;
        const __nv_bfloat16* kl = g_kT_lo + ((size_t)b * N_TOK + m) * CQ;
        float rsum = 0.f;
        for (int n = 0; n < N_TOK; n++) {
            const __nv_bfloat16* qh = g_qT_hi + ((size_t)b * N_TOK + n) * CQ;
            const __nv_bfloat16* ql = g_qT_lo + ((size_t)b * N_TOK + n) * CQ;
            float s = 0.f;
            for (int o = 0; o < CQ; o++)
                s += (__bfloat162float(qh[o]) + __bfloat162float(ql[o])) *
                     (__bfloat162float(kh[o]) + __bfloat162float(kl[o]));
            float e = __expf(s);
            rsum += e;
            __nv_bfloat16 h, l;
            split1(e, h, l);
            size_t off = ((size_t)b * N_TOK + m) * N_TOK + n;
            g_P_hi[off] = h;
            g_P_lo[off] = l;
        }
        g_rsum[(size_t)b * N_TOK + m] = rsum;
    }
#endif
}

// ---------------- av: D[m=128][c=256], 2-buffer, 2 CTAs/SM ------------------
// grid (8, 2, BATCH): m0 = x*128, c0g = y*256
__global__ void __launch_bounds__(256, 2) av_mma(const float* __restrict__ x,
                                                 const float* __restrict__ gamma_p,
                                                 float* __restrict__ out) {
#if USE_TCGEN05
    extern __shared__ char dyn[];
    __shared__ uint32_t s_tmem;
    __shared__ uint64_t s_mb[2];

    int tid = threadIdx.x, wid = tid >> 5, lane = tid & 31;
    int b = blockIdx.z, m0 = blockIdx.x * 128, c0g = blockIdx.y * 256;
    uint32_t idesc = IDESC(256);

    uint32_t dynb = (cvta_smem(dyn) + 1023u) & ~1023u;
    uint32_t mb0 = cvta_smem(&s_mb[0]), mb1 = cvta_smem(&s_mb[1]);

    if (wid == 0) { TC_ALLOC(cvta_smem(&s_tmem), 256); TC_RELINQ(); }
    if (tid == 0) { MB_INIT(mb0, 1); MB_INIT(mb1, 1); }
    __syncthreads();
    uint32_t tmem = s_tmem;

    const __nv_bfloat16* Ah = g_P_hi + ((size_t)b * N_TOK + m0) * N_TOK;
    const __nv_bfloat16* Al = g_P_lo + ((size_t)b * N_TOK + m0) * N_TOK;
    const __nv_bfloat16* Bh = g_v_hi + ((size_t)b * C_IN + c0g) * N_TOK;
    const __nv_bfloat16* Bl = g_v_lo + ((size_t)b * C_IN + c0g) * N_TOK;

    int ph0 = 0, ph1 = 0;
    const int KT = N_TOK / 32;   // 32
    for (int kt = 0; kt < KT; kt++) {
        int p = kt & 1;
        if (kt >= 2) {
            if (p == 0) { MB_WAIT(mb0, ph0); ph0 ^= 1; }
            else        { MB_WAIT(mb1, ph1); ph1 ^= 1; }
        }
        uint32_t base = dynb + (uint32_t)p * 49152u;
        int k0 = kt * 32;
        copy_rows64(Ah, N_TOK, k0, base, 128, tid);
        copy_rows64(Al, N_TOK, k0, base + 8192u, 128, tid);
        copy_rows64(Bh, N_TOK, k0, base + 16384u, 256, tid);
        copy_rows64(Bl, N_TOK, k0, base + 32768u, 256, tid);
        CP_COMMIT();
        CP_WAIT0();
        __syncthreads();
        if (wid == 0 && elect_one()) {
            FENCE_ASYNC();
            issue_chunk32(tmem, base, base + 8192u, base + 16384u, base + 32768u, idesc, kt == 0);
            TC_COMMIT(p == 0 ? mb0 : mb1);
        }
    }
    MB_WAIT(mb0, ph0);
    MB_WAIT(mb1, ph1);
    TC_FENCE_AFTER();

    float g = *gamma_p;
    int m = m0 + wid * 32 + lane;
    float ginv = (tid < 128) ? (g / g_rsum[(size_t)b * N_TOK + m]) : 0.f;
    for (int c0 = 0; c0 < 256; c0 += 32) {
        if (tid < 128) {
            uint32_t r[32];
            LDTM32(r, tmem + c0);
            TC_WAIT_LD();
#pragma unroll
            for (int j = 0; j < 32; j++) {
                int c = c0g + c0 + j;
                size_t off = ((size_t)b * C_IN + c) * N_TOK + m;
                out[off] = ginv * __uint_as_float(r[j]) + x[off];
            }
        }
    }
    __syncthreads();
    if (wid == 0) TC_DEALLOC(tmem, 256);
#else
    int tid = threadIdx.x;
    int b = blockIdx.z, m0 = blockIdx.x * 128, c0g = blockIdx.y * 256;
    float g = *gamma_p;
    for (int e = tid; e < 128 * 256; e += 256) {
        int m = m0 + (e & 127);
        int c = c0g + (e >> 7);
        const __nv_bfloat16* vh = g_v_hi + ((size_t)b * C_IN + c) * N_TOK;
        const __nv_bfloat16* vl = g_v_lo + ((size_t)b * C_IN + c) * N_TOK;
        const __nv_bfloat16* ph = g_P_hi + ((size_t)b * N_TOK + m) * N_TOK;
        const __nv_bfloat16* pl = g_P_lo + ((size_t)b * N_TOK + m) * N_TOK;
        float s = 0.f;
        for (int n = 0; n < N_TOK; n++)
            s += (__bfloat162float(vh[n]) + __bfloat162float(vl[n])) *
                 (__bfloat162float(ph[n]) + __bfloat162float(pl[n]));
        size_t off = ((size_t)b * C_IN + c) * N_TOK + m;
        out[off] = g * s / g_rsum[(size_t)b * N_TOK + m] + x[off];
    }
#endif
}

// ---------------- launch -----------------------------------------------------
extern "C" void kernel_launch(void* const* d_in, const int* in_sizes, int n_in,
                              void* d_out, int out_size) {
    const float* x     = (const float*)d_in[0];
    const float* Wq    = (const float*)d_in[1];
    const float* bq    = (const float*)d_in[2];
    const float* uq    = (const float*)d_in[3];
    const float* Wk    = (const float*)d_in[4];
    const float* bk    = (const float*)d_in[5];
    const float* uk    = (const float*)d_in[6];
    const float* Wv    = (const float*)d_in[7];
    const float* bv    = (const float*)d_in[8];
    const float* uv    = (const float*)d_in[9];
    const float* gamma = (const float*)d_in[10];
    float* out = (float*)d_out;

    cudaFuncSetAttribute(proj_mma, cudaFuncAttributeMaxDynamicSharedMemorySize, 99328);
    cudaFuncSetAttribute(qks_mma,  cudaFuncAttributeMaxDynamicSharedMemorySize, 164864);
    cudaFuncSetAttribute(av_mma,   cudaFuncAttributeMaxDynamicSharedMemorySize, 99328);

    sn_kernel<<<3, 512>>>(Wq, uq, bq, Wk, uk, bk, Wv, uv, bv);
    transpose_kernel<<<dim3(32, 16, BATCH), dim3(32, 8)>>>(x);
    proj_mma<<<dim3(8, 3, BATCH), 256, 99328>>>();
    qks_mma<<<dim3(8, BATCH), 256, 164864>>>();
    av_mma<<<dim3(8, 2, BATCH), 256, 99328>>>(x, gamma, out);
}

// round 13
// speedup vs baseline: 1.9485x; 1.0636x over previous
#include <cuda_runtime.h>
#include <cuda_bf16.h>
#include <math.h>
#include <stdint.h>

#define N_TOK 1024
#define C_IN  512
#define CQ    64
#define BATCH 32

#if defined(__CUDA_ARCH__)
#if defined(__CUDA_ARCH_FEAT_SM103_ALL)
#define USE_TCGEN05 1
#else
#define USE_TCGEN05 0
#endif
#else
#define USE_TCGEN05 0
#endif

// ---------------- scratch (device globals; no allocation allowed) ----------
__device__ __align__(128) __nv_bfloat16 g_Wn_hi[640 * C_IN];   // rows: q 0-63, k 64-127, v 128-639 (K-major)
__device__ __align__(128) __nv_bfloat16 g_Wn_lo[640 * C_IN];
__device__ __align__(128) float g_bias[640];
__device__ __align__(128) __nv_bfloat16 g_xT_hi[(size_t)BATCH * N_TOK * C_IN];  // [b][n][c]
__device__ __align__(128) __nv_bfloat16 g_xT_lo[(size_t)BATCH * N_TOK * C_IN];
__device__ __align__(128) __nv_bfloat16 g_qT_hi[(size_t)BATCH * N_TOK * CQ];    // [b][n][o]
__device__ __align__(128) __nv_bfloat16 g_qT_lo[(size_t)BATCH * N_TOK * CQ];
__device__ __align__(128) __nv_bfloat16 g_kT_hi[(size_t)BATCH * N_TOK * CQ];    // [b][m][o]
__device__ __align__(128) __nv_bfloat16 g_kT_lo[(size_t)BATCH * N_TOK * CQ];
__device__ __align__(128) __nv_bfloat16 g_v_hi [(size_t)BATCH * C_IN * N_TOK];  // [b][c][n]
__device__ __align__(128) __nv_bfloat16 g_v_lo [(size_t)BATCH * C_IN * N_TOK];
__device__ __align__(128) __nv_bfloat16 g_P    [(size_t)BATCH * N_TOK * N_TOK]; // [b][m][n] unnormalized exp(S), bf16
__device__ __align__(128) float         g_rsum [(size_t)BATCH * N_TOK];         // [b][m] row sums

// ---------------- common helpers --------------------------------------------
__device__ __forceinline__ uint32_t cvta_smem(const void* p) {
    uint32_t a;
    asm("{ .reg .u64 t; cvta.to.shared.u64 t, %1; cvt.u32.u64 %0, t; }" : "=r"(a) : "l"(p));
    return a;
}
__device__ __forceinline__ void pack_split2(float a, float b, uint32_t& h, uint32_t& l) {
    __nv_bfloat16 ah = __float2bfloat16(a);
    __nv_bfloat16 bh = __float2bfloat16(b);
    __nv_bfloat16 al = __float2bfloat16(a - __bfloat162float(ah));
    __nv_bfloat16 bl = __float2bfloat16(b - __bfloat162float(bh));
    h = (uint32_t)__bfloat16_as_ushort(ah) | ((uint32_t)__bfloat16_as_ushort(bh) << 16);
    l = (uint32_t)__bfloat16_as_ushort(al) | ((uint32_t)__bfloat16_as_ushort(bl) << 16);
}
__device__ __forceinline__ uint32_t pack_bf2(float a, float b) {
    return (uint32_t)__bfloat16_as_ushort(__float2bfloat16(a)) |
           ((uint32_t)__bfloat16_as_ushort(__float2bfloat16(b)) << 16);
}
__device__ __forceinline__ void split1(float v, __nv_bfloat16& h, __nv_bfloat16& l) {
    h = __float2bfloat16(v);
    l = __float2bfloat16(v - __bfloat162float(h));
}

#if USE_TCGEN05
__device__ __forceinline__ int elect_one() {
    uint32_t pred;
    asm volatile("{\n\t.reg .pred p;\n\telect.sync _|p, 0xFFFFFFFF;\n\tselp.b32 %0, 1, 0, p;\n\t}" : "=r"(pred));
    return (int)pred;
}
#define MB_INIT(addr, cnt) \
    asm volatile("mbarrier.init.shared.b64 [%0], %1;" :: "r"(addr), "r"((uint32_t)(cnt)) : "memory")
#define MB_WAIT(addr, phv) do { \
    uint32_t _m = (addr), _p = (uint32_t)(phv), _d; \
    asm volatile("{\n\t.reg .pred p;\n\t" \
        "mbarrier.try_wait.parity.acquire.cta.shared::cta.b64 p, [%1], %2;\n\t" \
        "selp.b32 %0,1,0,p;\n\t}" : "=r"(_d) : "r"(_m), "r"(_p) : "memory"); \
    while (!_d) { \
        asm volatile("{\n\t.reg .pred p;\n\t" \
            "mbarrier.try_wait.parity.acquire.cta.shared::cta.b64 p, [%1], %2, 0x989680;\n\t" \
            "selp.b32 %0,1,0,p;\n\t}" : "=r"(_d) : "r"(_m), "r"(_p) : "memory"); \
    } \
} while (0)
#define TC_ALLOC(addr, n) \
    asm volatile("tcgen05.alloc.cta_group::1.sync.aligned.shared::cta.b32 [%0], %1;" :: "r"(addr), "r"((uint32_t)(n)) : "memory")
#define TC_RELINQ() \
    asm volatile("tcgen05.relinquish_alloc_permit.cta_group::1.sync.aligned;")
#define TC_DEALLOC(tm, n) \
    asm volatile("tcgen05.dealloc.cta_group::1.sync.aligned.b32 %0, %1;" :: "r"(tm), "r"((uint32_t)(n)))
#define TC_COMMIT(addr) \
    asm volatile("tcgen05.commit.cta_group::1.mbarrier::arrive::one.shared::cluster.b64 [%0];" :: "r"(addr) : "memory")
#define TC_FENCE_AFTER()   asm volatile("tcgen05.fence::after_thread_sync;" ::: "memory")
#define TC_FENCE_BEFORE()  asm volatile("tcgen05.fence::before_thread_sync;" ::: "memory")
#define TC_WAIT_LD()       asm volatile("tcgen05.wait::ld.sync.aligned;" ::: "memory")
#define FENCE_ASYNC()      asm volatile("fence.proxy.async.shared::cta;" ::: "memory")
#define CP16(dst, src)  asm volatile("cp.async.cg.shared.global [%0], [%1], 16;" :: "r"(dst), "l"(src) : "memory")
#define CP_COMMIT()     asm volatile("cp.async.commit_group;" ::: "memory")
#define CP_WAIT0()      asm volatile("cp.async.wait_group 0;" ::: "memory")

#define LDTM32(r, tma) \
    asm volatile("tcgen05.ld.sync.aligned.32x32b.x32.b32 " \
        "{%0,%1,%2,%3,%4,%5,%6,%7,%8,%9,%10,%11,%12,%13,%14,%15," \
        "%16,%17,%18,%19,%20,%21,%22,%23,%24,%25,%26,%27,%28,%29,%30,%31}, [%32];" \
        : "=r"((r)[0]),"=r"((r)[1]),"=r"((r)[2]),"=r"((r)[3]),"=r"((r)[4]),"=r"((r)[5]),"=r"((r)[6]),"=r"((r)[7]), \
          "=r"((r)[8]),"=r"((r)[9]),"=r"((r)[10]),"=r"((r)[11]),"=r"((r)[12]),"=r"((r)[13]),"=r"((r)[14]),"=r"((r)[15]), \
          "=r"((r)[16]),"=r"((r)[17]),"=r"((r)[18]),"=r"((r)[19]),"=r"((r)[20]),"=r"((r)[21]),"=r"((r)[22]),"=r"((r)[23]), \
          "=r"((r)[24]),"=r"((r)[25]),"=r"((r)[26]),"=r"((r)[27]),"=r"((r)[28]),"=r"((r)[29]),"=r"((r)[30]),"=r"((r)[31]) \
        : "r"(tma))

// SW128 desc (128B rows): layout 2, version 1, SBO=64, LBO=1
__device__ __forceinline__ uint64_t smem_desc(uint32_t addr) {
    return 0x4000404000010000ULL | (uint64_t)((addr >> 4) & 0x3FFF);
}
// SW64 desc (64B rows): layout 4, version 1, SBO=32, LBO=1
__device__ __forceinline__ uint64_t smem_desc64(uint32_t addr) {
    return 0x8000402000010000ULL | (uint64_t)((addr >> 4) & 0x3FFF);
}
__device__ __forceinline__ void mma_bf16_ss(uint32_t d, uint64_t ad, uint64_t bd,
                                            uint32_t idesc, uint32_t en) {
    asm volatile(
        "{\n\t.reg .pred p;\n\tsetp.ne.u32 p, %4, 0;\n\t"
        "tcgen05.mma.cta_group::1.kind::f16 [%0], %1, %2, %3, {%5,%5,%5,%5}, p;\n\t}"
        :: "r"(d), "l"(ad), "l"(bd), "r"(idesc), "r"(en), "r"(0u) : "memory");
}
#define IDESC(NN) (0x8000490u | ((uint32_t)((NN) / 8) << 17))

// ---- SW128 (128B rows, K-chunk 64) copy ----
__device__ __forceinline__ void copy_rows(const __nv_bfloat16* __restrict__ src,
                                          int stride, int k0, uint32_t dst,
                                          int rows, int tid) {
    for (int s = tid; s < rows * 8; s += 256) {
        int r = s >> 3, seg = s & 7;
        const char* sp = (const char*)(src + (size_t)r * stride + k0) + seg * 16;
        uint32_t off = (uint32_t)(r * 128 + seg * 16);
        uint32_t sw = off ^ ((off >> 3) & 0x70u);
        CP16(dst + sw, sp);
    }
}
// ---- SW64 (64B rows, K-chunk 32) copy ----
__device__ __forceinline__ void copy_rows64(const __nv_bfloat16* __restrict__ src,
                                            int stride, int k0, uint32_t dst,
                                            int rows, int tid) {
    for (int s = tid; s < rows * 4; s += 256) {
        int r = s >> 2, seg = s & 3;
        const char* sp = (const char*)(src + (size_t)r * stride + k0) + seg * 16;
        uint32_t off = (uint32_t)(r * 64 + seg * 16);
        uint32_t sw = off ^ ((off >> 3) & 0x30u);
        CP16(dst + sw, sp);
    }
}

// SW64 chunk (K=32): 3 products x 2 K-steps (proj)
__device__ __forceinline__ void issue_chunk32(uint32_t d, uint32_t ahi, uint32_t alo,
                                              uint32_t bhi, uint32_t blo,
                                              uint32_t idesc, bool first) {
    uint64_t AH = smem_desc64(ahi), AL = smem_desc64(alo);
    uint64_t BH = smem_desc64(bhi), BL = smem_desc64(blo);
#pragma unroll
    for (int ks = 0; ks < 2; ks++) mma_bf16_ss(d, AH + 2 * ks, BH + 2 * ks, idesc, (first && ks == 0) ? 0u : 1u);
#pragma unroll
    for (int ks = 0; ks < 2; ks++) mma_bf16_ss(d, AH + 2 * ks, BL + 2 * ks, idesc, 1u);
#pragma unroll
    for (int ks = 0; ks < 2; ks++) mma_bf16_ss(d, AL + 2 * ks, BH + 2 * ks, idesc, 1u);
}

// SW64 chunk (K=32): 2 products (A plain bf16, B split) — av
__device__ __forceinline__ void issue_av32(uint32_t d, uint32_t a,
                                           uint32_t bhi, uint32_t blo,
                                           uint32_t idesc, bool first) {
    uint64_t A = smem_desc64(a);
    uint64_t BH = smem_desc64(bhi), BL = smem_desc64(blo);
#pragma unroll
    for (int ks = 0; ks < 2; ks++) mma_bf16_ss(d, A + 2 * ks, BH + 2 * ks, idesc, (first && ks == 0) ? 0u : 1u);
#pragma unroll
    for (int ks = 0; ks < 2; ks++) mma_bf16_ss(d, A + 2 * ks, BL + 2 * ks, idesc, 1u);
}

// qks: one K=64 shot across N=512 (2 x N=256 tiles), D cols 0..511
__device__ __forceinline__ void issue_qks(uint32_t tmem, uint32_t ahi, uint32_t alo,
                                          uint32_t bhi, uint32_t blo, uint32_t idesc) {
    uint64_t AH = smem_desc(ahi), AL = smem_desc(alo);
#pragma unroll
    for (int nt = 0; nt < 2; nt++) {
        uint64_t BH = smem_desc(bhi + (uint32_t)nt * 32768u);
        uint64_t BL = smem_desc(blo + (uint32_t)nt * 32768u);
        uint32_t d = tmem + (uint32_t)nt * 256u;
#pragma unroll
        for (int ks = 0; ks < 4; ks++) mma_bf16_ss(d, AH + 2 * ks, BH + 2 * ks, idesc, ks == 0 ? 0u : 1u);
#pragma unroll
        for (int ks = 0; ks < 4; ks++) mma_bf16_ss(d, AH + 2 * ks, BL + 2 * ks, idesc, 1u);
#pragma unroll
        for (int ks = 0; ks < 4; ks++) mma_bf16_ss(d, AL + 2 * ks, BH + 2 * ks, idesc, 1u);
    }
}
#endif  // USE_TCGEN05

// ---------------- spectral norm ---------------------------------------------
__global__ void sn_kernel(const float* __restrict__ Wq, const float* __restrict__ uq, const float* __restrict__ bq,
                          const float* __restrict__ Wk, const float* __restrict__ uk, const float* __restrict__ bk,
                          const float* __restrict__ Wv, const float* __restrict__ uv, const float* __restrict__ bv) {
    const float* W; const float* u; const float* bias; int out; int dst;
    if (blockIdx.x == 0)      { W = Wq; u = uq; bias = bq; out = CQ;   dst = 0;   }
    else if (blockIdx.x == 1) { W = Wk; u = uk; bias = bk; out = CQ;   dst = 64;  }
    else                      { W = Wv; u = uv; bias = bv; out = C_IN; dst = 128; }

    __shared__ float su[C_IN];
    __shared__ float sv[C_IN];
    __shared__ float red[512];
    int tid = threadIdx.x;

    if (tid < out) { su[tid] = u[tid]; g_bias[dst + tid] = bias[tid]; }
    __syncthreads();

    float t = 0.f;
    for (int i = 0; i < out; i++) t += W[i * C_IN + tid] * su[i];
    red[tid] = t * t;
    __syncthreads();
    for (int s = 256; s > 0; s >>= 1) { if (tid < s) red[tid] += red[tid + s]; __syncthreads(); }
    float nv = sqrtf(red[0]);
    sv[tid] = t / nv;
    __syncthreads();

    float p = 0.f;
    for (int i = tid; i < out; i += blockDim.x) {
        float r = 0.f;
        for (int j = 0; j < C_IN; j++) r += W[i * C_IN + j] * sv[j];
        p += r * r;
    }
    red[tid] = p;
    __syncthreads();
    for (int s = 256; s > 0; s >>= 1) { if (tid < s) red[tid] += red[tid + s]; __syncthreads(); }
    float inv_sigma = rsqrtf(red[0]);

    for (int e = tid; e < out * C_IN; e += blockDim.x) {
        float val = W[e] * inv_sigma;
        __nv_bfloat16 h, l;
        split1(val, h, l);
        g_Wn_hi[(size_t)dst * C_IN + e] = h;
        g_Wn_lo[(size_t)dst * C_IN + e] = l;
    }
}

// ---------------- x transpose + split ----------------------------------------
__global__ void transpose_kernel(const float* __restrict__ x) {
    __shared__ float t[32][33];
    int b = blockIdx.z, c0 = blockIdx.y * 32, n0 = blockIdx.x * 32;
    int tx = threadIdx.x, ty = threadIdx.y;
    const float* src = x + (size_t)b * C_IN * N_TOK;
    size_t dbase = (size_t)b * N_TOK * C_IN;
#pragma unroll
    for (int i = ty; i < 32; i += 8) t[i][tx] = src[(size_t)(c0 + i) * N_TOK + n0 + tx];
    __syncthreads();
#pragma unroll
    for (int i = ty; i < 32; i += 8) {
        float val = t[tx][i];
        __nv_bfloat16 h, l;
        split1(val, h, l);
        size_t off = dbase + (size_t)(n0 + i) * C_IN + c0 + tx;
        g_xT_hi[off] = h;
        g_xT_lo[off] = l;
    }
}

// ---------------- proj: D[n=128][o 256-tile], 2-buffer, 2 CTAs/SM -----------
// grid (8, 3, BATCH): n0 = x*128, o0 = y*256, NN = (y<2)?256:128
__global__ void __launch_bounds__(256, 2) proj_mma() {
#if USE_TCGEN05
    extern __shared__ char dyn[];
    __shared__ uint32_t s_tmem;
    __shared__ uint64_t s_mb[2];
    __shared__ float s_bias[256];

    int tid = threadIdx.x, wid = tid >> 5, lane = tid & 31;
    int b = blockIdx.z, n0 = blockIdx.x * 128, y = blockIdx.y;
    int o0 = y * 256;
    int NN = (y < 2) ? 256 : 128;
    uint32_t idesc = IDESC(NN);

    uint32_t dynb = (cvta_smem(dyn) + 1023u) & ~1023u;
    uint32_t mb0 = cvta_smem(&s_mb[0]), mb1 = cvta_smem(&s_mb[1]);

    if (wid == 0) { TC_ALLOC(cvta_smem(&s_tmem), 256); TC_RELINQ(); }
    if (tid == 0) { MB_INIT(mb0, 1); MB_INIT(mb1, 1); }
    for (int i = tid; i < NN; i += 256) s_bias[i] = g_bias[o0 + i];
    __syncthreads();
    uint32_t tmem = s_tmem;

    const __nv_bfloat16* Ah = g_xT_hi + ((size_t)b * N_TOK + n0) * C_IN;
    const __nv_bfloat16* Al = g_xT_lo + ((size_t)b * N_TOK + n0) * C_IN;
    const __nv_bfloat16* Bh = g_Wn_hi + (size_t)o0 * C_IN;
    const __nv_bfloat16* Bl = g_Wn_lo + (size_t)o0 * C_IN;

    int ph0 = 0, ph1 = 0;
    const int KT = C_IN / 32;   // 16
    for (int kt = 0; kt < KT; kt++) {
        int p = kt & 1;
        if (kt >= 2) {
            if (p == 0) { MB_WAIT(mb0, ph0); ph0 ^= 1; }
            else        { MB_WAIT(mb1, ph1); ph1 ^= 1; }
        }
        uint32_t base = dynb + (uint32_t)p * 49152u;
        int k0 = kt * 32;
        copy_rows64(Ah, C_IN, k0, base, 128, tid);
        copy_rows64(Al, C_IN, k0, base + 8192u, 128, tid);
        copy_rows64(Bh, C_IN, k0, base + 16384u, NN, tid);
        copy_rows64(Bl, C_IN, k0, base + 32768u, NN, tid);
        CP_COMMIT();
        CP_WAIT0();
        __syncthreads();
        if (wid == 0 && elect_one()) {
            FENCE_ASYNC();
            issue_chunk32(tmem, base, base + 8192u, base + 16384u, base + 32768u, idesc, kt == 0);
            TC_COMMIT(p == 0 ? mb0 : mb1);
        }
    }
    MB_WAIT(mb0, ph0);
    MB_WAIT(mb1, ph1);
    TC_FENCE_AFTER();
    __syncthreads();

    float* tb = (float*)dyn;   // reuse pipeline buffers for transpose staging
    for (int c0 = 0; c0 < NN; c0 += 32) {
        int oc0 = o0 + c0;
        bool dir = oc0 < 128;
        if (tid < 128) {
            uint32_t r[32];
            LDTM32(r, tmem + c0);
            TC_WAIT_LD();
            if (dir) {
                int n = n0 + wid * 32 + lane;
                int oo = (oc0 < 64) ? oc0 : (oc0 - 64);
                uint32_t* hi = (uint32_t*)((oc0 < 64) ? g_qT_hi : g_kT_hi) + ((size_t)b * N_TOK + n) * 32;
                uint32_t* lo = (uint32_t*)((oc0 < 64) ? g_qT_lo : g_kT_lo) + ((size_t)b * N_TOK + n) * 32;
#pragma unroll
                for (int j = 0; j < 32; j += 4) {
                    uint32_t h0, l0, h1, l1;
                    pack_split2(__uint_as_float(r[j + 0]) + s_bias[c0 + j + 0],
                                __uint_as_float(r[j + 1]) + s_bias[c0 + j + 1], h0, l0);
                    pack_split2(__uint_as_float(r[j + 2]) + s_bias[c0 + j + 2],
                                __uint_as_float(r[j + 3]) + s_bias[c0 + j + 3], h1, l1);
                    *(uint2*)(hi + ((oo + j) >> 1)) = make_uint2(h0, h1);
                    *(uint2*)(lo + ((oo + j) >> 1)) = make_uint2(l0, l1);
                }
            } else {
                int cb = wid * 1056 + lane * 33;
#pragma unroll
                for (int j = 0; j < 32; j++) tb[cb + j] = __uint_as_float(r[j]);
            }
        }
        if (!dir) {
            __syncthreads();
            int cg = oc0 - 128;
#pragma unroll
            for (int i = 0; i < 16; i++) {
                int rid = wid * 16 + i;
                int wsrc = rid >> 5, j = rid & 31;
                float val = tb[wsrc * 1056 + lane * 33 + j] + s_bias[c0 + j];
                __nv_bfloat16 h, l;
                split1(val, h, l);
                size_t off = ((size_t)b * C_IN + cg + j) * N_TOK + n0 + wsrc * 32 + lane;
                g_v_hi[off] = h;
                g_v_lo[off] = l;
            }
            __syncthreads();
        }
    }
    __syncthreads();
    if (wid == 0) TC_DEALLOC(tmem, 256);
#else
    int tid = threadIdx.x;
    int b = blockIdx.z, n0 = blockIdx.x * 128, y = blockIdx.y, o0 = y * 256;
    int NN = (y < 2) ? 256 : 128;
    for (int e = tid; e < 128 * NN; e += 256) {
        int n = n0 + (e & 127);
        int oc = o0 + (e >> 7);
        const __nv_bfloat16* xh = g_xT_hi + ((size_t)b * N_TOK + n) * C_IN;
        const __nv_bfloat16* xl = g_xT_lo + ((size_t)b * N_TOK + n) * C_IN;
        const __nv_bfloat16* wh = g_Wn_hi + (size_t)oc * C_IN;
        const __nv_bfloat16* wl = g_Wn_lo + (size_t)oc * C_IN;
        float s = 0.f;
        for (int c = 0; c < C_IN; c++) {
            float xa = __bfloat162float(xh[c]) + __bfloat162float(xl[c]);
            float wa = __bfloat162float(wh[c]) + __bfloat162float(wl[c]);
            s += xa * wa;
        }
        s += g_bias[oc];
        __nv_bfloat16 h, l;
        split1(s, h, l);
        if (oc < 64)       { size_t o = ((size_t)b * N_TOK + n) * CQ + oc;        g_qT_hi[o] = h; g_qT_lo[o] = l; }
        else if (oc < 128) { size_t o = ((size_t)b * N_TOK + n) * CQ + (oc - 64); g_kT_hi[o] = h; g_kT_lo[o] = l; }
        else               { size_t o = ((size_t)b * C_IN + (oc - 128)) * N_TOK + n; g_v_hi[o] = h; g_v_lo[o] = l; }
    }
#endif
}

// ---------------- qks: fused QK^T + exp + row-sum -----------------------------
// grid (8, BATCH): m0 = x*128. Writes unnormalized exp(S) as bf16 P + row sums.
__global__ void __launch_bounds__(256) qks_mma() {
#if USE_TCGEN05
    extern __shared__ char dyn[];
    __shared__ uint32_t s_tmem;
    __shared__ uint64_t s_mb[2];

    int tid = threadIdx.x, wid = tid >> 5, lane = tid & 31;
    int b = blockIdx.y, m0 = blockIdx.x * 128;
    uint32_t idesc = IDESC(256);

    uint32_t dynb = (cvta_smem(dyn) + 1023u) & ~1023u;
    uint32_t AHI = dynb, ALO = dynb + 16384u, BHI = dynb + 32768u, BLO = dynb + 98304u;
    uint32_t mb0 = cvta_smem(&s_mb[0]), mb1 = cvta_smem(&s_mb[1]);

    if (wid == 0) { TC_ALLOC(cvta_smem(&s_tmem), 512); TC_RELINQ(); }
    if (tid == 0) { MB_INIT(mb0, 1); MB_INIT(mb1, 1); }
    __syncthreads();
    uint32_t tmem = s_tmem;

    const __nv_bfloat16* Kh = g_kT_hi + ((size_t)b * N_TOK + m0) * CQ;
    const __nv_bfloat16* Kl = g_kT_lo + ((size_t)b * N_TOK + m0) * CQ;
    const __nv_bfloat16* Qh = g_qT_hi + (size_t)b * N_TOK * CQ;
    const __nv_bfloat16* Ql = g_qT_lo + (size_t)b * N_TOK * CQ;

    copy_rows(Kh, CQ, 0, AHI, 128, tid);
    copy_rows(Kl, CQ, 0, ALO, 128, tid);
    copy_rows(Qh, CQ, 0, BHI, 512, tid);
    copy_rows(Ql, CQ, 0, BLO, 512, tid);
    CP_COMMIT();
    CP_WAIT0();
    __syncthreads();
    if (wid == 0 && elect_one()) {
        FENCE_ASYNC();
        issue_qks(tmem, AHI, ALO, BHI, BLO, idesc);
        TC_COMMIT(mb0);
    }
    MB_WAIT(mb0, 0);
    TC_FENCE_AFTER();

    copy_rows(Qh + (size_t)512 * CQ, CQ, 0, BHI, 512, tid);
    copy_rows(Ql + (size_t)512 * CQ, CQ, 0, BLO, 512, tid);
    CP_COMMIT();

    float rsum = 0.f;
    int m = m0 + wid * 32 + lane;
    uint32_t* Ph = (uint32_t*)g_P + ((size_t)b * N_TOK + m) * 512;

    if (tid < 128) {
        for (int c0 = 0; c0 < 512; c0 += 32) {
            uint32_t r[32];
            LDTM32(r, tmem + c0);
            TC_WAIT_LD();
            uint32_t hb[16];
#pragma unroll
            for (int j = 0; j < 32; j += 2) {
                float e0 = __expf(__uint_as_float(r[j]));
                float e1 = __expf(__uint_as_float(r[j + 1]));
                rsum += e0 + e1;
                hb[j >> 1] = pack_bf2(e0, e1);
            }
            int base = c0 >> 1;
#pragma unroll
            for (int q = 0; q < 4; q++)
                *(uint4*)(Ph + base + q * 4) = make_uint4(hb[q*4], hb[q*4+1], hb[q*4+2], hb[q*4+3]);
        }
    }
    TC_FENCE_BEFORE();
    CP_WAIT0();
    __syncthreads();
    if (wid == 0 && elect_one()) {
        FENCE_ASYNC();
        TC_FENCE_AFTER();
        issue_qks(tmem, AHI, ALO, BHI, BLO, idesc);
        TC_COMMIT(mb1);
    }
    MB_WAIT(mb1, 0);
    TC_FENCE_AFTER();

    if (tid < 128) {
        for (int c0 = 0; c0 < 512; c0 += 32) {
            uint32_t r[32];
            LDTM32(r, tmem + c0);
            TC_WAIT_LD();
            uint32_t hb[16];
#pragma unroll
            for (int j = 0; j < 32; j += 2) {
                float e0 = __expf(__uint_as_float(r[j]));
                float e1 = __expf(__uint_as_float(r[j + 1]));
                rsum += e0 + e1;
                hb[j >> 1] = pack_bf2(e0, e1);
            }
            int base = 256 + (c0 >> 1);
#pragma unroll
            for (int q = 0; q < 4; q++)
                *(uint4*)(Ph + base + q * 4) = make_uint4(hb[q*4], hb[q*4+1], hb[q*4+2], hb[q*4+3]);
        }
        g_rsum[(size_t)b * N_TOK + m] = rsum;
    }
    __syncthreads();
    if (wid == 0) TC_DEALLOC(tmem, 512);
#else
    int tid = threadIdx.x;
    int b = blockIdx.y, m0 = blockIdx.x * 128;
    if (tid < 128) {
        int m = m0 + tid;
        const __nv_bfloat16* kh = g_kT_hi + ((size_t)b * N_TOK + m) * CQ;
        const __nv_bfloat16* kl = g_kT_lo + ((size_t)b * N_TOK + m) * CQ;
        float rsum = 0.f;
        for (int n = 0; n < N_TOK; n++) {
            const __nv_bfloat16* qh = g_qT_hi + ((size_t)b * N_TOK + n) * CQ;
            const __nv_bfloat16* ql = g_qT_lo + ((size_t)b * N_TOK + n) * CQ;
            float s = 0.f;
            for (int o = 0; o < CQ; o++)
                s += (__bfloat162float(qh[o]) + __bfloat162float(ql[o])) *
                     (__bfloat162float(kh[o]) + __bfloat162float(kl[o]));
            float e = __expf(s);
            rsum += e;
            g_P[((size_t)b * N_TOK + m) * N_TOK + n] = __float2bfloat16(e);
        }
        g_rsum[(size_t)b * N_TOK + m] = rsum;
    }
#endif
}

// ---------------- av: D[m=128][c=256], 2-buffer, 2 CTAs/SM ------------------
// grid (8, 2, BATCH): m0 = x*128, c0g = y*256. A = bf16 P (no split), B = v hi/lo.
// buffer (40KB): A 8K | BHI 16K | BLO 16K ; 2 buffers = 80KB
__global__ void __launch_bounds__(256, 2) av_mma(const float* __restrict__ x,
                                                 const float* __restrict__ gamma_p,
                                                 float* __restrict__ out) {
#if USE_TCGEN05
    extern __shared__ char dyn[];
    __shared__ uint32_t s_tmem;
    __shared__ uint64_t s_mb[2];

    int tid = threadIdx.x, wid = tid >> 5, lane = tid & 31;
    int b = blockIdx.z, m0 = blockIdx.x * 128, c0g = blockIdx.y * 256;
    uint32_t idesc = IDESC(256);

    uint32_t dynb = (cvta_smem(dyn) + 1023u) & ~1023u;
    uint32_t mb0 = cvta_smem(&s_mb[0]), mb1 = cvta_smem(&s_mb[1]);

    if (wid == 0) { TC_ALLOC(cvta_smem(&s_tmem), 256); TC_RELINQ(); }
    if (tid == 0) { MB_INIT(mb0, 1); MB_INIT(mb1, 1); }
    __syncthreads();
    uint32_t tmem = s_tmem;

    const __nv_bfloat16* Ap = g_P    + ((size_t)b * N_TOK + m0) * N_TOK;
    const __nv_bfloat16* Bh = g_v_hi + ((size_t)b * C_IN + c0g) * N_TOK;
    const __nv_bfloat16* Bl = g_v_lo + ((size_t)b * C_IN + c0g) * N_TOK;

    int ph0 = 0, ph1 = 0;
    const int KT = N_TOK / 32;   // 32
    for (int kt = 0; kt < KT; kt++) {
        int p = kt & 1;
        if (kt >= 2) {
            if (p == 0) { MB_WAIT(mb0, ph0); ph0 ^= 1; }
            else        { MB_WAIT(mb1, ph1); ph1 ^= 1; }
        }
        uint32_t base = dynb + (uint32_t)p * 40960u;
        int k0 = kt * 32;
        copy_rows64(Ap, N_TOK, k0, base, 128, tid);
        copy_rows64(Bh, N_TOK, k0, base + 8192u, 256, tid);
        copy_rows64(Bl, N_TOK, k0, base + 24576u, 256, tid);
        CP_COMMIT();
        CP_WAIT0();
        __syncthreads();
        if (wid == 0 && elect_one()) {
            FENCE_ASYNC();
            issue_av32(tmem, base, base + 8192u, base + 24576u, idesc, kt == 0);
            TC_COMMIT(p == 0 ? mb0 : mb1);
        }
    }
    MB_WAIT(mb0, ph0);
    MB_WAIT(mb1, ph1);
    TC_FENCE_AFTER();

    float g = *gamma_p;
    int m = m0 + wid * 32 + lane;
    float ginv = (tid < 128) ? (g / g_rsum[(size_t)b * N_TOK + m]) : 0.f;
    for (int c0 = 0; c0 < 256; c0 += 32) {
        if (tid < 128) {
            uint32_t r[32];
            LDTM32(r, tmem + c0);
            TC_WAIT_LD();
#pragma unroll
            for (int j = 0; j < 32; j++) {
                int c = c0g + c0 + j;
                size_t off = ((size_t)b * C_IN + c) * N_TOK + m;
                out[off] = ginv * __uint_as_float(r[j]) + x[off];
            }
        }
    }
    __syncthreads();
    if (wid == 0) TC_DEALLOC(tmem, 256);
#else
    int tid = threadIdx.x;
    int b = blockIdx.z, m0 = blockIdx.x * 128, c0g = blockIdx.y * 256;
    float g = *gamma_p;
    for (int e = tid; e < 128 * 256; e += 256) {
        int m = m0 + (e & 127);
        int c = c0g + (e >> 7);
        const __nv_bfloat16* vh = g_v_hi + ((size_t)b * C_IN + c) * N_TOK;
        const __nv_bfloat16* vl = g_v_lo + ((size_t)b * C_IN + c) * N_TOK;
        const __nv_bfloat16* pp = g_P + ((size_t)b * N_TOK + m) * N_TOK;
        float s = 0.f;
        for (int n = 0; n < N_TOK; n++)
            s += (__bfloat162float(vh[n]) + __bfloat162float(vl[n])) * __bfloat162float(pp[n]);
        size_t off = ((size_t)b * C_IN + c) * N_TOK + m;
        out[off] = g * s / g_rsum[(size_t)b * N_TOK + m] + x[off];
    }
#endif
}

// ---------------- launch -----------------------------------------------------
extern "C" void kernel_launch(void* const* d_in, const int* in_sizes, int n_in,
                              void* d_out, int out_size) {
    const float* x     = (const float*)d_in[0];
    const float* Wq    = (const float*)d_in[1];
    const float* bq    = (const float*)d_in[2];
    const float* uq    = (const float*)d_in[3];
    const float* Wk    = (const float*)d_in[4];
    const float* bk    = (const float*)d_in[5];
    const float* uk    = (const float*)d_in[6];
    const float* Wv    = (const float*)d_in[7];
    const float* bv    = (const float*)d_in[8];
    const float* uv    = (const float*)d_in[9];
    const float* gamma = (const float*)d_in[10];
    float* out = (float*)d_out;

    cudaFuncSetAttribute(proj_mma, cudaFuncAttributeMaxDynamicSharedMemorySize, 99328);
    cudaFuncSetAttribute(qks_mma,  cudaFuncAttributeMaxDynamicSharedMemorySize, 164864);
    cudaFuncSetAttribute(av_mma,   cudaFuncAttributeMaxDynamicSharedMemorySize, 82944);

    sn_kernel<<<3, 512>>>(Wq, uq, bq, Wk, uk, bk, Wv, uv, bv);
    transpose_kernel<<<dim3(32, 16, BATCH), dim3(32, 8)>>>(x);
    proj_mma<<<dim3(8, 3, BATCH), 256, 99328>>>();
    qks_mma<<<dim3(8, BATCH), 256, 164864>>>();
    av_mma<<<dim3(8, 2, BATCH), 256, 82944>>>(x, gamma, out);
}